// round 3
// baseline (speedup 1.0000x reference)
#include <cuda_runtime.h>
#include <math.h>

#define Bg 128
#define NPERg 400
#define NNODES (Bg*NPERg)      // 51200
#define EPGg 6400
#define NE (Bg*EPGg)           // 819200
#define Hdim 128
#define KP1 320
#define KP2 256
#define KP3 205

// ---------------- scratch (device globals; no allocation allowed) -------------
__device__ float g_tmp[NNODES*256];     // GEMM out: [xrel | xroot] per node
__device__ float g_h[NNODES*Hdim];      // current node features
__device__ int   g_deg[NNODES];
__device__ int   g_rowptr[Bg*(NPERg+1)];
__device__ int   g_cursor[NNODES];
__device__ int   g_col[NE];             // local src index per CSR entry
__device__ int   g_active[NNODES];
__device__ float g_z[Bg*256];           // accumulated readouts x1+x2+x3

// ---------------- init ----------------
__global__ void init_kernel() {
    int i = blockIdx.x * blockDim.x + threadIdx.x;
    if (i < NNODES) { g_deg[i] = 0; g_active[i] = 1; }
    if (i < Bg*256) g_z[i] = 0.f;
}

// ---------------- CSR build (per-graph, dst-major) ----------------
__global__ void csr_count(const int* __restrict__ edst) {
    int i = blockIdx.x * blockDim.x + threadIdx.x;
    if (i < NE) atomicAdd(&g_deg[edst[i]], 1);
}

__global__ void csr_scan() {
    int g = blockIdx.x;
    __shared__ int sd[NPERg];
    for (int v = threadIdx.x; v < NPERg; v += blockDim.x) sd[v] = g_deg[g*NPERg + v];
    __syncthreads();
    if (threadIdx.x == 0) {
        int run = 0;
        for (int v = 0; v < NPERg; v++) {
            g_rowptr[g*(NPERg+1) + v] = run;
            g_cursor[g*NPERg + v] = g*EPGg + run;
            run += sd[v];
        }
        g_rowptr[g*(NPERg+1) + NPERg] = run;
    }
}

__global__ void csr_fill(const int* __restrict__ esrc, const int* __restrict__ edst) {
    int i = blockIdx.x * blockDim.x + threadIdx.x;
    if (i < NE) {
        int d = edst[i], s = esrc[i];
        int pos = atomicAdd(&g_cursor[d], 1);
        g_col[pos] = s % NPERg;   // local src (same graph by construction)
    }
}

// ---------------- SGEMM: C[M,256] = A[M,K] * [Brel;Broot]^T ----------------
// grid (M/128, 2); blockIdx.y selects Brel (cols 0..127) or Broot (cols 128..255)
__global__ __launch_bounds__(256) void sgemm256(
    const float* __restrict__ Ain, const float* __restrict__ Brel,
    const float* __restrict__ Broot, int K, int useH)
{
    __shared__ float As[8][128];
    __shared__ float Bs[8][128];
    const float* A = useH ? g_h : Ain;
    const float* Bm = (blockIdx.y == 0) ? Brel : Broot;
    int m0   = blockIdx.x * 128;
    int noff = blockIdx.y * 128;
    int t  = threadIdx.x;
    int tx = t & 15, ty = t >> 4;
    float acc[8][8];
    #pragma unroll
    for (int i = 0; i < 8; i++)
        #pragma unroll
        for (int j = 0; j < 8; j++) acc[i][j] = 0.f;

    int lr = t >> 1;
    int lc = (t & 1) * 4;
    const float* Ap = A  + (size_t)(m0 + lr) * K + lc;
    const float* Bp = Bm + (size_t)lr * K + lc;

    for (int k0 = 0; k0 < K; k0 += 8) {
        float4 av = *(const float4*)(Ap + k0);
        float4 bv = *(const float4*)(Bp + k0);
        As[lc+0][lr] = av.x; As[lc+1][lr] = av.y; As[lc+2][lr] = av.z; As[lc+3][lr] = av.w;
        Bs[lc+0][lr] = bv.x; Bs[lc+1][lr] = bv.y; Bs[lc+2][lr] = bv.z; Bs[lc+3][lr] = bv.w;
        __syncthreads();
        #pragma unroll
        for (int kk = 0; kk < 8; kk++) {
            float af[8], bf[8];
            #pragma unroll
            for (int i = 0; i < 8; i++) af[i] = As[kk][ty*8 + i];
            #pragma unroll
            for (int j = 0; j < 8; j++) bf[j] = Bs[kk][tx*8 + j];
            #pragma unroll
            for (int i = 0; i < 8; i++)
                #pragma unroll
                for (int j = 0; j < 8; j++) acc[i][j] += af[i] * bf[j];
        }
        __syncthreads();
    }

    #pragma unroll
    for (int i = 0; i < 8; i++) {
        float* Cr = g_tmp + (size_t)(m0 + ty*8 + i) * 256 + noff + tx*8;
        float4 v0 = make_float4(acc[i][0], acc[i][1], acc[i][2], acc[i][3]);
        float4 v1 = make_float4(acc[i][4], acc[i][5], acc[i][6], acc[i][7]);
        *(float4*)(Cr)     = v0;
        *(float4*)(Cr + 4) = v1;
    }
}

// ---------------- SpMM + epilogue: h = relu(A_g @ xrel + xroot + b) * active ---
// one CTA per graph; xrel graph-slice staged in 200KB dynamic smem
__global__ __launch_bounds__(256) void spmm_epi(const float* __restrict__ bias)
{
    extern __shared__ float sx[];   // [400][128]
    int g = blockIdx.x, t = threadIdx.x;
    for (int idx = t; idx < NPERg*32; idx += 256) {
        int v = idx >> 5, c4 = (idx & 31) << 2;
        *(float4*)&sx[v*Hdim + c4] =
            *(const float4*)&g_tmp[(size_t)(g*NPERg + v)*256 + c4];
    }
    __syncthreads();

    int w = t >> 5, lane = t & 31;
    float4 bv = *(const float4*)&bias[lane*4];
    for (int v = w; v < NPERg; v += 8) {
        int row = g*NPERg + v;
        float4 acc = make_float4(0.f, 0.f, 0.f, 0.f);
        int e0 = g_rowptr[g*(NPERg+1) + v];
        int e1 = g_rowptr[g*(NPERg+1) + v + 1];
        const int* cp = &g_col[g*EPGg];
        for (int e = e0; e < e1; e++) {
            int s = cp[e];
            float4 m = *(const float4*)&sx[s*Hdim + lane*4];
            acc.x += m.x; acc.y += m.y; acc.z += m.z; acc.w += m.w;
        }
        float4 outv;
        if (g_active[row]) {
            float4 rt = *(const float4*)&g_tmp[(size_t)row*256 + 128 + lane*4];
            outv.x = fmaxf(acc.x + rt.x + bv.x, 0.f);
            outv.y = fmaxf(acc.y + rt.y + bv.y, 0.f);
            outv.z = fmaxf(acc.z + rt.z + bv.z, 0.f);
            outv.w = fmaxf(acc.w + rt.w + bv.w, 0.f);
        } else {
            outv = make_float4(0.f, 0.f, 0.f, 0.f);
        }
        *(float4*)&g_h[(size_t)row*Hdim + lane*4] = outv;
    }
}

// ---------------- TopK pool + gate + readout (one CTA per graph) --------------
__global__ __launch_bounds__(256) void pool_kernel(const float* __restrict__ pw, int k)
{
    __shared__ float sc[512];
    __shared__ int   sid[512];
    __shared__ float gate[NPERg];
    __shared__ unsigned char selF[NPERg];
    __shared__ float spw[128];
    __shared__ float snorm;

    int g = blockIdx.x, t = threadIdx.x;
    if (t < 128) spw[t] = pw[t];
    __syncthreads();
    if (t == 0) {
        float s = 0.f;
        for (int i = 0; i < 128; i++) s += spw[i]*spw[i];
        snorm = sqrtf(s) + 1e-16f;
    }
    __syncthreads();

    // scores (one warp per node round-robin)
    int w = t >> 5, lane = t & 31;
    for (int v = w; v < NPERg; v += 8) {
        int row = g*NPERg + v;
        const float* hr = &g_h[(size_t)row*Hdim];
        float d = hr[lane]      * spw[lane]
                + hr[lane + 32] * spw[lane + 32]
                + hr[lane + 64] * spw[lane + 64]
                + hr[lane + 96] * spw[lane + 96];
        #pragma unroll
        for (int o = 16; o > 0; o >>= 1) d += __shfl_xor_sync(0xffffffffu, d, o);
        if (lane == 0) {
            sc[v]  = g_active[row] ? d / snorm : -1e30f;
            sid[v] = v;
        }
    }
    for (int i = NPERg + t; i < 512; i += 256) { sc[i] = -3.0e38f; sid[i] = -1; }
    __syncthreads();

    // bitonic sort, descending (512 elems, 256 threads)
    for (int ksz = 2; ksz <= 512; ksz <<= 1) {
        for (int j = ksz >> 1; j > 0; j >>= 1) {
            for (int i = t; i < 512; i += 256) {
                int ixj = i ^ j;
                if (ixj > i) {
                    float a = sc[i], b = sc[ixj];
                    bool up = ((i & ksz) == 0);
                    if ((a < b) == up) {
                        sc[i] = b; sc[ixj] = a;
                        int tm = sid[i]; sid[i] = sid[ixj]; sid[ixj] = tm;
                    }
                }
            }
            __syncthreads();
        }
    }

    for (int v = t; v < NPERg; v += 256) { gate[v] = 0.f; selF[v] = 0; }
    __syncthreads();
    for (int i = t; i < k; i += 256) {
        int v = sid[i];
        gate[v] = tanhf(sc[i]);
        selF[v] = 1;
    }
    __syncthreads();

    for (int v = t; v < NPERg; v += 256) g_active[g*NPERg + v] = selF[v];

    // gate features (non-selected -> 0)
    for (int idx = t; idx < NPERg*32; idx += 256) {
        int v = idx >> 5, c4 = (idx & 31) << 2;
        float4* p = (float4*)&g_h[(size_t)(g*NPERg + v)*Hdim + c4];
        float4 val = *p;
        float gt = gate[v];
        val.x *= gt; val.y *= gt; val.z *= gt; val.w *= gt;
        *p = val;
    }
    __syncthreads();

    // readout: per-column max and mean over selected, accumulated into z
    if (t < Hdim) {
        float mx = -3.0e38f, sm = 0.f;
        for (int v = 0; v < NPERg; v++) {
            if (selF[v]) {
                float val = g_h[(size_t)(g*NPERg + v)*Hdim + t];
                mx = fmaxf(mx, val);
                sm += val;
            }
        }
        g_z[g*256 + t]       += mx;
        g_z[g*256 + 128 + t] += sm / (float)k;
    }
}

// ---------------- MLP head + log_softmax (one CTA per graph) ------------------
__global__ __launch_bounds__(128) void mlp_kernel(
    const float* __restrict__ W1, const float* __restrict__ bl1,
    const float* __restrict__ W2, const float* __restrict__ bl2,
    const float* __restrict__ W3, const float* __restrict__ bl3,
    float* __restrict__ out)
{
    int g = blockIdx.x, t = threadIdx.x;
    __shared__ float zs[256], a1[128], a2[64], lg[2];
    zs[t]       = g_z[g*256 + t];
    zs[t + 128] = g_z[g*256 + 128 + t];
    __syncthreads();

    {
        float acc = bl1[t];
        const float* wr = &W1[(size_t)t*256];
        for (int kk = 0; kk < 256; kk++) acc += wr[kk]*zs[kk];
        a1[t] = fmaxf(acc, 0.f);
    }
    __syncthreads();
    if (t < 64) {
        float acc = bl2[t];
        const float* wr = &W2[(size_t)t*128];
        for (int kk = 0; kk < 128; kk++) acc += wr[kk]*a1[kk];
        a2[t] = fmaxf(acc, 0.f);
    }
    __syncthreads();
    if (t < 2) {
        float acc = bl3[t];
        const float* wr = &W3[(size_t)t*64];
        for (int kk = 0; kk < 64; kk++) acc += wr[kk]*a2[kk];
        lg[t] = acc;
    }
    __syncthreads();
    if (t < 2) {
        float m = fmaxf(lg[0], lg[1]);
        float lse = m + logf(expf(lg[0] - m) + expf(lg[1] - m));
        out[g*2 + t] = lg[t] - lse;
    }
}

// ---------------- launcher ----------------
extern "C" void kernel_launch(void* const* d_in, const int* in_sizes, int n_in,
                              void* d_out, int out_size)
{
    const float* x      = (const float*)d_in[0];
    const int*   esrc   = (const int*)  d_in[1];
    const int*   edst   = (const int*)  d_in[2];
    const float* Wrel1  = (const float*)d_in[4];
    const float* Wroot1 = (const float*)d_in[5];
    const float* b1     = (const float*)d_in[6];
    const float* pw1    = (const float*)d_in[7];
    const float* Wrel2  = (const float*)d_in[8];
    const float* Wroot2 = (const float*)d_in[9];
    const float* b2     = (const float*)d_in[10];
    const float* pw2    = (const float*)d_in[11];
    const float* Wrel3  = (const float*)d_in[12];
    const float* Wroot3 = (const float*)d_in[13];
    const float* b3     = (const float*)d_in[14];
    const float* pw3    = (const float*)d_in[15];
    const float* W1     = (const float*)d_in[16];
    const float* bl1    = (const float*)d_in[17];
    const float* W2     = (const float*)d_in[18];
    const float* bl2    = (const float*)d_in[19];
    const float* W3     = (const float*)d_in[20];
    const float* bl3    = (const float*)d_in[21];
    float* out = (float*)d_out;

    const int SPMM_SMEM = NPERg * Hdim * (int)sizeof(float);  // 204800
    cudaFuncSetAttribute(spmm_epi, cudaFuncAttributeMaxDynamicSharedMemorySize, SPMM_SMEM);

    init_kernel<<<(NNODES + 255)/256, 256>>>();
    csr_count<<<(NE + 511)/512, 512>>>(edst);
    csr_scan<<<Bg, 256>>>();
    csr_fill<<<(NE + 511)/512, 512>>>(esrc, edst);

    // layer 1
    sgemm256<<<dim3(NNODES/128, 2), 256>>>(x, Wrel1, Wroot1, 400, 0);
    spmm_epi<<<Bg, 256, SPMM_SMEM>>>(b1);
    pool_kernel<<<Bg, 256>>>(pw1, KP1);

    // layer 2
    sgemm256<<<dim3(NNODES/128, 2), 256>>>(nullptr, Wrel2, Wroot2, Hdim, 1);
    spmm_epi<<<Bg, 256, SPMM_SMEM>>>(b2);
    pool_kernel<<<Bg, 256>>>(pw2, KP2);

    // layer 3
    sgemm256<<<dim3(NNODES/128, 2), 256>>>(nullptr, Wrel3, Wroot3, Hdim, 1);
    spmm_epi<<<Bg, 256, SPMM_SMEM>>>(b3);
    pool_kernel<<<Bg, 256>>>(pw3, KP3);

    // head
    mlp_kernel<<<Bg, 128>>>(W1, bl1, W2, bl2, W3, bl3, out);
}

// round 6
// speedup vs baseline: 1.1462x; 1.1462x over previous
#include <cuda_runtime.h>
#include <cuda_bf16.h>
#include <math.h>
#include <stdint.h>

#define Bg 128
#define NPERg 400
#define NNODES (Bg*NPERg)      // 51200
#define EPGg 6400
#define NE (Bg*EPGg)           // 819200
#define Hdim 128
#define KP1 320
#define KP2 256
#define KP3 205
#define KPAD1 448              // ceil(400/64)*64

// ---------------- scratch (device globals; no allocation allowed) -------------
__device__ float g_tmp[NNODES*256];     // GEMM out: [xrel | xroot] per node
__device__ float g_h[NNODES*Hdim];      // current node features
__device__ int   g_deg[NNODES];
__device__ int   g_rowptr[Bg*(NPERg+1)];
__device__ int   g_cursor[NNODES];
__device__ int   g_col[NE];             // local src index per CSR entry
__device__ int   g_active[NNODES];
__device__ float g_z[Bg*256];           // accumulated readouts x1+x2+x3
__device__ __nv_bfloat16 g_ah[(size_t)NNODES*KPAD1];  // A hi
__device__ __nv_bfloat16 g_al[(size_t)NNODES*KPAD1];  // A lo
__device__ __nv_bfloat16 g_bh[256*KPAD1];             // B hi ([Wrel;Wroot])
__device__ __nv_bfloat16 g_bl[256*KPAD1];             // B lo

// ---------------- helpers ----------------
__device__ __forceinline__ uint32_t smem_u32(const void* p) {
    uint32_t a;
    asm("{ .reg .u64 t; cvta.to.shared.u64 t, %1; cvt.u32.u64 %0, t; }" : "=r"(a) : "l"(p));
    return a;
}
__device__ __forceinline__ void ldmat_x4(uint32_t* r, uint32_t addr) {
    asm volatile("ldmatrix.sync.aligned.m8n8.x4.shared.b16 {%0,%1,%2,%3}, [%4];"
                 : "=r"(r[0]), "=r"(r[1]), "=r"(r[2]), "=r"(r[3]) : "r"(addr));
}
__device__ __forceinline__ void mma_bf16(float* c, const uint32_t* a, const uint32_t* b) {
    asm volatile("mma.sync.aligned.m16n8k16.row.col.f32.bf16.bf16.f32 "
                 "{%0,%1,%2,%3}, {%4,%5,%6,%7}, {%8,%9}, {%0,%1,%2,%3};"
                 : "+f"(c[0]), "+f"(c[1]), "+f"(c[2]), "+f"(c[3])
                 : "r"(a[0]), "r"(a[1]), "r"(a[2]), "r"(a[3]), "r"(b[0]), "r"(b[1]));
}

// ---------------- init ----------------
__global__ void init_kernel() {
    int i = blockIdx.x * blockDim.x + threadIdx.x;
    if (i < NNODES) { g_deg[i] = 0; g_active[i] = 1; }
    if (i < Bg*256) g_z[i] = 0.f;
}

// ---------------- CSR build ----------------
__global__ void csr_count(const int* __restrict__ edst) {
    int i = blockIdx.x * blockDim.x + threadIdx.x;
    if (i < NE) atomicAdd(&g_deg[edst[i]], 1);
}

__global__ void csr_scan() {
    int g = blockIdx.x;
    __shared__ int sd[NPERg];
    for (int v = threadIdx.x; v < NPERg; v += blockDim.x) sd[v] = g_deg[g*NPERg + v];
    __syncthreads();
    if (threadIdx.x == 0) {
        int run = 0;
        for (int v = 0; v < NPERg; v++) {
            g_rowptr[g*(NPERg+1) + v] = run;
            g_cursor[g*NPERg + v] = g*EPGg + run;
            run += sd[v];
        }
        g_rowptr[g*(NPERg+1) + NPERg] = run;
    }
}

__global__ void csr_fill(const int* __restrict__ esrc, const int* __restrict__ edst) {
    int i = blockIdx.x * blockDim.x + threadIdx.x;
    if (i < NE) {
        int d = edst[i], s = esrc[i];
        int pos = atomicAdd(&g_cursor[d], 1);
        g_col[pos] = s % NPERg;
    }
}

// ---------------- fp32 -> split bf16 conversion ----------------
__global__ void conv_a(const float* __restrict__ xin, int K, int Kpad, int useH) {
    long long idx = (long long)blockIdx.x * blockDim.x + threadIdx.x;
    long long tot = (long long)NNODES * Kpad;
    if (idx >= tot) return;
    int k = (int)(idx % Kpad);
    long long row = idx / Kpad;
    const float* src = useH ? g_h : xin;
    float v = (k < K) ? src[row * K + k] : 0.f;
    __nv_bfloat16 hi = __float2bfloat16(v);
    float lo = v - __bfloat162float(hi);
    g_ah[idx] = hi;
    g_al[idx] = __float2bfloat16(lo);
}

__global__ void conv_w(const float* __restrict__ Wrel, const float* __restrict__ Wroot,
                       int K, int Kpad) {
    int idx = blockIdx.x * blockDim.x + threadIdx.x;
    if (idx >= 256 * Kpad) return;
    int k = idx % Kpad;
    int r = idx / Kpad;
    float v = 0.f;
    if (k < K) v = (r < 128) ? Wrel[(size_t)r*K + k] : Wroot[(size_t)(r-128)*K + k];
    __nv_bfloat16 hi = __float2bfloat16(v);
    float lo = v - __bfloat162float(hi);
    g_bh[idx] = hi;
    g_bl[idx] = __float2bfloat16(lo);
}

// ---------------- HMMA GEMM: g_tmp[M,256] = A @ [Brel;Broot]^T ----------------
// split-bf16: D = Ah*Bh + Ah*Bl + Al*Bh (fp32 accum in registers).
// CTA tile 128x128, grid (400, 2); blockIdx.y picks B rows 0..127 / 128..255.
// 8 warps, each 32(M) x 64(N). K chunked by 64.
// smem 64KB: Ah@0, Al@16K, Bh@32K, Bl@48K — each [128 rows][64 bf16],
// row stride 128B, XOR swizzle: byte_off = row*128 + (kb ^ ((row&7)<<4)).
#define GEMM_SMEM 65536

__global__ __launch_bounds__(256) void hmma_gemm(int Kpad)
{
    extern __shared__ char smem[];
    const int t = threadIdx.x, wid = t >> 5, lane = t & 31;
    const int m0 = blockIdx.x * 128;
    const int nb = blockIdx.y;             // B row block
    const int warp_m = (wid & 3) * 32;
    const int warp_n = (wid >> 2) * 64;
    const uint32_t sb = smem_u32(smem);

    float acc[2][8][4];
    #pragma unroll
    for (int mi = 0; mi < 2; mi++)
        #pragma unroll
        for (int ni = 0; ni < 8; ni++)
            #pragma unroll
            for (int q = 0; q < 4; q++) acc[mi][ni][q] = 0.f;

    const int j = lane >> 3, rr = lane & 7;
    const int nchunks = Kpad >> 6;

    for (int c = 0; c < nchunks; c++) {
        const int k0 = c * 64;
        // ---- stage 4 tiles: Ah, Al, Bh, Bl (each 128x64 bf16, 1024 uint4) ----
        #pragma unroll
        for (int it = 0; it < 16; it++) {
            int idx = t + it * 256;                 // 0..4095
            int which = idx >> 10;                  // 0 Ah, 1 Al, 2 Bh, 3 Bl
            int rem = idx & 1023;
            int r = rem >> 3, u = rem & 7;
            const __nv_bfloat16* src =
                (which == 0) ? g_ah : (which == 1) ? g_al : (which == 2) ? g_bh : g_bl;
            size_t grow = (which < 2) ? (size_t)(m0 + r) : (size_t)(nb*128 + r);
            uint4 v = *(const uint4*)(src + grow * Kpad + k0 + u*8);
            uint32_t off = (uint32_t)(r*128 + ((u*16) ^ ((r & 7) << 4)));
            *(uint4*)(smem + which*16384 + off) = v;
        }
        __syncthreads();

        // ---- compute: 4 k16 steps ----
        #pragma unroll
        for (int ks = 0; ks < 4; ks++) {
            uint32_t ah[2][4], al[2][4];
            #pragma unroll
            for (int mi = 0; mi < 2; mi++) {
                int arow = warp_m + mi*16 + (j & 1)*8 + rr;
                uint32_t akb = (uint32_t)((ks*32 + (j >> 1)*16) ^ (rr << 4));
                uint32_t addr = sb + (uint32_t)(arow*128) + akb;
                ldmat_x4(ah[mi], addr);
                ldmat_x4(al[mi], addr + 16384u);
            }
            #pragma unroll
            for (int np = 0; np < 4; np++) {
                uint32_t bh[4], bl[4];
                int brow = warp_n + np*16 + (j >> 1)*8 + rr;
                uint32_t bkb = (uint32_t)((ks*32 + (j & 1)*16) ^ (rr << 4));
                uint32_t baddr = sb + 32768u + (uint32_t)(brow*128) + bkb;
                ldmat_x4(bh, baddr);
                ldmat_x4(bl, baddr + 16384u);
                #pragma unroll
                for (int tt = 0; tt < 2; tt++) {
                    int ni = 2*np + tt;
                    #pragma unroll
                    for (int mi = 0; mi < 2; mi++) {
                        mma_bf16(acc[mi][ni], ah[mi], bh + 2*tt);
                        mma_bf16(acc[mi][ni], ah[mi], bl + 2*tt);
                        mma_bf16(acc[mi][ni], al[mi], bh + 2*tt);
                    }
                }
            }
        }
        __syncthreads();
    }

    // ---- writeback ----
    const int gid = lane >> 2, tig = lane & 3;
    #pragma unroll
    for (int mi = 0; mi < 2; mi++) {
        #pragma unroll
        for (int ni = 0; ni < 8; ni++) {
            int row = m0 + warp_m + mi*16 + gid;
            int col = nb*128 + warp_n + ni*8 + 2*tig;
            float* p0 = &g_tmp[(size_t)row*256 + col];
            float* p1 = &g_tmp[(size_t)(row + 8)*256 + col];
            *(float2*)p0 = make_float2(acc[mi][ni][0], acc[mi][ni][1]);
            *(float2*)p1 = make_float2(acc[mi][ni][2], acc[mi][ni][3]);
        }
    }
}

// ---------------- SpMM + epilogue ----------------
__global__ __launch_bounds__(256) void spmm_epi(const float* __restrict__ bias)
{
    extern __shared__ float sx[];   // [400][128]
    int g = blockIdx.x, t = threadIdx.x;
    for (int idx = t; idx < NPERg*32; idx += 256) {
        int v = idx >> 5, c4 = (idx & 31) << 2;
        *(float4*)&sx[v*Hdim + c4] =
            *(const float4*)&g_tmp[(size_t)(g*NPERg + v)*256 + c4];
    }
    __syncthreads();

    int w = t >> 5, lane = t & 31;
    float4 bv = *(const float4*)&bias[lane*4];
    for (int v = w; v < NPERg; v += 8) {
        int row = g*NPERg + v;
        float4 acc = make_float4(0.f, 0.f, 0.f, 0.f);
        int e0 = g_rowptr[g*(NPERg+1) + v];
        int e1 = g_rowptr[g*(NPERg+1) + v + 1];
        const int* cp = &g_col[g*EPGg];
        for (int e = e0; e < e1; e++) {
            int s = cp[e];
            float4 m = *(const float4*)&sx[s*Hdim + lane*4];
            acc.x += m.x; acc.y += m.y; acc.z += m.z; acc.w += m.w;
        }
        float4 outv;
        if (g_active[row]) {
            float4 rt = *(const float4*)&g_tmp[(size_t)row*256 + 128 + lane*4];
            outv.x = fmaxf(acc.x + rt.x + bv.x, 0.f);
            outv.y = fmaxf(acc.y + rt.y + bv.y, 0.f);
            outv.z = fmaxf(acc.z + rt.z + bv.z, 0.f);
            outv.w = fmaxf(acc.w + rt.w + bv.w, 0.f);
        } else {
            outv = make_float4(0.f, 0.f, 0.f, 0.f);
        }
        *(float4*)&g_h[(size_t)row*Hdim + lane*4] = outv;
    }
}

// ---------------- TopK pool + gate + readout ----------------
__global__ __launch_bounds__(256) void pool_kernel(const float* __restrict__ pw, int k)
{
    __shared__ float sc[512];
    __shared__ int   sid[512];
    __shared__ float gate[NPERg];
    __shared__ unsigned char selF[NPERg];
    __shared__ float spw[128];
    __shared__ float snorm;

    int g = blockIdx.x, t = threadIdx.x;
    if (t < 128) spw[t] = pw[t];
    __syncthreads();
    if (t == 0) {
        float s = 0.f;
        for (int i = 0; i < 128; i++) s += spw[i]*spw[i];
        snorm = sqrtf(s) + 1e-16f;
    }
    __syncthreads();

    int w = t >> 5, lane = t & 31;
    for (int v = w; v < NPERg; v += 8) {
        int row = g*NPERg + v;
        const float* hr = &g_h[(size_t)row*Hdim];
        float d = hr[lane]      * spw[lane]
                + hr[lane + 32] * spw[lane + 32]
                + hr[lane + 64] * spw[lane + 64]
                + hr[lane + 96] * spw[lane + 96];
        #pragma unroll
        for (int o = 16; o > 0; o >>= 1) d += __shfl_xor_sync(0xffffffffu, d, o);
        if (lane == 0) {
            sc[v]  = g_active[row] ? d / snorm : -1e30f;
            sid[v] = v;
        }
    }
    for (int i = NPERg + t; i < 512; i += 256) { sc[i] = -3.0e38f; sid[i] = -1; }
    __syncthreads();

    for (int ksz = 2; ksz <= 512; ksz <<= 1) {
        for (int j = ksz >> 1; j > 0; j >>= 1) {
            for (int i = t; i < 512; i += 256) {
                int ixj = i ^ j;
                if (ixj > i) {
                    float a = sc[i], b = sc[ixj];
                    bool up = ((i & ksz) == 0);
                    if ((a < b) == up) {
                        sc[i] = b; sc[ixj] = a;
                        int tm = sid[i]; sid[i] = sid[ixj]; sid[ixj] = tm;
                    }
                }
            }
            __syncthreads();
        }
    }

    for (int v = t; v < NPERg; v += 256) { gate[v] = 0.f; selF[v] = 0; }
    __syncthreads();
    for (int i = t; i < k; i += 256) {
        int v = sid[i];
        gate[v] = tanhf(sc[i]);
        selF[v] = 1;
    }
    __syncthreads();

    for (int v = t; v < NPERg; v += 256) g_active[g*NPERg + v] = selF[v];

    for (int idx = t; idx < NPERg*32; idx += 256) {
        int v = idx >> 5, c4 = (idx & 31) << 2;
        float4* p = (float4*)&g_h[(size_t)(g*NPERg + v)*Hdim + c4];
        float4 val = *p;
        float gt = gate[v];
        val.x *= gt; val.y *= gt; val.z *= gt; val.w *= gt;
        *p = val;
    }
    __syncthreads();

    if (t < Hdim) {
        float mx = -3.0e38f, sm = 0.f;
        for (int v = 0; v < NPERg; v++) {
            if (selF[v]) {
                float val = g_h[(size_t)(g*NPERg + v)*Hdim + t];
                mx = fmaxf(mx, val);
                sm += val;
            }
        }
        g_z[g*256 + t]       += mx;
        g_z[g*256 + 128 + t] += sm / (float)k;
    }
}

// ---------------- MLP head + log_softmax ----------------
__global__ __launch_bounds__(128) void mlp_kernel(
    const float* __restrict__ W1, const float* __restrict__ bl1,
    const float* __restrict__ W2, const float* __restrict__ bl2,
    const float* __restrict__ W3, const float* __restrict__ bl3,
    float* __restrict__ out)
{
    int g = blockIdx.x, t = threadIdx.x;
    __shared__ float zs[256], a1[128], a2[64], lg[2];
    zs[t]       = g_z[g*256 + t];
    zs[t + 128] = g_z[g*256 + 128 + t];
    __syncthreads();

    {
        float acc = bl1[t];
        const float* wr = &W1[(size_t)t*256];
        for (int kk = 0; kk < 256; kk++) acc += wr[kk]*zs[kk];
        a1[t] = fmaxf(acc, 0.f);
    }
    __syncthreads();
    if (t < 64) {
        float acc = bl2[t];
        const float* wr = &W2[(size_t)t*128];
        for (int kk = 0; kk < 128; kk++) acc += wr[kk]*a1[kk];
        a2[t] = fmaxf(acc, 0.f);
    }
    __syncthreads();
    if (t < 2) {
        float acc = bl3[t];
        const float* wr = &W3[(size_t)t*64];
        for (int kk = 0; kk < 64; kk++) acc += wr[kk]*a2[kk];
        lg[t] = acc;
    }
    __syncthreads();
    if (t < 2) {
        float m = fmaxf(lg[0], lg[1]);
        float lse = m + logf(expf(lg[0] - m) + expf(lg[1] - m));
        out[g*2 + t] = lg[t] - lse;
    }
}

// ---------------- launcher ----------------
extern "C" void kernel_launch(void* const* d_in, const int* in_sizes, int n_in,
                              void* d_out, int out_size)
{
    const float* x      = (const float*)d_in[0];
    const int*   esrc   = (const int*)  d_in[1];
    const int*   edst   = (const int*)  d_in[2];
    const float* Wrel1  = (const float*)d_in[4];
    const float* Wroot1 = (const float*)d_in[5];
    const float* b1     = (const float*)d_in[6];
    const float* pw1    = (const float*)d_in[7];
    const float* Wrel2  = (const float*)d_in[8];
    const float* Wroot2 = (const float*)d_in[9];
    const float* b2     = (const float*)d_in[10];
    const float* pw2    = (const float*)d_in[11];
    const float* Wrel3  = (const float*)d_in[12];
    const float* Wroot3 = (const float*)d_in[13];
    const float* b3     = (const float*)d_in[14];
    const float* pw3    = (const float*)d_in[15];
    const float* W1     = (const float*)d_in[16];
    const float* bl1    = (const float*)d_in[17];
    const float* W2     = (const float*)d_in[18];
    const float* bl2    = (const float*)d_in[19];
    const float* W3     = (const float*)d_in[20];
    const float* bl3    = (const float*)d_in[21];
    float* out = (float*)d_out;

    const int SPMM_SMEM = NPERg * Hdim * (int)sizeof(float);  // 204800
    cudaFuncSetAttribute(spmm_epi, cudaFuncAttributeMaxDynamicSharedMemorySize, SPMM_SMEM);
    cudaFuncSetAttribute(hmma_gemm, cudaFuncAttributeMaxDynamicSharedMemorySize, GEMM_SMEM);

    init_kernel<<<(NNODES + 255)/256, 256>>>();
    csr_count<<<(NE + 511)/512, 512>>>(edst);
    csr_scan<<<Bg, 256>>>();
    csr_fill<<<(NE + 511)/512, 512>>>(esrc, edst);

    long long tot1 = (long long)NNODES * KPAD1;
    long long tot2 = (long long)NNODES * Hdim;

    // layer 1 (K=400, Kpad=448)
    conv_w<<<(256*KPAD1 + 255)/256, 256>>>(Wrel1, Wroot1, 400, KPAD1);
    conv_a<<<(int)((tot1 + 255)/256), 256>>>(x, 400, KPAD1, 0);
    hmma_gemm<<<dim3(NNODES/128, 2), 256, GEMM_SMEM>>>(KPAD1);
    spmm_epi<<<Bg, 256, SPMM_SMEM>>>(b1);
    pool_kernel<<<Bg, 256>>>(pw1, KP1);

    // layer 2 (K=128)
    conv_w<<<(256*Hdim + 255)/256, 256>>>(Wrel2, Wroot2, Hdim, Hdim);
    conv_a<<<(int)((tot2 + 255)/256), 256>>>(nullptr, Hdim, Hdim, 1);
    hmma_gemm<<<dim3(NNODES/128, 2), 256, GEMM_SMEM>>>(Hdim);
    spmm_epi<<<Bg, 256, SPMM_SMEM>>>(b2);
    pool_kernel<<<Bg, 256>>>(pw2, KP2);

    // layer 3 (K=128)
    conv_w<<<(256*Hdim + 255)/256, 256>>>(Wrel3, Wroot3, Hdim, Hdim);
    conv_a<<<(int)((tot2 + 255)/256), 256>>>(nullptr, Hdim, Hdim, 1);
    hmma_gemm<<<dim3(NNODES/128, 2), 256, GEMM_SMEM>>>(Hdim);
    spmm_epi<<<Bg, 256, SPMM_SMEM>>>(b3);
    pool_kernel<<<Bg, 256>>>(pw3, KP3);

    // head
    mlp_kernel<<<Bg, 128>>>(W1, bl1, W2, bl2, W3, bl3, out);
}

// round 10
// speedup vs baseline: 1.3504x; 1.1781x over previous
#include <cuda_runtime.h>
#include <cuda_bf16.h>
#include <math.h>
#include <stdint.h>

#define Bg 128
#define NPERg 400
#define NNODES (Bg*NPERg)      // 51200
#define EPGg 6400
#define NE (Bg*EPGg)           // 819200
#define Hdim 128
#define KP1 320
#define KP2 256
#define KP3 205
#define KPAD1 448              // ceil(400/64)*64

// ---------------- scratch (device globals; no allocation allowed) -------------
__device__ float g_tmp[NNODES*256];     // GEMM out: [xrel | xroot] per node
__device__ float g_h[NNODES*Hdim];      // current node features
__device__ int   g_deg[NNODES];
__device__ int   g_rowptr[Bg*(NPERg+1)];
__device__ int   g_cursor[NNODES];
__device__ int   g_col[NE];             // local src index per CSR entry
__device__ int   g_active[NNODES];
__device__ float g_z[Bg*256];           // accumulated readouts x1+x2+x3
__device__ __align__(16) __nv_bfloat16 g_ah[(size_t)NNODES*KPAD1];  // A hi
__device__ __align__(16) __nv_bfloat16 g_al[(size_t)NNODES*KPAD1];  // A lo
__device__ __align__(16) __nv_bfloat16 g_bh[256*KPAD1];             // B hi
__device__ __align__(16) __nv_bfloat16 g_bl[256*KPAD1];             // B lo

// ---------------- helpers ----------------
__device__ __forceinline__ uint32_t smem_u32(const void* p) {
    uint32_t a;
    asm("{ .reg .u64 t; cvta.to.shared.u64 t, %1; cvt.u32.u64 %0, t; }" : "=r"(a) : "l"(p));
    return a;
}
__device__ __forceinline__ void ldmat_x4(uint32_t* r, uint32_t addr) {
    asm volatile("ldmatrix.sync.aligned.m8n8.x4.shared.b16 {%0,%1,%2,%3}, [%4];"
                 : "=r"(r[0]), "=r"(r[1]), "=r"(r[2]), "=r"(r[3]) : "r"(addr));
}
__device__ __forceinline__ void mma_bf16(float* c, const uint32_t* a, const uint32_t* b) {
    asm volatile("mma.sync.aligned.m16n8k16.row.col.f32.bf16.bf16.f32 "
                 "{%0,%1,%2,%3}, {%4,%5,%6,%7}, {%8,%9}, {%0,%1,%2,%3};"
                 : "+f"(c[0]), "+f"(c[1]), "+f"(c[2]), "+f"(c[3])
                 : "r"(a[0]), "r"(a[1]), "r"(a[2]), "r"(a[3]), "r"(b[0]), "r"(b[1]));
}
__device__ __forceinline__ void cp16(uint32_t saddr, const void* gaddr) {
    asm volatile("cp.async.cg.shared.global [%0], [%1], 16;" :: "r"(saddr), "l"(gaddr));
}
#define CP_COMMIT() asm volatile("cp.async.commit_group;" ::: "memory")
#define CP_WAIT1()  asm volatile("cp.async.wait_group 1;" ::: "memory")
#define CP_WAIT0()  asm volatile("cp.async.wait_group 0;" ::: "memory")

// ---------------- init ----------------
__global__ void init_kernel() {
    int i = blockIdx.x * blockDim.x + threadIdx.x;
    if (i < NNODES) { g_deg[i] = 0; g_active[i] = 1; }
    if (i < Bg*256) g_z[i] = 0.f;
}

// ---------------- CSR build ----------------
__global__ void csr_count(const int* __restrict__ edst) {
    int i = blockIdx.x * blockDim.x + threadIdx.x;
    if (i < NE) atomicAdd(&g_deg[edst[i]], 1);
}

__global__ void csr_scan() {
    int g = blockIdx.x;
    __shared__ int sd[NPERg];
    for (int v = threadIdx.x; v < NPERg; v += blockDim.x) sd[v] = g_deg[g*NPERg + v];
    __syncthreads();
    if (threadIdx.x == 0) {
        int run = 0;
        for (int v = 0; v < NPERg; v++) {
            g_rowptr[g*(NPERg+1) + v] = run;
            g_cursor[g*NPERg + v] = g*EPGg + run;
            run += sd[v];
        }
        g_rowptr[g*(NPERg+1) + NPERg] = run;
    }
}

__global__ void csr_fill(const int* __restrict__ esrc, const int* __restrict__ edst) {
    int i = blockIdx.x * blockDim.x + threadIdx.x;
    if (i < NE) {
        int d = edst[i], s = esrc[i];
        int pos = atomicAdd(&g_cursor[d], 1);
        g_col[pos] = s % NPERg;
    }
}

// ---------------- fp32 -> split bf16 conversion (layer 1 input only) ----------
__global__ void conv_a(const float* __restrict__ xin, int K, int Kpad) {
    long long idx = (long long)blockIdx.x * blockDim.x + threadIdx.x;
    long long tot = (long long)NNODES * Kpad;
    if (idx >= tot) return;
    int k = (int)(idx % Kpad);
    long long row = idx / Kpad;
    float v = (k < K) ? xin[row * K + k] : 0.f;
    __nv_bfloat16 hi = __float2bfloat16(v);
    float lo = v - __bfloat162float(hi);
    g_ah[idx] = hi;
    g_al[idx] = __float2bfloat16(lo);
}

__global__ void conv_w(const float* __restrict__ Wrel, const float* __restrict__ Wroot,
                       int K, int Kpad) {
    int idx = blockIdx.x * blockDim.x + threadIdx.x;
    if (idx >= 256 * Kpad) return;
    int k = idx % Kpad;
    int r = idx / Kpad;
    float v = 0.f;
    if (k < K) v = (r < 128) ? Wrel[(size_t)r*K + k] : Wroot[(size_t)(r-128)*K + k];
    __nv_bfloat16 hi = __float2bfloat16(v);
    float lo = v - __bfloat162float(hi);
    g_bh[idx] = hi;
    g_bl[idx] = __float2bfloat16(lo);
}

// ---------------- HMMA GEMM (cp.async 2-stage): g_tmp = A @ [Brel;Broot]^T ----
// split-bf16: D = Ah*Bh + Ah*Bl + Al*Bh. CTA tile 128x128, grid (400, 2).
// 8 warps, each 32(M) x 64(N). K chunked by 64; 2 smem stages of 64KB.
#define STAGE_BYTES 65536
#define GEMM_SMEM   (2*STAGE_BYTES)

__global__ __launch_bounds__(256, 1) void hmma_gemm(int Kpad)
{
    extern __shared__ char smem[];
    const int t = threadIdx.x, wid = t >> 5, lane = t & 31;
    const int m0 = blockIdx.x * 128;
    const int nb = blockIdx.y;
    const int warp_m = (wid & 3) * 32;
    const int warp_n = (wid >> 2) * 64;
    const uint32_t sb = smem_u32(smem);
    const int nchunks = Kpad >> 6;

    float acc[2][8][4];
    #pragma unroll
    for (int mi = 0; mi < 2; mi++)
        #pragma unroll
        for (int ni = 0; ni < 8; ni++)
            #pragma unroll
            for (int q = 0; q < 4; q++) acc[mi][ni][q] = 0.f;

    const int j = lane >> 3, rr = lane & 7;

    auto issue = [&](int c, int stage) {
        const int k0 = c * 64;
        #pragma unroll
        for (int it = 0; it < 16; it++) {
            int idx = t + it * 256;
            int which = idx >> 10;
            int rem = idx & 1023;
            int r = rem >> 3, u = rem & 7;
            const __nv_bfloat16* src =
                (which == 0) ? g_ah : (which == 1) ? g_al : (which == 2) ? g_bh : g_bl;
            size_t grow = (which < 2) ? (size_t)(m0 + r) : (size_t)(nb*128 + r);
            const void* gp = src + grow * Kpad + k0 + u*8;
            uint32_t off = (uint32_t)(r*128 + ((u*16) ^ ((r & 7) << 4)));
            cp16(sb + (uint32_t)stage*STAGE_BYTES + (uint32_t)which*16384u + off, gp);
        }
        CP_COMMIT();
    };

    issue(0, 0);
    for (int c = 0; c < nchunks; c++) {
        const int st = c & 1;
        if (c + 1 < nchunks) { issue(c + 1, (c + 1) & 1); CP_WAIT1(); }
        else                 { CP_WAIT0(); }
        __syncthreads();

        const uint32_t sbase = sb + (uint32_t)st*STAGE_BYTES;
        #pragma unroll
        for (int ks = 0; ks < 4; ks++) {
            uint32_t ah[2][4], al[2][4];
            #pragma unroll
            for (int mi = 0; mi < 2; mi++) {
                int arow = warp_m + mi*16 + (j & 1)*8 + rr;
                uint32_t akb = (uint32_t)((ks*32 + (j >> 1)*16) ^ (rr << 4));
                uint32_t addr = sbase + (uint32_t)(arow*128) + akb;
                ldmat_x4(ah[mi], addr);
                ldmat_x4(al[mi], addr + 16384u);
            }
            #pragma unroll
            for (int np = 0; np < 4; np++) {
                uint32_t bh[4], bl[4];
                int brow = warp_n + np*16 + (j >> 1)*8 + rr;
                uint32_t bkb = (uint32_t)((ks*32 + (j & 1)*16) ^ (rr << 4));
                uint32_t baddr = sbase + 32768u + (uint32_t)(brow*128) + bkb;
                ldmat_x4(bh, baddr);
                ldmat_x4(bl, baddr + 16384u);
                #pragma unroll
                for (int tt = 0; tt < 2; tt++) {
                    int ni = 2*np + tt;
                    #pragma unroll
                    for (int mi = 0; mi < 2; mi++) {
                        mma_bf16(acc[mi][ni], ah[mi], bh + 2*tt);
                        mma_bf16(acc[mi][ni], ah[mi], bl + 2*tt);
                        mma_bf16(acc[mi][ni], al[mi], bh + 2*tt);
                    }
                }
            }
        }
        __syncthreads();
    }

    // ---- writeback ----
    const int gid = lane >> 2, tig = lane & 3;
    #pragma unroll
    for (int mi = 0; mi < 2; mi++) {
        #pragma unroll
        for (int ni = 0; ni < 8; ni++) {
            int row = m0 + warp_m + mi*16 + gid;
            int col = nb*128 + warp_n + ni*8 + 2*tig;
            float* p0 = &g_tmp[(size_t)row*256 + col];
            float* p1 = &g_tmp[(size_t)(row + 8)*256 + col];
            *(float2*)p0 = make_float2(acc[mi][ni][0], acc[mi][ni][1]);
            *(float2*)p1 = make_float2(acc[mi][ni][2], acc[mi][ni][3]);
        }
    }
}

// ---------------- SpMM + epilogue ----------------
__global__ __launch_bounds__(256) void spmm_epi(const float* __restrict__ bias)
{
    extern __shared__ float sx[];   // [400][128]
    int g = blockIdx.x, t = threadIdx.x;
    for (int idx = t; idx < NPERg*32; idx += 256) {
        int v = idx >> 5, c4 = (idx & 31) << 2;
        *(float4*)&sx[v*Hdim + c4] =
            *(const float4*)&g_tmp[(size_t)(g*NPERg + v)*256 + c4];
    }
    __syncthreads();

    int w = t >> 5, lane = t & 31;
    float4 bv = *(const float4*)&bias[lane*4];
    for (int v = w; v < NPERg; v += 8) {
        int row = g*NPERg + v;
        float4 acc = make_float4(0.f, 0.f, 0.f, 0.f);
        int e0 = g_rowptr[g*(NPERg+1) + v];
        int e1 = g_rowptr[g*(NPERg+1) + v + 1];
        const int* cp = &g_col[g*EPGg];
        for (int e = e0; e < e1; e++) {
            int s = cp[e];
            float4 m = *(const float4*)&sx[s*Hdim + lane*4];
            acc.x += m.x; acc.y += m.y; acc.z += m.z; acc.w += m.w;
        }
        float4 outv;
        if (g_active[row]) {
            float4 rt = *(const float4*)&g_tmp[(size_t)row*256 + 128 + lane*4];
            outv.x = fmaxf(acc.x + rt.x + bv.x, 0.f);
            outv.y = fmaxf(acc.y + rt.y + bv.y, 0.f);
            outv.z = fmaxf(acc.z + rt.z + bv.z, 0.f);
            outv.w = fmaxf(acc.w + rt.w + bv.w, 0.f);
        } else {
            outv = make_float4(0.f, 0.f, 0.f, 0.f);
        }
        *(float4*)&g_h[(size_t)row*Hdim + lane*4] = outv;
    }
}

// ---------------- TopK pool + gate + readout + bf16 conv (fused) --------------
__global__ __launch_bounds__(256) void pool_kernel(const float* __restrict__ pw,
                                                   int k, int doConv)
{
    __shared__ __align__(16) float red_mx[8][128];
    __shared__ __align__(16) float red_sm[8][128];
    __shared__ __align__(16) float sc[512];
    __shared__ int   sid[512];
    __shared__ float gate[NPERg];
    __shared__ unsigned char selF[NPERg];
    __shared__ __align__(16) float spw[128];
    __shared__ float snorm;

    int g = blockIdx.x, t = threadIdx.x;
    if (t < 128) spw[t] = pw[t];
    __syncthreads();
    if (t == 0) {
        float s = 0.f;
        for (int i = 0; i < 128; i++) s += spw[i]*spw[i];
        snorm = sqrtf(s) + 1e-16f;
    }
    __syncthreads();

    int w = t >> 5, lane = t & 31;
    for (int v = w; v < NPERg; v += 8) {
        int row = g*NPERg + v;
        const float* hr = &g_h[(size_t)row*Hdim];
        float d = hr[lane]      * spw[lane]
                + hr[lane + 32] * spw[lane + 32]
                + hr[lane + 64] * spw[lane + 64]
                + hr[lane + 96] * spw[lane + 96];
        #pragma unroll
        for (int o = 16; o > 0; o >>= 1) d += __shfl_xor_sync(0xffffffffu, d, o);
        if (lane == 0) {
            sc[v]  = g_active[row] ? d / snorm : -1e30f;
            sid[v] = v;
        }
    }
    for (int i = NPERg + t; i < 512; i += 256) { sc[i] = -3.0e38f; sid[i] = -1; }
    __syncthreads();

    for (int ksz = 2; ksz <= 512; ksz <<= 1) {
        for (int j = ksz >> 1; j > 0; j >>= 1) {
            for (int i = t; i < 512; i += 256) {
                int ixj = i ^ j;
                if (ixj > i) {
                    float a = sc[i], b = sc[ixj];
                    bool up = ((i & ksz) == 0);
                    if ((a < b) == up) {
                        sc[i] = b; sc[ixj] = a;
                        int tm = sid[i]; sid[i] = sid[ixj]; sid[ixj] = tm;
                    }
                }
            }
            __syncthreads();
        }
    }

    for (int v = t; v < NPERg; v += 256) { gate[v] = 0.f; selF[v] = 0; }
    __syncthreads();
    for (int i = t; i < k; i += 256) {
        int v = sid[i];
        gate[v] = tanhf(sc[i]);
        selF[v] = 1;
    }
    __syncthreads();

    for (int v = t; v < NPERg; v += 256) g_active[g*NPERg + v] = selF[v];

    // ---- fused gate + readout (+ optional bf16 conversion) ----
    const int c4 = (t & 31) << 2;
    const int v0 = t >> 5;
    float4 mx = make_float4(-3.0e38f, -3.0e38f, -3.0e38f, -3.0e38f);
    float4 sm = make_float4(0.f, 0.f, 0.f, 0.f);
    for (int v = v0; v < NPERg; v += 8) {
        size_t row = (size_t)(g*NPERg + v);
        float4* p = (float4*)&g_h[row*Hdim + c4];
        float4 val = *p;
        float gt = gate[v];
        val.x *= gt; val.y *= gt; val.z *= gt; val.w *= gt;
        *p = val;
        if (doConv) {
            __nv_bfloat16 h0 = __float2bfloat16(val.x);
            __nv_bfloat16 h1 = __float2bfloat16(val.y);
            __nv_bfloat16 h2 = __float2bfloat16(val.z);
            __nv_bfloat16 h3 = __float2bfloat16(val.w);
            __nv_bfloat162* ph = (__nv_bfloat162*)&g_ah[row*Hdim + c4];
            ph[0] = __nv_bfloat162(h0, h1);
            ph[1] = __nv_bfloat162(h2, h3);
            __nv_bfloat162* pl = (__nv_bfloat162*)&g_al[row*Hdim + c4];
            pl[0] = __nv_bfloat162(__float2bfloat16(val.x - __bfloat162float(h0)),
                                   __float2bfloat16(val.y - __bfloat162float(h1)));
            pl[1] = __nv_bfloat162(__float2bfloat16(val.z - __bfloat162float(h2)),
                                   __float2bfloat16(val.w - __bfloat162float(h3)));
        }
        if (selF[v]) {
            mx.x = fmaxf(mx.x, val.x); mx.y = fmaxf(mx.y, val.y);
            mx.z = fmaxf(mx.z, val.z); mx.w = fmaxf(mx.w, val.w);
            sm.x += val.x; sm.y += val.y; sm.z += val.z; sm.w += val.w;
        }
    }
    *(float4*)&red_mx[v0][c4] = mx;
    *(float4*)&red_sm[v0][c4] = sm;
    __syncthreads();

    if (t < 128) {
        float m = red_mx[0][t], s = red_sm[0][t];
        #pragma unroll
        for (int r = 1; r < 8; r++) {
            m = fmaxf(m, red_mx[r][t]);
            s += red_sm[r][t];
        }
        g_z[g*256 + t]       += m;
        g_z[g*256 + 128 + t] += s / (float)k;
    }
}

// ---------------- MLP head + log_softmax ----------------
__global__ __launch_bounds__(128) void mlp_kernel(
    const float* __restrict__ W1, const float* __restrict__ bl1,
    const float* __restrict__ W2, const float* __restrict__ bl2,
    const float* __restrict__ W3, const float* __restrict__ bl3,
    float* __restrict__ out)
{
    int g = blockIdx.x, t = threadIdx.x;
    __shared__ float zs[256], a1[128], a2[64], lg[2];
    zs[t]       = g_z[g*256 + t];
    zs[t + 128] = g_z[g*256 + 128 + t];
    __syncthreads();

    {
        float acc = bl1[t];
        const float* wr = &W1[(size_t)t*256];
        for (int kk = 0; kk < 256; kk++) acc += wr[kk]*zs[kk];
        a1[t] = fmaxf(acc, 0.f);
    }
    __syncthreads();
    if (t < 64) {
        float acc = bl2[t];
        const float* wr = &W2[(size_t)t*128];
        for (int kk = 0; kk < 128; kk++) acc += wr[kk]*a1[kk];
        a2[t] = fmaxf(acc, 0.f);
    }
    __syncthreads();
    if (t < 2) {
        float acc = bl3[t];
        const float* wr = &W3[(size_t)t*64];
        for (int kk = 0; kk < 64; kk++) acc += wr[kk]*a2[kk];
        lg[t] = acc;
    }
    __syncthreads();
    if (t < 2) {
        float m = fmaxf(lg[0], lg[1]);
        float lse = m + logf(expf(lg[0] - m) + expf(lg[1] - m));
        out[g*2 + t] = lg[t] - lse;
    }
}

// ---------------- launcher ----------------
extern "C" void kernel_launch(void* const* d_in, const int* in_sizes, int n_in,
                              void* d_out, int out_size)
{
    const float* x      = (const float*)d_in[0];
    const int*   esrc   = (const int*)  d_in[1];
    const int*   edst   = (const int*)  d_in[2];
    const float* Wrel1  = (const float*)d_in[4];
    const float* Wroot1 = (const float*)d_in[5];
    const float* b1     = (const float*)d_in[6];
    const float* pw1    = (const float*)d_in[7];
    const float* Wrel2  = (const float*)d_in[8];
    const float* Wroot2 = (const float*)d_in[9];
    const float* b2     = (const float*)d_in[10];
    const float* pw2    = (const float*)d_in[11];
    const float* Wrel3  = (const float*)d_in[12];
    const float* Wroot3 = (const float*)d_in[13];
    const float* b3     = (const float*)d_in[14];
    const float* pw3    = (const float*)d_in[15];
    const float* W1     = (const float*)d_in[16];
    const float* bl1    = (const float*)d_in[17];
    const float* W2     = (const float*)d_in[18];
    const float* bl2    = (const float*)d_in[19];
    const float* W3     = (const float*)d_in[20];
    const float* bl3    = (const float*)d_in[21];
    float* out = (float*)d_out;

    const int SPMM_SMEM = NPERg * Hdim * (int)sizeof(float);  // 204800
    cudaFuncSetAttribute(spmm_epi, cudaFuncAttributeMaxDynamicSharedMemorySize, SPMM_SMEM);
    cudaFuncSetAttribute(hmma_gemm, cudaFuncAttributeMaxDynamicSharedMemorySize, GEMM_SMEM);

    init_kernel<<<(NNODES + 255)/256, 256>>>();
    csr_count<<<(NE + 511)/512, 512>>>(edst);
    csr_scan<<<Bg, 256>>>();
    csr_fill<<<(NE + 511)/512, 512>>>(esrc, edst);

    long long tot1 = (long long)NNODES * KPAD1;

    // layer 1 (K=400, Kpad=448)
    conv_w<<<(256*KPAD1 + 255)/256, 256>>>(Wrel1, Wroot1, 400, KPAD1);
    conv_a<<<(int)((tot1 + 255)/256), 256>>>(x, 400, KPAD1);
    hmma_gemm<<<dim3(NNODES/128, 2), 256, GEMM_SMEM>>>(KPAD1);
    spmm_epi<<<Bg, 256, SPMM_SMEM>>>(b1);
    pool_kernel<<<Bg, 256>>>(pw1, KP1, 1);   // emits g_ah/g_al for layer 2

    // layer 2 (K=128)
    conv_w<<<(256*Hdim + 255)/256, 256>>>(Wrel2, Wroot2, Hdim, Hdim);
    hmma_gemm<<<dim3(NNODES/128, 2), 256, GEMM_SMEM>>>(Hdim);
    spmm_epi<<<Bg, 256, SPMM_SMEM>>>(b2);
    pool_kernel<<<Bg, 256>>>(pw2, KP2, 1);   // emits g_ah/g_al for layer 3

    // layer 3 (K=128)
    conv_w<<<(256*Hdim + 255)/256, 256>>>(Wrel3, Wroot3, Hdim, Hdim);
    hmma_gemm<<<dim3(NNODES/128, 2), 256, GEMM_SMEM>>>(Hdim);
    spmm_epi<<<Bg, 256, SPMM_SMEM>>>(b3);
    pool_kernel<<<Bg, 256>>>(pw3, KP3, 0);

    // head
    mlp_kernel<<<Bg, 128>>>(W1, bl1, W2, bl2, W3, bl3, out);
}

// round 11
// speedup vs baseline: 1.4401x; 1.0664x over previous
#include <cuda_runtime.h>
#include <cuda_bf16.h>
#include <math.h>
#include <stdint.h>

#define Bg 128
#define NPERg 400
#define NNODES (Bg*NPERg)      // 51200
#define EPGg 6400
#define NE (Bg*EPGg)           // 819200
#define Hdim 128
#define KP1 320
#define KP2 256
#define KP3 205
#define KPAD1 448              // ceil(400/64)*64

// ---------------- scratch (device globals; no allocation allowed) -------------
__device__ float g_tmp[NNODES*256];     // GEMM out: [xrel | xroot] per node
__device__ float g_h[NNODES*Hdim];      // current node features
__device__ int   g_deg[NNODES];
__device__ int   g_rowptr[Bg*(NPERg+1)];
__device__ int   g_cursor[NNODES];
__device__ int   g_col[NE];             // local src index per CSR entry
__device__ int   g_active[NNODES];
__device__ float g_z[Bg*256];           // accumulated readouts x1+x2+x3
__device__ __align__(16) __nv_bfloat16 g_ah[(size_t)NNODES*KPAD1];  // A hi
__device__ __align__(16) __nv_bfloat16 g_al[(size_t)NNODES*KPAD1];  // A lo
__device__ __align__(16) __nv_bfloat16 g_bh[256*KPAD1];             // B hi
__device__ __align__(16) __nv_bfloat16 g_bl[256*KPAD1];             // B lo

// ---------------- helpers ----------------
__device__ __forceinline__ uint32_t smem_u32(const void* p) {
    uint32_t a;
    asm("{ .reg .u64 t; cvta.to.shared.u64 t, %1; cvt.u32.u64 %0, t; }" : "=r"(a) : "l"(p));
    return a;
}
__device__ __forceinline__ void ldmat_x4(uint32_t* r, uint32_t addr) {
    asm volatile("ldmatrix.sync.aligned.m8n8.x4.shared.b16 {%0,%1,%2,%3}, [%4];"
                 : "=r"(r[0]), "=r"(r[1]), "=r"(r[2]), "=r"(r[3]) : "r"(addr));
}
__device__ __forceinline__ void mma_bf16(float* c, const uint32_t* a, const uint32_t* b) {
    asm volatile("mma.sync.aligned.m16n8k16.row.col.f32.bf16.bf16.f32 "
                 "{%0,%1,%2,%3}, {%4,%5,%6,%7}, {%8,%9}, {%0,%1,%2,%3};"
                 : "+f"(c[0]), "+f"(c[1]), "+f"(c[2]), "+f"(c[3])
                 : "r"(a[0]), "r"(a[1]), "r"(a[2]), "r"(a[3]), "r"(b[0]), "r"(b[1]));
}
__device__ __forceinline__ void cp16(uint32_t saddr, const void* gaddr) {
    asm volatile("cp.async.cg.shared.global [%0], [%1], 16;" :: "r"(saddr), "l"(gaddr));
}
#define CP_COMMIT() asm volatile("cp.async.commit_group;" ::: "memory")
#define CP_WAIT1()  asm volatile("cp.async.wait_group 1;" ::: "memory")
#define CP_WAIT0()  asm volatile("cp.async.wait_group 0;" ::: "memory")

// ---------------- init ----------------
__global__ void init_kernel() {
    int i = blockIdx.x * blockDim.x + threadIdx.x;
    if (i < NNODES) { g_deg[i] = 0; g_active[i] = 1; }
    if (i < Bg*256) g_z[i] = 0.f;
}

// ---------------- CSR build ----------------
__global__ void csr_count(const int* __restrict__ edst) {
    int i = blockIdx.x * blockDim.x + threadIdx.x;
    if (i < NE) atomicAdd(&g_deg[edst[i]], 1);
}

__global__ void csr_scan() {
    int g = blockIdx.x;
    __shared__ int sd[NPERg];
    for (int v = threadIdx.x; v < NPERg; v += blockDim.x) sd[v] = g_deg[g*NPERg + v];
    __syncthreads();
    if (threadIdx.x == 0) {
        int run = 0;
        for (int v = 0; v < NPERg; v++) {
            g_rowptr[g*(NPERg+1) + v] = run;
            g_cursor[g*NPERg + v] = g*EPGg + run;
            run += sd[v];
        }
        g_rowptr[g*(NPERg+1) + NPERg] = run;
    }
}

__global__ void csr_fill(const int* __restrict__ esrc, const int* __restrict__ edst) {
    int i = blockIdx.x * blockDim.x + threadIdx.x;
    if (i < NE) {
        int d = edst[i], s = esrc[i];
        int pos = atomicAdd(&g_cursor[d], 1);
        g_col[pos] = s % NPERg;
    }
}

// ---------------- fp32 -> split bf16 conversion (layer 1 input, vectorized) ---
__global__ void conv_a(const float* __restrict__ xin, int K, int Kpad) {
    long long gid = (long long)blockIdx.x * blockDim.x + threadIdx.x;
    long long tot4 = (long long)NNODES * Kpad / 4;
    if (gid >= tot4) return;
    long long base = gid * 4;
    int k = (int)(base % Kpad);
    long long row = base / Kpad;
    float4 v;
    if (k < K) v = *(const float4*)&xin[row * K + k];   // K%4==0 so k+3<K too
    else       v = make_float4(0.f, 0.f, 0.f, 0.f);
    __nv_bfloat16 h0 = __float2bfloat16(v.x), h1 = __float2bfloat16(v.y);
    __nv_bfloat16 h2 = __float2bfloat16(v.z), h3 = __float2bfloat16(v.w);
    __nv_bfloat162* ph = (__nv_bfloat162*)&g_ah[base];
    ph[0] = __nv_bfloat162(h0, h1);
    ph[1] = __nv_bfloat162(h2, h3);
    __nv_bfloat162* pl = (__nv_bfloat162*)&g_al[base];
    pl[0] = __nv_bfloat162(__float2bfloat16(v.x - __bfloat162float(h0)),
                           __float2bfloat16(v.y - __bfloat162float(h1)));
    pl[1] = __nv_bfloat162(__float2bfloat16(v.z - __bfloat162float(h2)),
                           __float2bfloat16(v.w - __bfloat162float(h3)));
}

__global__ void conv_w(const float* __restrict__ Wrel, const float* __restrict__ Wroot,
                       int K, int Kpad) {
    int idx = blockIdx.x * blockDim.x + threadIdx.x;
    if (idx >= 256 * Kpad) return;
    int k = idx % Kpad;
    int r = idx / Kpad;
    float v = 0.f;
    if (k < K) v = (r < 128) ? Wrel[(size_t)r*K + k] : Wroot[(size_t)(r-128)*K + k];
    __nv_bfloat16 hi = __float2bfloat16(v);
    float lo = v - __bfloat162float(hi);
    g_bh[idx] = hi;
    g_bl[idx] = __float2bfloat16(lo);
}

// ---------------- HMMA GEMM (merged-N, cp.async 2-stage) ----------------------
// g_tmp[M,256] = A @ [Brel;Broot]^T, split-bf16: D = Ah*Bh + Ah*Bl + Al*Bh.
// CTA tile 128(M) x 256(N), grid 400. 16 warps (512 thr), warp tile 32x64.
// K chunked by 64; 2 stages of 96KB: Ah@0 Al@16K Bh@32K Bl@64K (B has 256 rows).
// Row stride 128B, XOR swizzle: byte_off = row*128 + (kb ^ ((row&7)<<4)).
#define STAGE_BYTES 98304
#define GEMM_SMEM   (2*STAGE_BYTES)   // 196608

__global__ __launch_bounds__(512, 1) void hmma_gemm(int Kpad)
{
    extern __shared__ char smem[];
    const int t = threadIdx.x, wid = t >> 5, lane = t & 31;
    const int m0 = blockIdx.x * 128;
    const int warp_m = (wid & 3) * 32;
    const int warp_n = (wid >> 2) * 64;      // 0..192
    const uint32_t sb = smem_u32(smem);
    const int nchunks = Kpad >> 6;

    float acc[2][8][4];
    #pragma unroll
    for (int mi = 0; mi < 2; mi++)
        #pragma unroll
        for (int ni = 0; ni < 8; ni++)
            #pragma unroll
            for (int q = 0; q < 4; q++) acc[mi][ni][q] = 0.f;

    const int j = lane >> 3, rr = lane & 7;

    // 6144 uint4 per stage (A: 2x1024, B: 2x2048); 12 cp.async per thread
    auto issue = [&](int c, int stage) {
        const int k0 = c * 64;
        const uint32_t sdst = sb + (uint32_t)stage * STAGE_BYTES;
        #pragma unroll
        for (int it = 0; it < 12; it++) {
            int idx = t + it * 512;            // 0..6143
            const __nv_bfloat16* src;
            size_t grow;
            uint32_t dstoff;
            int rem;
            if (idx < 2048) {                  // A
                int buf = idx >> 10;           // 0 hi, 1 lo
                rem = idx & 1023;
                src = buf ? g_al : g_ah;
                grow = (size_t)(m0 + (rem >> 3));
                dstoff = (uint32_t)buf * 16384u;
            } else {                           // B (256 rows)
                int j2 = idx - 2048;
                int buf = j2 >> 11;
                rem = j2 & 2047;
                src = buf ? g_bl : g_bh;
                grow = (size_t)(rem >> 3);
                dstoff = 32768u + (uint32_t)buf * 32768u;
            }
            int r = rem >> 3, u = rem & 7;
            const void* gp = src + grow * Kpad + k0 + u*8;
            uint32_t off = (uint32_t)(r*128 + ((u*16) ^ ((r & 7) << 4)));
            cp16(sdst + dstoff + off, gp);
        }
        CP_COMMIT();
    };

    issue(0, 0);
    for (int c = 0; c < nchunks; c++) {
        const int st = c & 1;
        if (c + 1 < nchunks) { issue(c + 1, (c + 1) & 1); CP_WAIT1(); }
        else                 { CP_WAIT0(); }
        __syncthreads();

        const uint32_t sbase = sb + (uint32_t)st*STAGE_BYTES;
        #pragma unroll
        for (int ks = 0; ks < 4; ks++) {
            uint32_t ah[2][4], al[2][4];
            #pragma unroll
            for (int mi = 0; mi < 2; mi++) {
                int arow = warp_m + mi*16 + (j & 1)*8 + rr;
                uint32_t akb = (uint32_t)((ks*32 + (j >> 1)*16) ^ (rr << 4));
                uint32_t addr = sbase + (uint32_t)(arow*128) + akb;
                ldmat_x4(ah[mi], addr);
                ldmat_x4(al[mi], addr + 16384u);
            }
            #pragma unroll
            for (int np = 0; np < 4; np++) {
                uint32_t bh[4], bl[4];
                int brow = warp_n + np*16 + (j >> 1)*8 + rr;
                uint32_t bkb = (uint32_t)((ks*32 + (j & 1)*16) ^ (rr << 4));
                uint32_t baddr = sbase + 32768u + (uint32_t)(brow*128) + bkb;
                ldmat_x4(bh, baddr);
                ldmat_x4(bl, baddr + 32768u);
                // product-major order: same-acc mmas are 4 apart (RAW distance)
                #pragma unroll
                for (int p = 0; p < 3; p++) {
                    #pragma unroll
                    for (int tt = 0; tt < 2; tt++) {
                        #pragma unroll
                        for (int mi = 0; mi < 2; mi++) {
                            const uint32_t* af = (p == 2) ? al[mi] : ah[mi];
                            const uint32_t* bf = (p == 1) ? (bl + 2*tt) : (bh + 2*tt);
                            mma_bf16(acc[mi][2*np + tt], af, bf);
                        }
                    }
                }
            }
        }
        __syncthreads();
    }

    // ---- writeback ----
    const int gid = lane >> 2, tig = lane & 3;
    #pragma unroll
    for (int mi = 0; mi < 2; mi++) {
        #pragma unroll
        for (int ni = 0; ni < 8; ni++) {
            int row = m0 + warp_m + mi*16 + gid;
            int col = warp_n + ni*8 + 2*tig;
            float* p0 = &g_tmp[(size_t)row*256 + col];
            float* p1 = &g_tmp[(size_t)(row + 8)*256 + col];
            *(float2*)p0 = make_float2(acc[mi][ni][0], acc[mi][ni][1]);
            *(float2*)p1 = make_float2(acc[mi][ni][2], acc[mi][ni][3]);
        }
    }
}

// ---------------- SpMM + epilogue ----------------
__global__ __launch_bounds__(256) void spmm_epi(const float* __restrict__ bias)
{
    extern __shared__ float sx[];   // [400][128]
    int g = blockIdx.x, t = threadIdx.x;
    for (int idx = t; idx < NPERg*32; idx += 256) {
        int v = idx >> 5, c4 = (idx & 31) << 2;
        *(float4*)&sx[v*Hdim + c4] =
            *(const float4*)&g_tmp[(size_t)(g*NPERg + v)*256 + c4];
    }
    __syncthreads();

    int w = t >> 5, lane = t & 31;
    float4 bv = *(const float4*)&bias[lane*4];
    for (int v = w; v < NPERg; v += 8) {
        int row = g*NPERg + v;
        float4 acc = make_float4(0.f, 0.f, 0.f, 0.f);
        int e0 = g_rowptr[g*(NPERg+1) + v];
        int e1 = g_rowptr[g*(NPERg+1) + v + 1];
        const int* cp = &g_col[g*EPGg];
        for (int e = e0; e < e1; e++) {
            int s = cp[e];
            float4 m = *(const float4*)&sx[s*Hdim + lane*4];
            acc.x += m.x; acc.y += m.y; acc.z += m.z; acc.w += m.w;
        }
        float4 outv;
        if (g_active[row]) {
            float4 rt = *(const float4*)&g_tmp[(size_t)row*256 + 128 + lane*4];
            outv.x = fmaxf(acc.x + rt.x + bv.x, 0.f);
            outv.y = fmaxf(acc.y + rt.y + bv.y, 0.f);
            outv.z = fmaxf(acc.z + rt.z + bv.z, 0.f);
            outv.w = fmaxf(acc.w + rt.w + bv.w, 0.f);
        } else {
            outv = make_float4(0.f, 0.f, 0.f, 0.f);
        }
        *(float4*)&g_h[(size_t)row*Hdim + lane*4] = outv;
    }
}

// ---------------- TopK pool + gate + readout + bf16 conv (fused) --------------
__global__ __launch_bounds__(256) void pool_kernel(const float* __restrict__ pw,
                                                   int k, int doConv)
{
    __shared__ __align__(16) float red_mx[8][128];
    __shared__ __align__(16) float red_sm[8][128];
    __shared__ __align__(16) float sc[512];
    __shared__ int   sid[512];
    __shared__ float gate[NPERg];
    __shared__ unsigned char selF[NPERg];
    __shared__ __align__(16) float spw[128];
    __shared__ float snorm;

    int g = blockIdx.x, t = threadIdx.x;
    if (t < 128) spw[t] = pw[t];
    __syncthreads();
    if (t == 0) {
        float s = 0.f;
        for (int i = 0; i < 128; i++) s += spw[i]*spw[i];
        snorm = sqrtf(s) + 1e-16f;
    }
    __syncthreads();

    int w = t >> 5, lane = t & 31;
    for (int v = w; v < NPERg; v += 8) {
        int row = g*NPERg + v;
        const float* hr = &g_h[(size_t)row*Hdim];
        float d = hr[lane]      * spw[lane]
                + hr[lane + 32] * spw[lane + 32]
                + hr[lane + 64] * spw[lane + 64]
                + hr[lane + 96] * spw[lane + 96];
        #pragma unroll
        for (int o = 16; o > 0; o >>= 1) d += __shfl_xor_sync(0xffffffffu, d, o);
        if (lane == 0) {
            sc[v]  = g_active[row] ? d / snorm : -1e30f;
            sid[v] = v;
        }
    }
    for (int i = NPERg + t; i < 512; i += 256) { sc[i] = -3.0e38f; sid[i] = -1; }
    __syncthreads();

    for (int ksz = 2; ksz <= 512; ksz <<= 1) {
        for (int j = ksz >> 1; j > 0; j >>= 1) {
            for (int i = t; i < 512; i += 256) {
                int ixj = i ^ j;
                if (ixj > i) {
                    float a = sc[i], b = sc[ixj];
                    bool up = ((i & ksz) == 0);
                    if ((a < b) == up) {
                        sc[i] = b; sc[ixj] = a;
                        int tm = sid[i]; sid[i] = sid[ixj]; sid[ixj] = tm;
                    }
                }
            }
            __syncthreads();
        }
    }

    for (int v = t; v < NPERg; v += 256) { gate[v] = 0.f; selF[v] = 0; }
    __syncthreads();
    for (int i = t; i < k; i += 256) {
        int v = sid[i];
        gate[v] = tanhf(sc[i]);
        selF[v] = 1;
    }
    __syncthreads();

    for (int v = t; v < NPERg; v += 256) g_active[g*NPERg + v] = selF[v];

    // ---- fused gate + readout (+ optional bf16 conversion) ----
    const int c4 = (t & 31) << 2;
    const int v0 = t >> 5;
    float4 mx = make_float4(-3.0e38f, -3.0e38f, -3.0e38f, -3.0e38f);
    float4 sm = make_float4(0.f, 0.f, 0.f, 0.f);
    for (int v = v0; v < NPERg; v += 8) {
        size_t row = (size_t)(g*NPERg + v);
        float4* p = (float4*)&g_h[row*Hdim + c4];
        float4 val = *p;
        float gt = gate[v];
        val.x *= gt; val.y *= gt; val.z *= gt; val.w *= gt;
        *p = val;
        if (doConv) {
            __nv_bfloat16 h0 = __float2bfloat16(val.x);
            __nv_bfloat16 h1 = __float2bfloat16(val.y);
            __nv_bfloat16 h2 = __float2bfloat16(val.z);
            __nv_bfloat16 h3 = __float2bfloat16(val.w);
            __nv_bfloat162* ph = (__nv_bfloat162*)&g_ah[row*Hdim + c4];
            ph[0] = __nv_bfloat162(h0, h1);
            ph[1] = __nv_bfloat162(h2, h3);
            __nv_bfloat162* pl = (__nv_bfloat162*)&g_al[row*Hdim + c4];
            pl[0] = __nv_bfloat162(__float2bfloat16(val.x - __bfloat162float(h0)),
                                   __float2bfloat16(val.y - __bfloat162float(h1)));
            pl[1] = __nv_bfloat162(__float2bfloat16(val.z - __bfloat162float(h2)),
                                   __float2bfloat16(val.w - __bfloat162float(h3)));
        }
        if (selF[v]) {
            mx.x = fmaxf(mx.x, val.x); mx.y = fmaxf(mx.y, val.y);
            mx.z = fmaxf(mx.z, val.z); mx.w = fmaxf(mx.w, val.w);
            sm.x += val.x; sm.y += val.y; sm.z += val.z; sm.w += val.w;
        }
    }
    *(float4*)&red_mx[v0][c4] = mx;
    *(float4*)&red_sm[v0][c4] = sm;
    __syncthreads();

    if (t < 128) {
        float m = red_mx[0][t], s = red_sm[0][t];
        #pragma unroll
        for (int r = 1; r < 8; r++) {
            m = fmaxf(m, red_mx[r][t]);
            s += red_sm[r][t];
        }
        g_z[g*256 + t]       += m;
        g_z[g*256 + 128 + t] += s / (float)k;
    }
}

// ---------------- MLP head + log_softmax ----------------
__global__ __launch_bounds__(128) void mlp_kernel(
    const float* __restrict__ W1, const float* __restrict__ bl1,
    const float* __restrict__ W2, const float* __restrict__ bl2,
    const float* __restrict__ W3, const float* __restrict__ bl3,
    float* __restrict__ out)
{
    int g = blockIdx.x, t = threadIdx.x;
    __shared__ float zs[256], a1[128], a2[64], lg[2];
    zs[t]       = g_z[g*256 + t];
    zs[t + 128] = g_z[g*256 + 128 + t];
    __syncthreads();

    {
        float acc = bl1[t];
        const float* wr = &W1[(size_t)t*256];
        for (int kk = 0; kk < 256; kk++) acc += wr[kk]*zs[kk];
        a1[t] = fmaxf(acc, 0.f);
    }
    __syncthreads();
    if (t < 64) {
        float acc = bl2[t];
        const float* wr = &W2[(size_t)t*128];
        for (int kk = 0; kk < 128; kk++) acc += wr[kk]*a1[kk];
        a2[t] = fmaxf(acc, 0.f);
    }
    __syncthreads();
    if (t < 2) {
        float acc = bl3[t];
        const float* wr = &W3[(size_t)t*64];
        for (int kk = 0; kk < 64; kk++) acc += wr[kk]*a2[kk];
        lg[t] = acc;
    }
    __syncthreads();
    if (t < 2) {
        float m = fmaxf(lg[0], lg[1]);
        float lse = m + logf(expf(lg[0] - m) + expf(lg[1] - m));
        out[g*2 + t] = lg[t] - lse;
    }
}

// ---------------- launcher ----------------
extern "C" void kernel_launch(void* const* d_in, const int* in_sizes, int n_in,
                              void* d_out, int out_size)
{
    const float* x      = (const float*)d_in[0];
    const int*   esrc   = (const int*)  d_in[1];
    const int*   edst   = (const int*)  d_in[2];
    const float* Wrel1  = (const float*)d_in[4];
    const float* Wroot1 = (const float*)d_in[5];
    const float* b1     = (const float*)d_in[6];
    const float* pw1    = (const float*)d_in[7];
    const float* Wrel2  = (const float*)d_in[8];
    const float* Wroot2 = (const float*)d_in[9];
    const float* b2     = (const float*)d_in[10];
    const float* pw2    = (const float*)d_in[11];
    const float* Wrel3  = (const float*)d_in[12];
    const float* Wroot3 = (const float*)d_in[13];
    const float* b3     = (const float*)d_in[14];
    const float* pw3    = (const float*)d_in[15];
    const float* W1     = (const float*)d_in[16];
    const float* bl1    = (const float*)d_in[17];
    const float* W2     = (const float*)d_in[18];
    const float* bl2    = (const float*)d_in[19];
    const float* W3     = (const float*)d_in[20];
    const float* bl3    = (const float*)d_in[21];
    float* out = (float*)d_out;

    const int SPMM_SMEM = NPERg * Hdim * (int)sizeof(float);  // 204800
    cudaFuncSetAttribute(spmm_epi, cudaFuncAttributeMaxDynamicSharedMemorySize, SPMM_SMEM);
    cudaFuncSetAttribute(hmma_gemm, cudaFuncAttributeMaxDynamicSharedMemorySize, GEMM_SMEM);

    long long tot4 = (long long)NNODES * KPAD1 / 4;

    // ---- launch order puts hmma_gemm at position 4 (the profiled slot) ----
    init_kernel<<<(NNODES + 255)/256, 256>>>();
    conv_w<<<(256*KPAD1 + 255)/256, 256>>>(Wrel1, Wroot1, 400, KPAD1);
    conv_a<<<(int)((tot4 + 255)/256), 256>>>(x, 400, KPAD1);
    hmma_gemm<<<NNODES/128, 512, GEMM_SMEM>>>(KPAD1);        // <- profiled

    // CSR build (only needed before spmm)
    csr_count<<<(NE + 511)/512, 512>>>(edst);
    csr_scan<<<Bg, 256>>>();
    csr_fill<<<(NE + 511)/512, 512>>>(esrc, edst);

    // layer 1 tail
    spmm_epi<<<Bg, 256, SPMM_SMEM>>>(b1);
    pool_kernel<<<Bg, 256>>>(pw1, KP1, 1);   // emits g_ah/g_al for layer 2

    // layer 2 (K=128)
    conv_w<<<(256*Hdim + 255)/256, 256>>>(Wrel2, Wroot2, Hdim, Hdim);
    hmma_gemm<<<NNODES/128, 512, GEMM_SMEM>>>(Hdim);
    spmm_epi<<<Bg, 256, SPMM_SMEM>>>(b2);
    pool_kernel<<<Bg, 256>>>(pw2, KP2, 1);   // emits g_ah/g_al for layer 3

    // layer 3 (K=128)
    conv_w<<<(256*Hdim + 255)/256, 256>>>(Wrel3, Wroot3, Hdim, Hdim);
    hmma_gemm<<<NNODES/128, 512, GEMM_SMEM>>>(Hdim);
    spmm_epi<<<Bg, 256, SPMM_SMEM>>>(b3);
    pool_kernel<<<Bg, 256>>>(pw3, KP3, 0);

    // head
    mlp_kernel<<<Bg, 128>>>(W1, bl1, W2, bl2, W3, bl3, out);
}

// round 12
// speedup vs baseline: 1.6099x; 1.1179x over previous
#include <cuda_runtime.h>
#include <cuda_bf16.h>
#include <math.h>
#include <stdint.h>

#define Bg 128
#define NPERg 400
#define NNODES (Bg*NPERg)      // 51200
#define EPGg 6400
#define NE (Bg*EPGg)           // 819200
#define Hdim 128
#define KP1 320
#define KP2 256
#define KP3 205
#define KPAD1 448              // ceil(400/64)*64

// ---------------- scratch (device globals; no allocation allowed) -------------
__device__ float g_tmp[NNODES*256];     // GEMM out: [xrel | xroot] per node
__device__ float g_h[NNODES*Hdim];      // node features (internal to fused layer)
__device__ int   g_rowptr[Bg*(NPERg+1)];
__device__ int   g_col[NE];             // local src index per CSR entry
__device__ int   g_active[NNODES];
__device__ float g_z[Bg*256];           // accumulated readouts x1+x2+x3
__device__ __align__(16) __nv_bfloat16 g_ah[(size_t)NNODES*KPAD1];  // A hi
__device__ __align__(16) __nv_bfloat16 g_al[(size_t)NNODES*KPAD1];  // A lo
__device__ __align__(16) __nv_bfloat16 g_bh[256*KPAD1];             // B hi
__device__ __align__(16) __nv_bfloat16 g_bl[256*KPAD1];             // B lo

// ---------------- helpers ----------------
__device__ __forceinline__ uint32_t smem_u32(const void* p) {
    uint32_t a;
    asm("{ .reg .u64 t; cvta.to.shared.u64 t, %1; cvt.u32.u64 %0, t; }" : "=r"(a) : "l"(p));
    return a;
}
__device__ __forceinline__ void ldmat_x4(uint32_t* r, uint32_t addr) {
    asm volatile("ldmatrix.sync.aligned.m8n8.x4.shared.b16 {%0,%1,%2,%3}, [%4];"
                 : "=r"(r[0]), "=r"(r[1]), "=r"(r[2]), "=r"(r[3]) : "r"(addr));
}
__device__ __forceinline__ void mma_bf16(float* c, const uint32_t* a, const uint32_t* b) {
    asm volatile("mma.sync.aligned.m16n8k16.row.col.f32.bf16.bf16.f32 "
                 "{%0,%1,%2,%3}, {%4,%5,%6,%7}, {%8,%9}, {%0,%1,%2,%3};"
                 : "+f"(c[0]), "+f"(c[1]), "+f"(c[2]), "+f"(c[3])
                 : "r"(a[0]), "r"(a[1]), "r"(a[2]), "r"(a[3]), "r"(b[0]), "r"(b[1]));
}
__device__ __forceinline__ void cp16(uint32_t saddr, const void* gaddr) {
    asm volatile("cp.async.cg.shared.global [%0], [%1], 16;" :: "r"(saddr), "l"(gaddr));
}
#define CP_COMMIT() asm volatile("cp.async.commit_group;" ::: "memory")
#define CP_WAIT1()  asm volatile("cp.async.wait_group 1;" ::: "memory")
#define CP_WAIT0()  asm volatile("cp.async.wait_group 0;" ::: "memory")

// ---------------- CSR build + state init (one CTA per graph) ------------------
__global__ __launch_bounds__(256) void csr_build(const int* __restrict__ esrc,
                                                 const int* __restrict__ edst)
{
    __shared__ int sdeg[NPERg];
    __shared__ int sa[512], sb2[512];
    __shared__ int cursor[NPERg];
    const int g = blockIdx.x, t = threadIdx.x;
    const int ebase = g * EPGg, vbase = g * NPERg;

    for (int v = t; v < NPERg; v += 256) sdeg[v] = 0;
    __syncthreads();
    for (int e = t; e < EPGg; e += 256)
        atomicAdd(&sdeg[edst[ebase + e] - vbase], 1);
    __syncthreads();

    // inclusive scan over 512 (padded)
    for (int i = t; i < 512; i += 256) sa[i] = (i < NPERg) ? sdeg[i] : 0;
    __syncthreads();
    int* src = sa; int* dst = sb2;
    for (int off = 1; off < 512; off <<= 1) {
        for (int i = t; i < 512; i += 256)
            dst[i] = src[i] + ((i >= off) ? src[i - off] : 0);
        __syncthreads();
        int* tmp = src; src = dst; dst = tmp;
    }

    for (int v = t; v < NPERg; v += 256) {
        int ex = v ? src[v - 1] : 0;
        g_rowptr[g*(NPERg+1) + v] = ex;
        cursor[v] = ebase + ex;
        g_active[vbase + v] = 1;
    }
    if (t == 0) g_rowptr[g*(NPERg+1) + NPERg] = src[NPERg - 1];
    g_z[g*256 + t] = 0.f;  // t in [0,256)
    __syncthreads();

    for (int e = t; e < EPGg; e += 256) {
        int d = edst[ebase + e] - vbase;
        int s = esrc[ebase + e] - vbase;
        int pos = atomicAdd(&cursor[d], 1);
        g_col[pos] = s;
    }
}

// ---------------- fp32 -> split bf16 conversion (layer 1 input, vectorized) ---
__global__ void conv_a(const float* __restrict__ xin, int K, int Kpad) {
    long long gid = (long long)blockIdx.x * blockDim.x + threadIdx.x;
    long long tot4 = (long long)NNODES * Kpad / 4;
    if (gid >= tot4) return;
    long long base = gid * 4;
    int k = (int)(base % Kpad);
    long long row = base / Kpad;
    float4 v;
    if (k < K) v = *(const float4*)&xin[row * K + k];
    else       v = make_float4(0.f, 0.f, 0.f, 0.f);
    __nv_bfloat16 h0 = __float2bfloat16(v.x), h1 = __float2bfloat16(v.y);
    __nv_bfloat16 h2 = __float2bfloat16(v.z), h3 = __float2bfloat16(v.w);
    __nv_bfloat162* ph = (__nv_bfloat162*)&g_ah[base];
    ph[0] = __nv_bfloat162(h0, h1);
    ph[1] = __nv_bfloat162(h2, h3);
    __nv_bfloat162* pl = (__nv_bfloat162*)&g_al[base];
    pl[0] = __nv_bfloat162(__float2bfloat16(v.x - __bfloat162float(h0)),
                           __float2bfloat16(v.y - __bfloat162float(h1)));
    pl[1] = __nv_bfloat162(__float2bfloat16(v.z - __bfloat162float(h2)),
                           __float2bfloat16(v.w - __bfloat162float(h3)));
}

__global__ void conv_w(const float* __restrict__ Wrel, const float* __restrict__ Wroot,
                       int K, int Kpad) {
    int idx = blockIdx.x * blockDim.x + threadIdx.x;
    if (idx >= 256 * Kpad) return;
    int k = idx % Kpad;
    int r = idx / Kpad;
    float v = 0.f;
    if (k < K) v = (r < 128) ? Wrel[(size_t)r*K + k] : Wroot[(size_t)(r-128)*K + k];
    __nv_bfloat16 hi = __float2bfloat16(v);
    float lo = v - __bfloat162float(hi);
    g_bh[idx] = hi;
    g_bl[idx] = __float2bfloat16(lo);
}

// ---------------- HMMA GEMM (merged-N, cp.async 2-stage) ----------------------
#define STAGE_BYTES 98304
#define GEMM_SMEM   (2*STAGE_BYTES)   // 196608

__global__ __launch_bounds__(512, 1) void hmma_gemm(int Kpad)
{
    extern __shared__ char smem[];
    const int t = threadIdx.x, wid = t >> 5, lane = t & 31;
    const int m0 = blockIdx.x * 128;
    const int warp_m = (wid & 3) * 32;
    const int warp_n = (wid >> 2) * 64;
    const uint32_t sb = smem_u32(smem);
    const int nchunks = Kpad >> 6;

    float acc[2][8][4];
    #pragma unroll
    for (int mi = 0; mi < 2; mi++)
        #pragma unroll
        for (int ni = 0; ni < 8; ni++)
            #pragma unroll
            for (int q = 0; q < 4; q++) acc[mi][ni][q] = 0.f;

    const int j = lane >> 3, rr = lane & 7;

    auto issue = [&](int c, int stage) {
        const int k0 = c * 64;
        const uint32_t sdst = sb + (uint32_t)stage * STAGE_BYTES;
        #pragma unroll
        for (int it = 0; it < 12; it++) {
            int idx = t + it * 512;
            const __nv_bfloat16* src;
            size_t grow;
            uint32_t dstoff;
            int rem;
            if (idx < 2048) {
                int buf = idx >> 10;
                rem = idx & 1023;
                src = buf ? g_al : g_ah;
                grow = (size_t)(m0 + (rem >> 3));
                dstoff = (uint32_t)buf * 16384u;
            } else {
                int j2 = idx - 2048;
                int buf = j2 >> 11;
                rem = j2 & 2047;
                src = buf ? g_bl : g_bh;
                grow = (size_t)(rem >> 3);
                dstoff = 32768u + (uint32_t)buf * 32768u;
            }
            int r = rem >> 3, u = rem & 7;
            const void* gp = src + grow * Kpad + k0 + u*8;
            uint32_t off = (uint32_t)(r*128 + ((u*16) ^ ((r & 7) << 4)));
            cp16(sdst + dstoff + off, gp);
        }
        CP_COMMIT();
    };

    issue(0, 0);
    for (int c = 0; c < nchunks; c++) {
        const int st = c & 1;
        if (c + 1 < nchunks) { issue(c + 1, (c + 1) & 1); CP_WAIT1(); }
        else                 { CP_WAIT0(); }
        __syncthreads();

        const uint32_t sbase = sb + (uint32_t)st*STAGE_BYTES;
        #pragma unroll
        for (int ks = 0; ks < 4; ks++) {
            uint32_t ah[2][4], al[2][4];
            #pragma unroll
            for (int mi = 0; mi < 2; mi++) {
                int arow = warp_m + mi*16 + (j & 1)*8 + rr;
                uint32_t akb = (uint32_t)((ks*32 + (j >> 1)*16) ^ (rr << 4));
                uint32_t addr = sbase + (uint32_t)(arow*128) + akb;
                ldmat_x4(ah[mi], addr);
                ldmat_x4(al[mi], addr + 16384u);
            }
            #pragma unroll
            for (int np = 0; np < 4; np++) {
                uint32_t bh[4], bl[4];
                int brow = warp_n + np*16 + (j >> 1)*8 + rr;
                uint32_t bkb = (uint32_t)((ks*32 + (j & 1)*16) ^ (rr << 4));
                uint32_t baddr = sbase + 32768u + (uint32_t)(brow*128) + bkb;
                ldmat_x4(bh, baddr);
                ldmat_x4(bl, baddr + 32768u);
                #pragma unroll
                for (int p = 0; p < 3; p++) {
                    #pragma unroll
                    for (int tt = 0; tt < 2; tt++) {
                        #pragma unroll
                        for (int mi = 0; mi < 2; mi++) {
                            const uint32_t* af = (p == 2) ? al[mi] : ah[mi];
                            const uint32_t* bf = (p == 1) ? (bl + 2*tt) : (bh + 2*tt);
                            mma_bf16(acc[mi][2*np + tt], af, bf);
                        }
                    }
                }
            }
        }
        __syncthreads();
    }

    const int gid = lane >> 2, tig = lane & 3;
    #pragma unroll
    for (int mi = 0; mi < 2; mi++) {
        #pragma unroll
        for (int ni = 0; ni < 8; ni++) {
            int row = m0 + warp_m + mi*16 + gid;
            int col = warp_n + ni*8 + 2*tig;
            float* p0 = &g_tmp[(size_t)row*256 + col];
            float* p1 = &g_tmp[(size_t)(row + 8)*256 + col];
            *(float2*)p0 = make_float2(acc[mi][ni][0], acc[mi][ni][1]);
            *(float2*)p1 = make_float2(acc[mi][ni][2], acc[mi][ni][3]);
        }
    }
}

// ---------------- fused layer: SpMM + epilogue + score + topk + gate + readout
// one CTA per graph, 256 threads; dynamic smem = xrel slice [400][128] (200KB)
__global__ __launch_bounds__(256) void layer_fused(const float* __restrict__ bias,
                                                   const float* __restrict__ pw,
                                                   int k, int doConv)
{
    extern __shared__ float sx[];   // [400][128]
    __shared__ __align__(16) float red_mx[8][128];
    __shared__ __align__(16) float red_sm[8][128];
    __shared__ __align__(16) float sc[512];
    __shared__ int   sid[512];
    __shared__ float gate[NPERg];
    __shared__ unsigned char selF[NPERg];
    __shared__ __align__(16) float spw[128];
    __shared__ float snorm;

    const int g = blockIdx.x, t = threadIdx.x;
    const int w = t >> 5, lane = t & 31;

    // stage xrel slice + pw
    for (int idx = t; idx < NPERg*32; idx += 256) {
        int v = idx >> 5, c4 = (idx & 31) << 2;
        *(float4*)&sx[v*Hdim + c4] =
            *(const float4*)&g_tmp[(size_t)(g*NPERg + v)*256 + c4];
    }
    if (t < 128) spw[t] = pw[t];
    __syncthreads();
    if (t == 0) {
        float s = 0.f;
        for (int i = 0; i < 128; i++) s += spw[i]*spw[i];
        snorm = sqrtf(s) + 1e-16f;
    }
    __syncthreads();

    // ---- phase A: aggregate + epilogue + score ----
    float4 bv = *(const float4*)&bias[lane*4];
    float4 pwv = *(const float4*)&spw[lane*4];
    for (int v = w; v < NPERg; v += 8) {
        int row = g*NPERg + v;
        float4 acc = make_float4(0.f, 0.f, 0.f, 0.f);
        int e0 = g_rowptr[g*(NPERg+1) + v];
        int e1 = g_rowptr[g*(NPERg+1) + v + 1];
        const int* cp = &g_col[g*EPGg];
        for (int e = e0; e < e1; e++) {
            int s = cp[e];
            float4 m = *(const float4*)&sx[s*Hdim + lane*4];
            acc.x += m.x; acc.y += m.y; acc.z += m.z; acc.w += m.w;
        }
        int act = g_active[row];
        float4 outv = make_float4(0.f, 0.f, 0.f, 0.f);
        if (act) {
            float4 rt = *(const float4*)&g_tmp[(size_t)row*256 + 128 + lane*4];
            outv.x = fmaxf(acc.x + rt.x + bv.x, 0.f);
            outv.y = fmaxf(acc.y + rt.y + bv.y, 0.f);
            outv.z = fmaxf(acc.z + rt.z + bv.z, 0.f);
            outv.w = fmaxf(acc.w + rt.w + bv.w, 0.f);
        }
        *(float4*)&g_h[(size_t)row*Hdim + lane*4] = outv;
        float d = outv.x*pwv.x + outv.y*pwv.y + outv.z*pwv.z + outv.w*pwv.w;
        #pragma unroll
        for (int o = 16; o > 0; o >>= 1) d += __shfl_xor_sync(0xffffffffu, d, o);
        if (lane == 0) {
            sc[v]  = act ? d / snorm : -1e30f;
            sid[v] = v;
        }
    }
    for (int i = NPERg + t; i < 512; i += 256) { sc[i] = -3.0e38f; sid[i] = -1; }
    __syncthreads();

    // ---- phase B: bitonic sort (descending) ----
    for (int ksz = 2; ksz <= 512; ksz <<= 1) {
        for (int j = ksz >> 1; j > 0; j >>= 1) {
            for (int i = t; i < 512; i += 256) {
                int ixj = i ^ j;
                if (ixj > i) {
                    float a = sc[i], b = sc[ixj];
                    bool up = ((i & ksz) == 0);
                    if ((a < b) == up) {
                        sc[i] = b; sc[ixj] = a;
                        int tm = sid[i]; sid[i] = sid[ixj]; sid[ixj] = tm;
                    }
                }
            }
            __syncthreads();
        }
    }

    for (int v = t; v < NPERg; v += 256) { gate[v] = 0.f; selF[v] = 0; }
    __syncthreads();
    for (int i = t; i < k; i += 256) {
        int v = sid[i];
        gate[v] = tanhf(sc[i]);
        selF[v] = 1;
    }
    __syncthreads();

    for (int v = t; v < NPERg; v += 256) g_active[g*NPERg + v] = selF[v];

    // ---- phase C: gate + readout (+ optional bf16 conversion) ----
    const int c4 = (t & 31) << 2;
    const int v0 = t >> 5;
    float4 mx = make_float4(-3.0e38f, -3.0e38f, -3.0e38f, -3.0e38f);
    float4 sm = make_float4(0.f, 0.f, 0.f, 0.f);
    for (int v = v0; v < NPERg; v += 8) {
        size_t row = (size_t)(g*NPERg + v);
        float4 val = *(const float4*)&g_h[row*Hdim + c4];
        float gt = gate[v];
        val.x *= gt; val.y *= gt; val.z *= gt; val.w *= gt;
        if (doConv) {
            __nv_bfloat16 h0 = __float2bfloat16(val.x);
            __nv_bfloat16 h1 = __float2bfloat16(val.y);
            __nv_bfloat16 h2 = __float2bfloat16(val.z);
            __nv_bfloat16 h3 = __float2bfloat16(val.w);
            __nv_bfloat162* ph = (__nv_bfloat162*)&g_ah[row*Hdim + c4];
            ph[0] = __nv_bfloat162(h0, h1);
            ph[1] = __nv_bfloat162(h2, h3);
            __nv_bfloat162* pl = (__nv_bfloat162*)&g_al[row*Hdim + c4];
            pl[0] = __nv_bfloat162(__float2bfloat16(val.x - __bfloat162float(h0)),
                                   __float2bfloat16(val.y - __bfloat162float(h1)));
            pl[1] = __nv_bfloat162(__float2bfloat16(val.z - __bfloat162float(h2)),
                                   __float2bfloat16(val.w - __bfloat162float(h3)));
        }
        if (selF[v]) {
            mx.x = fmaxf(mx.x, val.x); mx.y = fmaxf(mx.y, val.y);
            mx.z = fmaxf(mx.z, val.z); mx.w = fmaxf(mx.w, val.w);
            sm.x += val.x; sm.y += val.y; sm.z += val.z; sm.w += val.w;
        }
    }
    *(float4*)&red_mx[v0][c4] = mx;
    *(float4*)&red_sm[v0][c4] = sm;
    __syncthreads();

    if (t < 128) {
        float m = red_mx[0][t], s = red_sm[0][t];
        #pragma unroll
        for (int r = 1; r < 8; r++) {
            m = fmaxf(m, red_mx[r][t]);
            s += red_sm[r][t];
        }
        g_z[g*256 + t]       += m;
        g_z[g*256 + 128 + t] += s / (float)k;
    }
}

// ---------------- MLP head + log_softmax ----------------
__global__ __launch_bounds__(128) void mlp_kernel(
    const float* __restrict__ W1, const float* __restrict__ bl1,
    const float* __restrict__ W2, const float* __restrict__ bl2,
    const float* __restrict__ W3, const float* __restrict__ bl3,
    float* __restrict__ out)
{
    int g = blockIdx.x, t = threadIdx.x;
    __shared__ float zs[256], a1[128], a2[64], lg[2];
    zs[t]       = g_z[g*256 + t];
    zs[t + 128] = g_z[g*256 + 128 + t];
    __syncthreads();

    {
        float acc = bl1[t];
        const float* wr = &W1[(size_t)t*256];
        for (int kk = 0; kk < 256; kk++) acc += wr[kk]*zs[kk];
        a1[t] = fmaxf(acc, 0.f);
    }
    __syncthreads();
    if (t < 64) {
        float acc = bl2[t];
        const float* wr = &W2[(size_t)t*128];
        for (int kk = 0; kk < 128; kk++) acc += wr[kk]*a1[kk];
        a2[t] = fmaxf(acc, 0.f);
    }
    __syncthreads();
    if (t < 2) {
        float acc = bl3[t];
        const float* wr = &W3[(size_t)t*64];
        for (int kk = 0; kk < 64; kk++) acc += wr[kk]*a2[kk];
        lg[t] = acc;
    }
    __syncthreads();
    if (t < 2) {
        float m = fmaxf(lg[0], lg[1]);
        float lse = m + logf(expf(lg[0] - m) + expf(lg[1] - m));
        out[g*2 + t] = lg[t] - lse;
    }
}

// ---------------- launcher ----------------
extern "C" void kernel_launch(void* const* d_in, const int* in_sizes, int n_in,
                              void* d_out, int out_size)
{
    const float* x      = (const float*)d_in[0];
    const int*   esrc   = (const int*)  d_in[1];
    const int*   edst   = (const int*)  d_in[2];
    const float* Wrel1  = (const float*)d_in[4];
    const float* Wroot1 = (const float*)d_in[5];
    const float* b1     = (const float*)d_in[6];
    const float* pw1    = (const float*)d_in[7];
    const float* Wrel2  = (const float*)d_in[8];
    const float* Wroot2 = (const float*)d_in[9];
    const float* b2     = (const float*)d_in[10];
    const float* pw2    = (const float*)d_in[11];
    const float* Wrel3  = (const float*)d_in[12];
    const float* Wroot3 = (const float*)d_in[13];
    const float* b3     = (const float*)d_in[14];
    const float* pw3    = (const float*)d_in[15];
    const float* W1     = (const float*)d_in[16];
    const float* bl1    = (const float*)d_in[17];
    const float* W2     = (const float*)d_in[18];
    const float* bl2    = (const float*)d_in[19];
    const float* W3     = (const float*)d_in[20];
    const float* bl3    = (const float*)d_in[21];
    float* out = (float*)d_out;

    const int LAYER_SMEM = NPERg * Hdim * (int)sizeof(float);  // 204800
    cudaFuncSetAttribute(layer_fused, cudaFuncAttributeMaxDynamicSharedMemorySize, LAYER_SMEM);
    cudaFuncSetAttribute(hmma_gemm, cudaFuncAttributeMaxDynamicSharedMemorySize, GEMM_SMEM);

    long long tot4 = (long long)NNODES * KPAD1 / 4;

    // layer 1 (K=400, Kpad=448); hmma_gemm stays in the profiled slot (#4)
    csr_build<<<Bg, 256>>>(esrc, edst);
    conv_w<<<(256*KPAD1 + 255)/256, 256>>>(Wrel1, Wroot1, 400, KPAD1);
    conv_a<<<(int)((tot4 + 255)/256), 256>>>(x, 400, KPAD1);
    hmma_gemm<<<NNODES/128, 512, GEMM_SMEM>>>(KPAD1);        // <- profiled
    layer_fused<<<Bg, 256, LAYER_SMEM>>>(b1, pw1, KP1, 1);   // emits ah/al for L2

    // layer 2 (K=128)
    conv_w<<<(256*Hdim + 255)/256, 256>>>(Wrel2, Wroot2, Hdim, Hdim);
    hmma_gemm<<<NNODES/128, 512, GEMM_SMEM>>>(Hdim);
    layer_fused<<<Bg, 256, LAYER_SMEM>>>(b2, pw2, KP2, 1);   // emits ah/al for L3

    // layer 3 (K=128)
    conv_w<<<(256*Hdim + 255)/256, 256>>>(Wrel3, Wroot3, Hdim, Hdim);
    hmma_gemm<<<NNODES/128, 512, GEMM_SMEM>>>(Hdim);
    layer_fused<<<Bg, 256, LAYER_SMEM>>>(b3, pw3, KP3, 0);

    // head
    mlp_kernel<<<Bg, 128>>>(W1, bl1, W2, bl2, W3, bl3, out);
}

// round 13
// speedup vs baseline: 1.6127x; 1.0017x over previous
#include <cuda_runtime.h>
#include <cuda_bf16.h>
#include <math.h>
#include <stdint.h>

#define Bg 128
#define NPERg 400
#define NNODES (Bg*NPERg)      // 51200
#define EPGg 6400
#define NE (Bg*EPGg)           // 819200
#define Hdim 128
#define KP1 320
#define KP2 256
#define KP3 205
#define KPAD1 448              // ceil(400/64)*64

// ---------------- scratch (device globals; no allocation allowed) -------------
__device__ float g_tmp[NNODES*256];     // GEMM out: [xrel | xroot] per node
__device__ float g_h[NNODES*Hdim];      // node features (internal to fused layer)
__device__ int   g_rowptr[Bg*(NPERg+1)];
__device__ int   g_col[NE];             // local src index per CSR entry
__device__ int   g_active[NNODES];
__device__ float g_z[Bg*256];           // accumulated readouts x1+x2+x3
__device__ __align__(16) __nv_bfloat16 g_ah[(size_t)NNODES*KPAD1];  // A hi
__device__ __align__(16) __nv_bfloat16 g_al[(size_t)NNODES*KPAD1];  // A lo
__device__ __align__(16) __nv_bfloat16 g_bh[256*KPAD1];             // B hi
__device__ __align__(16) __nv_bfloat16 g_bl[256*KPAD1];             // B lo

// ---------------- helpers ----------------
__device__ __forceinline__ uint32_t smem_u32(const void* p) {
    uint32_t a;
    asm("{ .reg .u64 t; cvta.to.shared.u64 t, %1; cvt.u32.u64 %0, t; }" : "=r"(a) : "l"(p));
    return a;
}
__device__ __forceinline__ void ldmat_x4(uint32_t* r, uint32_t addr) {
    asm volatile("ldmatrix.sync.aligned.m8n8.x4.shared.b16 {%0,%1,%2,%3}, [%4];"
                 : "=r"(r[0]), "=r"(r[1]), "=r"(r[2]), "=r"(r[3]) : "r"(addr));
}
__device__ __forceinline__ void mma_bf16(float* c, const uint32_t* a, const uint32_t* b) {
    asm volatile("mma.sync.aligned.m16n8k16.row.col.f32.bf16.bf16.f32 "
                 "{%0,%1,%2,%3}, {%4,%5,%6,%7}, {%8,%9}, {%0,%1,%2,%3};"
                 : "+f"(c[0]), "+f"(c[1]), "+f"(c[2]), "+f"(c[3])
                 : "r"(a[0]), "r"(a[1]), "r"(a[2]), "r"(a[3]), "r"(b[0]), "r"(b[1]));
}
__device__ __forceinline__ void cp16(uint32_t saddr, const void* gaddr) {
    asm volatile("cp.async.cg.shared.global [%0], [%1], 16;" :: "r"(saddr), "l"(gaddr));
}
#define CP_COMMIT() asm volatile("cp.async.commit_group;" ::: "memory")
#define CP_WAIT1()  asm volatile("cp.async.wait_group 1;" ::: "memory")
#define CP_WAIT0()  asm volatile("cp.async.wait_group 0;" ::: "memory")

// ---------------- CSR build + state init (one CTA per graph) ------------------
__global__ __launch_bounds__(256) void csr_build(const int* __restrict__ esrc,
                                                 const int* __restrict__ edst)
{
    __shared__ int sdeg[NPERg];
    __shared__ int sa[512], sb2[512];
    __shared__ int cursor[NPERg];
    const int g = blockIdx.x, t = threadIdx.x;
    const int ebase = g * EPGg, vbase = g * NPERg;

    for (int v = t; v < NPERg; v += 256) sdeg[v] = 0;
    __syncthreads();
    for (int e = t; e < EPGg; e += 256)
        atomicAdd(&sdeg[edst[ebase + e] - vbase], 1);
    __syncthreads();

    for (int i = t; i < 512; i += 256) sa[i] = (i < NPERg) ? sdeg[i] : 0;
    __syncthreads();
    int* src = sa; int* dst = sb2;
    for (int off = 1; off < 512; off <<= 1) {
        for (int i = t; i < 512; i += 256)
            dst[i] = src[i] + ((i >= off) ? src[i - off] : 0);
        __syncthreads();
        int* tmp = src; src = dst; dst = tmp;
    }

    for (int v = t; v < NPERg; v += 256) {
        int ex = v ? src[v - 1] : 0;
        g_rowptr[g*(NPERg+1) + v] = ex;
        cursor[v] = ebase + ex;
        g_active[vbase + v] = 1;
    }
    if (t == 0) g_rowptr[g*(NPERg+1) + NPERg] = src[NPERg - 1];
    g_z[g*256 + t] = 0.f;
    __syncthreads();

    for (int e = t; e < EPGg; e += 256) {
        int d = edst[ebase + e] - vbase;
        int s = esrc[ebase + e] - vbase;
        int pos = atomicAdd(&cursor[d], 1);
        g_col[pos] = s;
    }
}

// ---------------- fused conversion: weights + layer-1 input ------------------
// blocks [0, WBLK): conv_w;  blocks [WBLK, WBLK+ABLK): conv_a (vectorized)
#define WBLK ((256*KPAD1 + 255)/256)                        // 448
#define ABLK ((int)(((long long)NNODES*KPAD1/4 + 255)/256)) // 22400
__global__ void conv_all(const float* __restrict__ xin,
                         const float* __restrict__ Wrel, const float* __restrict__ Wroot,
                         int K, int Kpad)
{
    if (blockIdx.x < WBLK) {
        int idx = blockIdx.x * 256 + threadIdx.x;
        if (idx >= 256 * Kpad) return;
        int k = idx % Kpad;
        int r = idx / Kpad;
        float v = 0.f;
        if (k < K) v = (r < 128) ? Wrel[(size_t)r*K + k] : Wroot[(size_t)(r-128)*K + k];
        __nv_bfloat16 hi = __float2bfloat16(v);
        g_bh[idx] = hi;
        g_bl[idx] = __float2bfloat16(v - __bfloat162float(hi));
    } else {
        long long gid = (long long)(blockIdx.x - WBLK) * 256 + threadIdx.x;
        long long tot4 = (long long)NNODES * Kpad / 4;
        if (gid >= tot4) return;
        long long base = gid * 4;
        int k = (int)(base % Kpad);
        long long row = base / Kpad;
        float4 v;
        if (k < K) v = *(const float4*)&xin[row * K + k];
        else       v = make_float4(0.f, 0.f, 0.f, 0.f);
        __nv_bfloat16 h0 = __float2bfloat16(v.x), h1 = __float2bfloat16(v.y);
        __nv_bfloat16 h2 = __float2bfloat16(v.z), h3 = __float2bfloat16(v.w);
        __nv_bfloat162* ph = (__nv_bfloat162*)&g_ah[base];
        ph[0] = __nv_bfloat162(h0, h1);
        ph[1] = __nv_bfloat162(h2, h3);
        __nv_bfloat162* pl = (__nv_bfloat162*)&g_al[base];
        pl[0] = __nv_bfloat162(__float2bfloat16(v.x - __bfloat162float(h0)),
                               __float2bfloat16(v.y - __bfloat162float(h1)));
        pl[1] = __nv_bfloat162(__float2bfloat16(v.z - __bfloat162float(h2)),
                               __float2bfloat16(v.w - __bfloat162float(h3)));
    }
}

__global__ void conv_w(const float* __restrict__ Wrel, const float* __restrict__ Wroot,
                       int K, int Kpad) {
    int idx = blockIdx.x * blockDim.x + threadIdx.x;
    if (idx >= 256 * Kpad) return;
    int k = idx % Kpad;
    int r = idx / Kpad;
    float v = 0.f;
    if (k < K) v = (r < 128) ? Wrel[(size_t)r*K + k] : Wroot[(size_t)(r-128)*K + k];
    __nv_bfloat16 hi = __float2bfloat16(v);
    g_bh[idx] = hi;
    g_bl[idx] = __float2bfloat16(v - __bfloat162float(hi));
}

// ---------------- HMMA GEMM (merged-N, cp.async 2-stage) ----------------------
#define STAGE_BYTES 98304
#define GEMM_SMEM   (2*STAGE_BYTES)   // 196608

__global__ __launch_bounds__(512, 1) void hmma_gemm(int Kpad)
{
    extern __shared__ char smem[];
    const int t = threadIdx.x, wid = t >> 5, lane = t & 31;
    const int m0 = blockIdx.x * 128;
    const int warp_m = (wid & 3) * 32;
    const int warp_n = (wid >> 2) * 64;
    const uint32_t sb = smem_u32(smem);
    const int nchunks = Kpad >> 6;

    float acc[2][8][4];
    #pragma unroll
    for (int mi = 0; mi < 2; mi++)
        #pragma unroll
        for (int ni = 0; ni < 8; ni++)
            #pragma unroll
            for (int q = 0; q < 4; q++) acc[mi][ni][q] = 0.f;

    const int j = lane >> 3, rr = lane & 7;

    auto issue = [&](int c, int stage) {
        const int k0 = c * 64;
        const uint32_t sdst = sb + (uint32_t)stage * STAGE_BYTES;
        #pragma unroll
        for (int it = 0; it < 12; it++) {
            int idx = t + it * 512;
            const __nv_bfloat16* src;
            size_t grow;
            uint32_t dstoff;
            int rem;
            if (idx < 2048) {
                int buf = idx >> 10;
                rem = idx & 1023;
                src = buf ? g_al : g_ah;
                grow = (size_t)(m0 + (rem >> 3));
                dstoff = (uint32_t)buf * 16384u;
            } else {
                int j2 = idx - 2048;
                int buf = j2 >> 11;
                rem = j2 & 2047;
                src = buf ? g_bl : g_bh;
                grow = (size_t)(rem >> 3);
                dstoff = 32768u + (uint32_t)buf * 32768u;
            }
            int r = rem >> 3, u = rem & 7;
            const void* gp = src + grow * Kpad + k0 + u*8;
            uint32_t off = (uint32_t)(r*128 + ((u*16) ^ ((r & 7) << 4)));
            cp16(sdst + dstoff + off, gp);
        }
        CP_COMMIT();
    };

    issue(0, 0);
    for (int c = 0; c < nchunks; c++) {
        const int st = c & 1;
        if (c + 1 < nchunks) { issue(c + 1, (c + 1) & 1); CP_WAIT1(); }
        else                 { CP_WAIT0(); }
        __syncthreads();

        const uint32_t sbase = sb + (uint32_t)st*STAGE_BYTES;
        #pragma unroll
        for (int ks = 0; ks < 4; ks++) {
            uint32_t ah[2][4], al[2][4];
            #pragma unroll
            for (int mi = 0; mi < 2; mi++) {
                int arow = warp_m + mi*16 + (j & 1)*8 + rr;
                uint32_t akb = (uint32_t)((ks*32 + (j >> 1)*16) ^ (rr << 4));
                uint32_t addr = sbase + (uint32_t)(arow*128) + akb;
                ldmat_x4(ah[mi], addr);
                ldmat_x4(al[mi], addr + 16384u);
            }
            #pragma unroll
            for (int np = 0; np < 4; np++) {
                uint32_t bh[4], bl[4];
                int brow = warp_n + np*16 + (j >> 1)*8 + rr;
                uint32_t bkb = (uint32_t)((ks*32 + (j & 1)*16) ^ (rr << 4));
                uint32_t baddr = sbase + 32768u + (uint32_t)(brow*128) + bkb;
                ldmat_x4(bh, baddr);
                ldmat_x4(bl, baddr + 32768u);
                #pragma unroll
                for (int p = 0; p < 3; p++) {
                    #pragma unroll
                    for (int tt = 0; tt < 2; tt++) {
                        #pragma unroll
                        for (int mi = 0; mi < 2; mi++) {
                            const uint32_t* af = (p == 2) ? al[mi] : ah[mi];
                            const uint32_t* bf = (p == 1) ? (bl + 2*tt) : (bh + 2*tt);
                            mma_bf16(acc[mi][2*np + tt], af, bf);
                        }
                    }
                }
            }
        }
        __syncthreads();
    }

    const int gid = lane >> 2, tig = lane & 3;
    #pragma unroll
    for (int mi = 0; mi < 2; mi++) {
        #pragma unroll
        for (int ni = 0; ni < 8; ni++) {
            int row = m0 + warp_m + mi*16 + gid;
            int col = warp_n + ni*8 + 2*tig;
            float* p0 = &g_tmp[(size_t)row*256 + col];
            float* p1 = &g_tmp[(size_t)(row + 8)*256 + col];
            *(float2*)p0 = make_float2(acc[mi][ni][0], acc[mi][ni][1]);
            *(float2*)p1 = make_float2(acc[mi][ni][2], acc[mi][ni][3]);
        }
    }
}

// ---------------- fused layer: SpMM + epilogue + score + topk + gate + readout
// one CTA per graph, 256 threads; dynamic smem = xrel slice [400][128] (200KB)
__global__ __launch_bounds__(256) void layer_fused(const float* __restrict__ bias,
                                                   const float* __restrict__ pw,
                                                   int k, int doConv)
{
    extern __shared__ float sx[];   // [400][128]
    __shared__ __align__(16) float red_mx[8][128];
    __shared__ __align__(16) float red_sm[8][128];
    __shared__ unsigned long long skey[512];   // sortable(score)<<9 | (511-v)
    __shared__ float gate[NPERg];
    __shared__ unsigned char selF[NPERg];
    __shared__ __align__(16) float spw[128];
    __shared__ float snorm;

    const int g = blockIdx.x, t = threadIdx.x;
    const int w = t >> 5, lane = t & 31;

    for (int idx = t; idx < NPERg*32; idx += 256) {
        int v = idx >> 5, c4 = (idx & 31) << 2;
        *(float4*)&sx[v*Hdim + c4] =
            *(const float4*)&g_tmp[(size_t)(g*NPERg + v)*256 + c4];
    }
    if (t < 128) spw[t] = pw[t];
    __syncthreads();
    if (t == 0) {
        float s = 0.f;
        for (int i = 0; i < 128; i++) s += spw[i]*spw[i];
        snorm = sqrtf(s) + 1e-16f;
    }
    __syncthreads();

    // ---- phase A: aggregate + epilogue + score ----
    float4 bv = *(const float4*)&bias[lane*4];
    float4 pwv = *(const float4*)&spw[lane*4];
    for (int v = w; v < NPERg; v += 8) {
        int row = g*NPERg + v;
        float4 acc = make_float4(0.f, 0.f, 0.f, 0.f);
        int e0 = g_rowptr[g*(NPERg+1) + v];
        int e1 = g_rowptr[g*(NPERg+1) + v + 1];
        const int* cp = &g_col[g*EPGg];
        int e = e0;
        for (; e + 3 < e1; e += 4) {            // 4x unroll: batch LDG+LDS
            int s0 = cp[e], s1 = cp[e+1], s2 = cp[e+2], s3 = cp[e+3];
            float4 m0 = *(const float4*)&sx[s0*Hdim + lane*4];
            float4 m1 = *(const float4*)&sx[s1*Hdim + lane*4];
            float4 m2 = *(const float4*)&sx[s2*Hdim + lane*4];
            float4 m3 = *(const float4*)&sx[s3*Hdim + lane*4];
            acc.x += (m0.x + m1.x) + (m2.x + m3.x);
            acc.y += (m0.y + m1.y) + (m2.y + m3.y);
            acc.z += (m0.z + m1.z) + (m2.z + m3.z);
            acc.w += (m0.w + m1.w) + (m2.w + m3.w);
        }
        for (; e < e1; e++) {
            int s = cp[e];
            float4 m = *(const float4*)&sx[s*Hdim + lane*4];
            acc.x += m.x; acc.y += m.y; acc.z += m.z; acc.w += m.w;
        }
        int act = g_active[row];
        float4 outv = make_float4(0.f, 0.f, 0.f, 0.f);
        if (act) {
            float4 rt = *(const float4*)&g_tmp[(size_t)row*256 + 128 + lane*4];
            outv.x = fmaxf(acc.x + rt.x + bv.x, 0.f);
            outv.y = fmaxf(acc.y + rt.y + bv.y, 0.f);
            outv.z = fmaxf(acc.z + rt.z + bv.z, 0.f);
            outv.w = fmaxf(acc.w + rt.w + bv.w, 0.f);
        }
        *(float4*)&g_h[(size_t)row*Hdim + lane*4] = outv;
        float d = outv.x*pwv.x + outv.y*pwv.y + outv.z*pwv.z + outv.w*pwv.w;
        #pragma unroll
        for (int o = 16; o > 0; o >>= 1) d += __shfl_xor_sync(0xffffffffu, d, o);
        if (lane == 0) {
            float scv = act ? d / snorm : -1e30f;
            uint32_t ub = __float_as_uint(scv);
            ub = (ub & 0x80000000u) ? ~ub : (ub | 0x80000000u);
            skey[v] = ((unsigned long long)ub << 9) | (unsigned long long)(511 - v);
        }
    }
    for (int i = NPERg + t; i < 512; i += 256) skey[i] = 0ull;
    __syncthreads();

    // ---- phase B: bitonic sort on packed keys (descending) ----
    for (int ksz = 2; ksz <= 512; ksz <<= 1) {
        for (int j = ksz >> 1; j > 0; j >>= 1) {
            for (int i = t; i < 512; i += 256) {
                int ixj = i ^ j;
                if (ixj > i) {
                    unsigned long long a = skey[i], b = skey[ixj];
                    bool up = ((i & ksz) == 0);
                    if ((a < b) == up) { skey[i] = b; skey[ixj] = a; }
                }
            }
            __syncthreads();
        }
    }

    for (int v = t; v < NPERg; v += 256) { gate[v] = 0.f; selF[v] = 0; }
    __syncthreads();
    for (int i = t; i < k; i += 256) {
        unsigned long long kk = skey[i];
        int v = 511 - (int)(kk & 511u);
        uint32_t ub = (uint32_t)(kk >> 9);
        uint32_t fb = (ub & 0x80000000u) ? (ub & 0x7FFFFFFFu) : ~ub;
        gate[v] = tanhf(__uint_as_float(fb));
        selF[v] = 1;
    }
    __syncthreads();

    for (int v = t; v < NPERg; v += 256) g_active[g*NPERg + v] = selF[v];

    // ---- phase C: gate + readout (+ optional bf16 conversion) ----
    const int c4 = (t & 31) << 2;
    const int v0 = t >> 5;
    float4 mx = make_float4(-3.0e38f, -3.0e38f, -3.0e38f, -3.0e38f);
    float4 sm = make_float4(0.f, 0.f, 0.f, 0.f);
    for (int v = v0; v < NPERg; v += 8) {
        size_t row = (size_t)(g*NPERg + v);
        float4 val = *(const float4*)&g_h[row*Hdim + c4];
        float gt = gate[v];
        val.x *= gt; val.y *= gt; val.z *= gt; val.w *= gt;
        if (doConv) {
            __nv_bfloat16 h0 = __float2bfloat16(val.x);
            __nv_bfloat16 h1 = __float2bfloat16(val.y);
            __nv_bfloat16 h2 = __float2bfloat16(val.z);
            __nv_bfloat16 h3 = __float2bfloat16(val.w);
            __nv_bfloat162* ph = (__nv_bfloat162*)&g_ah[row*Hdim + c4];
            ph[0] = __nv_bfloat162(h0, h1);
            ph[1] = __nv_bfloat162(h2, h3);
            __nv_bfloat162* pl = (__nv_bfloat162*)&g_al[row*Hdim + c4];
            pl[0] = __nv_bfloat162(__float2bfloat16(val.x - __bfloat162float(h0)),
                                   __float2bfloat16(val.y - __bfloat162float(h1)));
            pl[1] = __nv_bfloat162(__float2bfloat16(val.z - __bfloat162float(h2)),
                                   __float2bfloat16(val.w - __bfloat162float(h3)));
        }
        if (selF[v]) {
            mx.x = fmaxf(mx.x, val.x); mx.y = fmaxf(mx.y, val.y);
            mx.z = fmaxf(mx.z, val.z); mx.w = fmaxf(mx.w, val.w);
            sm.x += val.x; sm.y += val.y; sm.z += val.z; sm.w += val.w;
        }
    }
    *(float4*)&red_mx[v0][c4] = mx;
    *(float4*)&red_sm[v0][c4] = sm;
    __syncthreads();

    if (t < 128) {
        float m = red_mx[0][t], s = red_sm[0][t];
        #pragma unroll
        for (int r = 1; r < 8; r++) {
            m = fmaxf(m, red_mx[r][t]);
            s += red_sm[r][t];
        }
        g_z[g*256 + t]       += m;
        g_z[g*256 + 128 + t] += s / (float)k;
    }
}

// ---------------- MLP head + log_softmax ----------------
__global__ __launch_bounds__(128) void mlp_kernel(
    const float* __restrict__ W1, const float* __restrict__ bl1,
    const float* __restrict__ W2, const float* __restrict__ bl2,
    const float* __restrict__ W3, const float* __restrict__ bl3,
    float* __restrict__ out)
{
    int g = blockIdx.x, t = threadIdx.x;
    __shared__ float zs[256], a1[128], a2[64], lg[2];
    zs[t]       = g_z[g*256 + t];
    zs[t + 128] = g_z[g*256 + 128 + t];
    __syncthreads();

    {
        float acc = bl1[t];
        const float* wr = &W1[(size_t)t*256];
        for (int kk = 0; kk < 256; kk++) acc += wr[kk]*zs[kk];
        a1[t] = fmaxf(acc, 0.f);
    }
    __syncthreads();
    if (t < 64) {
        float acc = bl2[t];
        const float* wr = &W2[(size_t)t*128];
        for (int kk = 0; kk < 128; kk++) acc += wr[kk]*a1[kk];
        a2[t] = fmaxf(acc, 0.f);
    }
    __syncthreads();
    if (t < 2) {
        float acc = bl3[t];
        const float* wr = &W3[(size_t)t*64];
        for (int kk = 0; kk < 64; kk++) acc += wr[kk]*a2[kk];
        lg[t] = acc;
    }
    __syncthreads();
    if (t < 2) {
        float m = fmaxf(lg[0], lg[1]);
        float lse = m + logf(expf(lg[0] - m) + expf(lg[1] - m));
        out[g*2 + t] = lg[t] - lse;
    }
}

// ---------------- launcher ----------------
extern "C" void kernel_launch(void* const* d_in, const int* in_sizes, int n_in,
                              void* d_out, int out_size)
{
    const float* x      = (const float*)d_in[0];
    const int*   esrc   = (const int*)  d_in[1];
    const int*   edst   = (const int*)  d_in[2];
    const float* Wrel1  = (const float*)d_in[4];
    const float* Wroot1 = (const float*)d_in[5];
    const float* b1     = (const float*)d_in[6];
    const float* pw1    = (const float*)d_in[7];
    const float* Wrel2  = (const float*)d_in[8];
    const float* Wroot2 = (const float*)d_in[9];
    const float* b2     = (const float*)d_in[10];
    const float* pw2    = (const float*)d_in[11];
    const float* Wrel3  = (const float*)d_in[12];
    const float* Wroot3 = (const float*)d_in[13];
    const float* b3     = (const float*)d_in[14];
    const float* pw3    = (const float*)d_in[15];
    const float* W1     = (const float*)d_in[16];
    const float* bl1    = (const float*)d_in[17];
    const float* W2     = (const float*)d_in[18];
    const float* bl2    = (const float*)d_in[19];
    const float* W3     = (const float*)d_in[20];
    const float* bl3    = (const float*)d_in[21];
    float* out = (float*)d_out;

    const int LAYER_SMEM = NPERg * Hdim * (int)sizeof(float);  // 204800
    cudaFuncSetAttribute(layer_fused, cudaFuncAttributeMaxDynamicSharedMemorySize, LAYER_SMEM);
    cudaFuncSetAttribute(hmma_gemm, cudaFuncAttributeMaxDynamicSharedMemorySize, GEMM_SMEM);

    // layer 1 (K=400, Kpad=448); layer_fused now sits in profiled slot #4
    csr_build<<<Bg, 256>>>(esrc, edst);
    conv_all<<<WBLK + ABLK, 256>>>(x, Wrel1, Wroot1, 400, KPAD1);
    hmma_gemm<<<NNODES/128, 512, GEMM_SMEM>>>(KPAD1);
    layer_fused<<<Bg, 256, LAYER_SMEM>>>(b1, pw1, KP1, 1);   // <- profiled

    // layer 2 (K=128)
    conv_w<<<(256*Hdim + 255)/256, 256>>>(Wrel2, Wroot2, Hdim, Hdim);
    hmma_gemm<<<NNODES/128, 512, GEMM_SMEM>>>(Hdim);
    layer_fused<<<Bg, 256, LAYER_SMEM>>>(b2, pw2, KP2, 1);

    // layer 3 (K=128)
    conv_w<<<(256*Hdim + 255)/256, 256>>>(Wrel3, Wroot3, Hdim, Hdim);
    hmma_gemm<<<NNODES/128, 512, GEMM_SMEM>>>(Hdim);
    layer_fused<<<Bg, 256, LAYER_SMEM>>>(b3, pw3, KP3, 0);

    // head
    mlp_kernel<<<Bg, 128>>>(W1, bl1, W2, bl2, W3, bl3, out);
}

// round 14
// speedup vs baseline: 2.5152x; 1.5597x over previous
#include <cuda_runtime.h>
#include <cuda_bf16.h>
#include <math.h>
#include <stdint.h>

#define Bg 128
#define NPERg 400
#define NNODES (Bg*NPERg)      // 51200
#define EPGg 6400
#define NE (Bg*EPGg)           // 819200
#define Hdim 128
#define KP1 320
#define KP2 256
#define KP3 205
#define KPAD1 448              // ceil(400/64)*64

// ---------------- scratch (device globals; no allocation allowed) -------------
__device__ float g_tmp[NNODES*256];     // GEMM out: [xrel | xroot] per node
__device__ float g_h[NNODES*Hdim];      // node features (internal to fused layer)
__device__ int   g_rowptr[Bg*(NPERg+1)];
__device__ int   g_col[NE];             // local src index per CSR entry
__device__ int   g_active[NNODES];
__device__ float g_z[Bg*256];           // accumulated readouts x1+x2+x3
__device__ __align__(16) __nv_bfloat16 g_ah[(size_t)NNODES*KPAD1];  // A hi
__device__ __align__(16) __nv_bfloat16 g_al[(size_t)NNODES*KPAD1];  // A lo
__device__ __align__(16) __nv_bfloat16 g_bh[256*KPAD1];             // B hi
__device__ __align__(16) __nv_bfloat16 g_bl[256*KPAD1];             // B lo

// ---------------- helpers ----------------
__device__ __forceinline__ uint32_t smem_u32(const void* p) {
    uint32_t a;
    asm("{ .reg .u64 t; cvta.to.shared.u64 t, %1; cvt.u32.u64 %0, t; }" : "=r"(a) : "l"(p));
    return a;
}
__device__ __forceinline__ void ldmat_x4(uint32_t* r, uint32_t addr) {
    asm volatile("ldmatrix.sync.aligned.m8n8.x4.shared.b16 {%0,%1,%2,%3}, [%4];"
                 : "=r"(r[0]), "=r"(r[1]), "=r"(r[2]), "=r"(r[3]) : "r"(addr));
}
__device__ __forceinline__ void mma_bf16(float* c, const uint32_t* a, const uint32_t* b) {
    asm volatile("mma.sync.aligned.m16n8k16.row.col.f32.bf16.bf16.f32 "
                 "{%0,%1,%2,%3}, {%4,%5,%6,%7}, {%8,%9}, {%0,%1,%2,%3};"
                 : "+f"(c[0]), "+f"(c[1]), "+f"(c[2]), "+f"(c[3])
                 : "r"(a[0]), "r"(a[1]), "r"(a[2]), "r"(a[3]), "r"(b[0]), "r"(b[1]));
}
__device__ __forceinline__ void cp16(uint32_t saddr, const void* gaddr) {
    asm volatile("cp.async.cg.shared.global [%0], [%1], 16;" :: "r"(saddr), "l"(gaddr));
}
#define CP_COMMIT() asm volatile("cp.async.commit_group;" ::: "memory")
#define CP_WAIT1()  asm volatile("cp.async.wait_group 1;" ::: "memory")
#define CP_WAIT0()  asm volatile("cp.async.wait_group 0;" ::: "memory")

// ---------------- CSR build + state init (one CTA per graph) ------------------
__global__ __launch_bounds__(256) void csr_build(const int* __restrict__ esrc,
                                                 const int* __restrict__ edst)
{
    __shared__ int sdeg[NPERg];
    __shared__ int sa[512], sb2[512];
    __shared__ int cursor[NPERg];
    const int g = blockIdx.x, t = threadIdx.x;
    const int ebase = g * EPGg, vbase = g * NPERg;

    for (int v = t; v < NPERg; v += 256) sdeg[v] = 0;
    __syncthreads();
    for (int e = t; e < EPGg; e += 256)
        atomicAdd(&sdeg[edst[ebase + e] - vbase], 1);
    __syncthreads();

    for (int i = t; i < 512; i += 256) sa[i] = (i < NPERg) ? sdeg[i] : 0;
    __syncthreads();
    int* src = sa; int* dst = sb2;
    for (int off = 1; off < 512; off <<= 1) {
        for (int i = t; i < 512; i += 256)
            dst[i] = src[i] + ((i >= off) ? src[i - off] : 0);
        __syncthreads();
        int* tmp = src; src = dst; dst = tmp;
    }

    for (int v = t; v < NPERg; v += 256) {
        int ex = v ? src[v - 1] : 0;
        g_rowptr[g*(NPERg+1) + v] = ex;
        cursor[v] = ebase + ex;
        g_active[vbase + v] = 1;
    }
    if (t == 0) g_rowptr[g*(NPERg+1) + NPERg] = src[NPERg - 1];
    g_z[g*256 + t] = 0.f;
    __syncthreads();

    for (int e = t; e < EPGg; e += 256) {
        int d = edst[ebase + e] - vbase;
        int s = esrc[ebase + e] - vbase;
        int pos = atomicAdd(&cursor[d], 1);
        g_col[pos] = s;
    }
}

// ---------------- fused conversion: weights + layer-1 input ------------------
#define WBLK ((256*KPAD1 + 255)/256)                        // 448
#define ABLK ((int)(((long long)NNODES*KPAD1/4 + 255)/256)) // 22400
__global__ void conv_all(const float* __restrict__ xin,
                         const float* __restrict__ Wrel, const float* __restrict__ Wroot,
                         int K, int Kpad)
{
    if (blockIdx.x < WBLK) {
        int idx = blockIdx.x * 256 + threadIdx.x;
        if (idx >= 256 * Kpad) return;
        int k = idx % Kpad;
        int r = idx / Kpad;
        float v = 0.f;
        if (k < K) v = (r < 128) ? Wrel[(size_t)r*K + k] : Wroot[(size_t)(r-128)*K + k];
        __nv_bfloat16 hi = __float2bfloat16(v);
        g_bh[idx] = hi;
        g_bl[idx] = __float2bfloat16(v - __bfloat162float(hi));
    } else {
        long long gid = (long long)(blockIdx.x - WBLK) * 256 + threadIdx.x;
        long long tot4 = (long long)NNODES * Kpad / 4;
        if (gid >= tot4) return;
        long long base = gid * 4;
        int k = (int)(base % Kpad);
        long long row = base / Kpad;
        float4 v;
        if (k < K) v = *(const float4*)&xin[row * K + k];
        else       v = make_float4(0.f, 0.f, 0.f, 0.f);
        __nv_bfloat16 h0 = __float2bfloat16(v.x), h1 = __float2bfloat16(v.y);
        __nv_bfloat16 h2 = __float2bfloat16(v.z), h3 = __float2bfloat16(v.w);
        __nv_bfloat162* ph = (__nv_bfloat162*)&g_ah[base];
        ph[0] = __nv_bfloat162(h0, h1);
        ph[1] = __nv_bfloat162(h2, h3);
        __nv_bfloat162* pl = (__nv_bfloat162*)&g_al[base];
        pl[0] = __nv_bfloat162(__float2bfloat16(v.x - __bfloat162float(h0)),
                               __float2bfloat16(v.y - __bfloat162float(h1)));
        pl[1] = __nv_bfloat162(__float2bfloat16(v.z - __bfloat162float(h2)),
                               __float2bfloat16(v.w - __bfloat162float(h3)));
    }
}

__global__ void conv_w(const float* __restrict__ Wrel, const float* __restrict__ Wroot,
                       int K, int Kpad) {
    int idx = blockIdx.x * blockDim.x + threadIdx.x;
    if (idx >= 256 * Kpad) return;
    int k = idx % Kpad;
    int r = idx / Kpad;
    float v = 0.f;
    if (k < K) v = (r < 128) ? Wrel[(size_t)r*K + k] : Wroot[(size_t)(r-128)*K + k];
    __nv_bfloat16 hi = __float2bfloat16(v);
    g_bh[idx] = hi;
    g_bl[idx] = __float2bfloat16(v - __bfloat162float(hi));
}

// ---------------- HMMA GEMM (merged-N, cp.async 2-stage) ----------------------
#define STAGE_BYTES 98304
#define GEMM_SMEM   (2*STAGE_BYTES)   // 196608

__global__ __launch_bounds__(512, 1) void hmma_gemm(int Kpad)
{
    extern __shared__ char smem[];
    const int t = threadIdx.x, wid = t >> 5, lane = t & 31;
    const int m0 = blockIdx.x * 128;
    const int warp_m = (wid & 3) * 32;
    const int warp_n = (wid >> 2) * 64;
    const uint32_t sb = smem_u32(smem);
    const int nchunks = Kpad >> 6;

    float acc[2][8][4];
    #pragma unroll
    for (int mi = 0; mi < 2; mi++)
        #pragma unroll
        for (int ni = 0; ni < 8; ni++)
            #pragma unroll
            for (int q = 0; q < 4; q++) acc[mi][ni][q] = 0.f;

    const int j = lane >> 3, rr = lane & 7;

    auto issue = [&](int c, int stage) {
        const int k0 = c * 64;
        const uint32_t sdst = sb + (uint32_t)stage * STAGE_BYTES;
        #pragma unroll
        for (int it = 0; it < 12; it++) {
            int idx = t + it * 512;
            const __nv_bfloat16* src;
            size_t grow;
            uint32_t dstoff;
            int rem;
            if (idx < 2048) {
                int buf = idx >> 10;
                rem = idx & 1023;
                src = buf ? g_al : g_ah;
                grow = (size_t)(m0 + (rem >> 3));
                dstoff = (uint32_t)buf * 16384u;
            } else {
                int j2 = idx - 2048;
                int buf = j2 >> 11;
                rem = j2 & 2047;
                src = buf ? g_bl : g_bh;
                grow = (size_t)(rem >> 3);
                dstoff = 32768u + (uint32_t)buf * 32768u;
            }
            int r = rem >> 3, u = rem & 7;
            const void* gp = src + grow * Kpad + k0 + u*8;
            uint32_t off = (uint32_t)(r*128 + ((u*16) ^ ((r & 7) << 4)));
            cp16(sdst + dstoff + off, gp);
        }
        CP_COMMIT();
    };

    issue(0, 0);
    for (int c = 0; c < nchunks; c++) {
        const int st = c & 1;
        if (c + 1 < nchunks) { issue(c + 1, (c + 1) & 1); CP_WAIT1(); }
        else                 { CP_WAIT0(); }
        __syncthreads();

        const uint32_t sbase = sb + (uint32_t)st*STAGE_BYTES;
        #pragma unroll
        for (int ks = 0; ks < 4; ks++) {
            uint32_t ah[2][4], al[2][4];
            #pragma unroll
            for (int mi = 0; mi < 2; mi++) {
                int arow = warp_m + mi*16 + (j & 1)*8 + rr;
                uint32_t akb = (uint32_t)((ks*32 + (j >> 1)*16) ^ (rr << 4));
                uint32_t addr = sbase + (uint32_t)(arow*128) + akb;
                ldmat_x4(ah[mi], addr);
                ldmat_x4(al[mi], addr + 16384u);
            }
            #pragma unroll
            for (int np = 0; np < 4; np++) {
                uint32_t bh[4], bl[4];
                int brow = warp_n + np*16 + (j >> 1)*8 + rr;
                uint32_t bkb = (uint32_t)((ks*32 + (j & 1)*16) ^ (rr << 4));
                uint32_t baddr = sbase + 32768u + (uint32_t)(brow*128) + bkb;
                ldmat_x4(bh, baddr);
                ldmat_x4(bl, baddr + 32768u);
                #pragma unroll
                for (int p = 0; p < 3; p++) {
                    #pragma unroll
                    for (int tt = 0; tt < 2; tt++) {
                        #pragma unroll
                        for (int mi = 0; mi < 2; mi++) {
                            const uint32_t* af = (p == 2) ? al[mi] : ah[mi];
                            const uint32_t* bf = (p == 1) ? (bl + 2*tt) : (bh + 2*tt);
                            mma_bf16(acc[mi][2*np + tt], af, bf);
                        }
                    }
                }
            }
        }
        __syncthreads();
    }

    const int gid = lane >> 2, tig = lane & 3;
    #pragma unroll
    for (int mi = 0; mi < 2; mi++) {
        #pragma unroll
        for (int ni = 0; ni < 8; ni++) {
            int row = m0 + warp_m + mi*16 + gid;
            int col = warp_n + ni*8 + 2*tig;
            float* p0 = &g_tmp[(size_t)row*256 + col];
            float* p1 = &g_tmp[(size_t)(row + 8)*256 + col];
            *(float2*)p0 = make_float2(acc[mi][ni][0], acc[mi][ni][1]);
            *(float2*)p1 = make_float2(acc[mi][ni][2], acc[mi][ni][3]);
        }
    }
}

// ---------------- fused layer: SpMM + epilogue + score + topk + gate + readout
// one CTA per graph, 1024 threads (32 warps); dynamic smem = xrel [400][128]
// (200KB). The 200KB tile is DEAD after phase A; the phase-C reduction buffers
// alias into it (red_mx = sx[0:4096], red_sm = sx[4096:8192]).
__global__ __launch_bounds__(1024) void layer_fused(const float* __restrict__ bias,
                                                    const float* __restrict__ pw,
                                                    int k, int doConv)
{
    extern __shared__ float sx[];   // [400][128]
    __shared__ unsigned long long skey[512];   // sortable(score)<<9 | (511-v)
    __shared__ float gate[NPERg];
    __shared__ unsigned char selF[NPERg];
    __shared__ __align__(16) float spw[128];
    __shared__ float snorm;

    const int g = blockIdx.x, t = threadIdx.x;
    const int w = t >> 5, lane = t & 31;

    for (int idx = t; idx < NPERg*32; idx += 1024) {
        int v = idx >> 5, c4 = (idx & 31) << 2;
        *(float4*)&sx[v*Hdim + c4] =
            *(const float4*)&g_tmp[(size_t)(g*NPERg + v)*256 + c4];
    }
    if (t < 128) spw[t] = pw[t];
    __syncthreads();
    if (t == 0) {
        float s = 0.f;
        for (int i = 0; i < 128; i++) s += spw[i]*spw[i];
        snorm = sqrtf(s) + 1e-16f;
    }
    __syncthreads();

    // ---- phase A: aggregate + epilogue + score (32 warps, ~13 nodes each) ----
    float4 bv = *(const float4*)&bias[lane*4];
    float4 pwv = *(const float4*)&spw[lane*4];
    for (int v = w; v < NPERg; v += 32) {
        int row = g*NPERg + v;
        float4 acc = make_float4(0.f, 0.f, 0.f, 0.f);
        int e0 = g_rowptr[g*(NPERg+1) + v];
        int e1 = g_rowptr[g*(NPERg+1) + v + 1];
        const int* cp = &g_col[g*EPGg];
        int e = e0;
        for (; e + 3 < e1; e += 4) {
            int s0 = cp[e], s1 = cp[e+1], s2 = cp[e+2], s3 = cp[e+3];
            float4 m0 = *(const float4*)&sx[s0*Hdim + lane*4];
            float4 m1 = *(const float4*)&sx[s1*Hdim + lane*4];
            float4 m2 = *(const float4*)&sx[s2*Hdim + lane*4];
            float4 m3 = *(const float4*)&sx[s3*Hdim + lane*4];
            acc.x += (m0.x + m1.x) + (m2.x + m3.x);
            acc.y += (m0.y + m1.y) + (m2.y + m3.y);
            acc.z += (m0.z + m1.z) + (m2.z + m3.z);
            acc.w += (m0.w + m1.w) + (m2.w + m3.w);
        }
        for (; e < e1; e++) {
            int s = cp[e];
            float4 m = *(const float4*)&sx[s*Hdim + lane*4];
            acc.x += m.x; acc.y += m.y; acc.z += m.z; acc.w += m.w;
        }
        int act = g_active[row];
        float4 outv = make_float4(0.f, 0.f, 0.f, 0.f);
        if (act) {
            float4 rt = *(const float4*)&g_tmp[(size_t)row*256 + 128 + lane*4];
            outv.x = fmaxf(acc.x + rt.x + bv.x, 0.f);
            outv.y = fmaxf(acc.y + rt.y + bv.y, 0.f);
            outv.z = fmaxf(acc.z + rt.z + bv.z, 0.f);
            outv.w = fmaxf(acc.w + rt.w + bv.w, 0.f);
        }
        *(float4*)&g_h[(size_t)row*Hdim + lane*4] = outv;
        float d = outv.x*pwv.x + outv.y*pwv.y + outv.z*pwv.z + outv.w*pwv.w;
        #pragma unroll
        for (int o = 16; o > 0; o >>= 1) d += __shfl_xor_sync(0xffffffffu, d, o);
        if (lane == 0) {
            float scv = act ? d / snorm : -1e30f;
            uint32_t ub = __float_as_uint(scv);
            ub = (ub & 0x80000000u) ? ~ub : (ub | 0x80000000u);
            skey[v] = ((unsigned long long)ub << 9) | (unsigned long long)(511 - v);
        }
    }
    for (int i = NPERg + t; i < 512; i += 1024) skey[i] = 0ull;
    __syncthreads();

    // ---- phase B: bitonic sort on packed keys (descending) ----
    for (int ksz = 2; ksz <= 512; ksz <<= 1) {
        for (int j = ksz >> 1; j > 0; j >>= 1) {
            if (t < 512) {
                int i = t;
                int ixj = i ^ j;
                if (ixj > i) {
                    unsigned long long a = skey[i], b = skey[ixj];
                    bool up = ((i & ksz) == 0);
                    if ((a < b) == up) { skey[i] = b; skey[ixj] = a; }
                }
            }
            __syncthreads();
        }
    }

    for (int v = t; v < NPERg; v += 1024) { gate[v] = 0.f; selF[v] = 0; }
    __syncthreads();
    if (t < k) {
        unsigned long long kk = skey[t];
        int v = 511 - (int)(kk & 511u);
        uint32_t ub = (uint32_t)(kk >> 9);
        uint32_t fb = (ub & 0x80000000u) ? (ub & 0x7FFFFFFFu) : ~ub;
        gate[v] = tanhf(__uint_as_float(fb));
        selF[v] = 1;
    }
    __syncthreads();

    for (int v = t; v < NPERg; v += 1024) g_active[g*NPERg + v] = selF[v];

    // ---- phase C: gate + readout (+ optional bf16 conversion) ----
    // reduction buffers alias the (now dead) sx tile
    float* red_mx = sx;                 // [32][128]
    float* red_sm = sx + 32*128;        // [32][128]
    const int c4 = (lane) << 2;         // 0..124
    const int v0 = w;                   // 0..31
    float4 mx = make_float4(-3.0e38f, -3.0e38f, -3.0e38f, -3.0e38f);
    float4 sm = make_float4(0.f, 0.f, 0.f, 0.f);
    for (int v = v0; v < NPERg; v += 32) {
        size_t row = (size_t)(g*NPERg + v);
        float4 val = *(const float4*)&g_h[row*Hdim + c4];
        float gt = gate[v];
        val.x *= gt; val.y *= gt; val.z *= gt; val.w *= gt;
        if (doConv) {
            __nv_bfloat16 h0 = __float2bfloat16(val.x);
            __nv_bfloat16 h1 = __float2bfloat16(val.y);
            __nv_bfloat16 h2 = __float2bfloat16(val.z);
            __nv_bfloat16 h3 = __float2bfloat16(val.w);
            __nv_bfloat162* ph = (__nv_bfloat162*)&g_ah[row*Hdim + c4];
            ph[0] = __nv_bfloat162(h0, h1);
            ph[1] = __nv_bfloat162(h2, h3);
            __nv_bfloat162* pl = (__nv_bfloat162*)&g_al[row*Hdim + c4];
            pl[0] = __nv_bfloat162(__float2bfloat16(val.x - __bfloat162float(h0)),
                                   __float2bfloat16(val.y - __bfloat162float(h1)));
            pl[1] = __nv_bfloat162(__float2bfloat16(val.z - __bfloat162float(h2)),
                                   __float2bfloat16(val.w - __bfloat162float(h3)));
        }
        if (selF[v]) {
            mx.x = fmaxf(mx.x, val.x); mx.y = fmaxf(mx.y, val.y);
            mx.z = fmaxf(mx.z, val.z); mx.w = fmaxf(mx.w, val.w);
            sm.x += val.x; sm.y += val.y; sm.z += val.z; sm.w += val.w;
        }
    }
    *(float4*)&red_mx[v0*128 + c4] = mx;
    *(float4*)&red_sm[v0*128 + c4] = sm;
    __syncthreads();

    if (t < 128) {
        float m = red_mx[t], s = red_sm[t];
        #pragma unroll
        for (int r = 1; r < 32; r++) {
            m = fmaxf(m, red_mx[r*128 + t]);
            s += red_sm[r*128 + t];
        }
        g_z[g*256 + t]       += m;
        g_z[g*256 + 128 + t] += s / (float)k;
    }
}

// ---------------- MLP head + log_softmax ----------------
__global__ __launch_bounds__(128) void mlp_kernel(
    const float* __restrict__ W1, const float* __restrict__ bl1,
    const float* __restrict__ W2, const float* __restrict__ bl2,
    const float* __restrict__ W3, const float* __restrict__ bl3,
    float* __restrict__ out)
{
    int g = blockIdx.x, t = threadIdx.x;
    __shared__ float zs[256], a1[128], a2[64], lg[2];
    zs[t]       = g_z[g*256 + t];
    zs[t + 128] = g_z[g*256 + 128 + t];
    __syncthreads();

    {
        float acc = bl1[t];
        const float* wr = &W1[(size_t)t*256];
        for (int kk = 0; kk < 256; kk++) acc += wr[kk]*zs[kk];
        a1[t] = fmaxf(acc, 0.f);
    }
    __syncthreads();
    if (t < 64) {
        float acc = bl2[t];
        const float* wr = &W2[(size_t)t*128];
        for (int kk = 0; kk < 128; kk++) acc += wr[kk]*a1[kk];
        a2[t] = fmaxf(acc, 0.f);
    }
    __syncthreads();
    if (t < 2) {
        float acc = bl3[t];
        const float* wr = &W3[(size_t)t*64];
        for (int kk = 0; kk < 64; kk++) acc += wr[kk]*a2[kk];
        lg[t] = acc;
    }
    __syncthreads();
    if (t < 2) {
        float m = fmaxf(lg[0], lg[1]);
        float lse = m + logf(expf(lg[0] - m) + expf(lg[1] - m));
        out[g*2 + t] = lg[t] - lse;
    }
}

// ---------------- launcher ----------------
extern "C" void kernel_launch(void* const* d_in, const int* in_sizes, int n_in,
                              void* d_out, int out_size)
{
    const float* x      = (const float*)d_in[0];
    const int*   esrc   = (const int*)  d_in[1];
    const int*   edst   = (const int*)  d_in[2];
    const float* Wrel1  = (const float*)d_in[4];
    const float* Wroot1 = (const float*)d_in[5];
    const float* b1     = (const float*)d_in[6];
    const float* pw1    = (const float*)d_in[7];
    const float* Wrel2  = (const float*)d_in[8];
    const float* Wroot2 = (const float*)d_in[9];
    const float* b2     = (const float*)d_in[10];
    const float* pw2    = (const float*)d_in[11];
    const float* Wrel3  = (const float*)d_in[12];
    const float* Wroot3 = (const float*)d_in[13];
    const float* b3     = (const float*)d_in[14];
    const float* pw3    = (const float*)d_in[15];
    const float* W1     = (const float*)d_in[16];
    const float* bl1    = (const float*)d_in[17];
    const float* W2     = (const float*)d_in[18];
    const float* bl2    = (const float*)d_in[19];
    const float* W3     = (const float*)d_in[20];
    const float* bl3    = (const float*)d_in[21];
    float* out = (float*)d_out;

    const int LAYER_SMEM = NPERg * Hdim * (int)sizeof(float);  // 204800
    cudaFuncSetAttribute(layer_fused, cudaFuncAttributeMaxDynamicSharedMemorySize, LAYER_SMEM);
    cudaFuncSetAttribute(hmma_gemm, cudaFuncAttributeMaxDynamicSharedMemorySize, GEMM_SMEM);

    // layer 1 (K=400, Kpad=448); layer_fused in profiled slot #4
    csr_build<<<Bg, 256>>>(esrc, edst);
    conv_all<<<WBLK + ABLK, 256>>>(x, Wrel1, Wroot1, 400, KPAD1);
    hmma_gemm<<<NNODES/128, 512, GEMM_SMEM>>>(KPAD1);
    layer_fused<<<Bg, 1024, LAYER_SMEM>>>(b1, pw1, KP1, 1);  // <- profiled

    // layer 2 (K=128)
    conv_w<<<(256*Hdim + 255)/256, 256>>>(Wrel2, Wroot2, Hdim, Hdim);
    hmma_gemm<<<NNODES/128, 512, GEMM_SMEM>>>(Hdim);
    layer_fused<<<Bg, 1024, LAYER_SMEM>>>(b2, pw2, KP2, 1);

    // layer 3 (K=128)
    conv_w<<<(256*Hdim + 255)/256, 256>>>(Wrel3, Wroot3, Hdim, Hdim);
    hmma_gemm<<<NNODES/128, 512, GEMM_SMEM>>>(Hdim);
    layer_fused<<<Bg, 1024, LAYER_SMEM>>>(b3, pw3, KP3, 0);

    // head
    mlp_kernel<<<Bg, 128>>>(W1, bl1, W2, bl2, W3, bl3, out);
}

// round 15
// speedup vs baseline: 2.5874x; 1.0287x over previous
#include <cuda_runtime.h>
#include <cuda_bf16.h>
#include <math.h>
#include <stdint.h>

#define Bg 128
#define NPERg 400
#define NNODES (Bg*NPERg)      // 51200
#define EPGg 6400
#define NE (Bg*EPGg)           // 819200
#define Hdim 128
#define KP1 320
#define KP2 256
#define KP3 205
#define KPAD1 448              // ceil(400/64)*64

// ---------------- scratch (device globals; no allocation allowed) -------------
__device__ float g_tmp[NNODES*256];     // GEMM out: [xrel | xroot] per node
__device__ float g_h[NNODES*Hdim];      // node features (internal to fused layer)
__device__ int   g_rowptr[Bg*(NPERg+1)];
__device__ int   g_col[NE];             // local src index per CSR entry
__device__ int   g_active[NNODES];
__device__ float g_z[Bg*256];           // accumulated readouts x1+x2 (L3 in-reg)
__device__ __align__(16) __nv_bfloat16 g_ah[(size_t)NNODES*KPAD1];  // A hi
__device__ __align__(16) __nv_bfloat16 g_al[(size_t)NNODES*KPAD1];  // A lo
__device__ __align__(16) __nv_bfloat16 g_bh[256*KPAD1];             // B hi
__device__ __align__(16) __nv_bfloat16 g_bl[256*KPAD1];             // B lo

// ---------------- helpers ----------------
__device__ __forceinline__ uint32_t smem_u32(const void* p) {
    uint32_t a;
    asm("{ .reg .u64 t; cvta.to.shared.u64 t, %1; cvt.u32.u64 %0, t; }" : "=r"(a) : "l"(p));
    return a;
}
__device__ __forceinline__ void ldmat_x4(uint32_t* r, uint32_t addr) {
    asm volatile("ldmatrix.sync.aligned.m8n8.x4.shared.b16 {%0,%1,%2,%3}, [%4];"
                 : "=r"(r[0]), "=r"(r[1]), "=r"(r[2]), "=r"(r[3]) : "r"(addr));
}
__device__ __forceinline__ void mma_bf16(float* c, const uint32_t* a, const uint32_t* b) {
    asm volatile("mma.sync.aligned.m16n8k16.row.col.f32.bf16.bf16.f32 "
                 "{%0,%1,%2,%3}, {%4,%5,%6,%7}, {%8,%9}, {%0,%1,%2,%3};"
                 : "+f"(c[0]), "+f"(c[1]), "+f"(c[2]), "+f"(c[3])
                 : "r"(a[0]), "r"(a[1]), "r"(a[2]), "r"(a[3]), "r"(b[0]), "r"(b[1]));
}
__device__ __forceinline__ void cp16(uint32_t saddr, const void* gaddr) {
    asm volatile("cp.async.cg.shared.global [%0], [%1], 16;" :: "r"(saddr), "l"(gaddr));
}
#define CP_COMMIT() asm volatile("cp.async.commit_group;" ::: "memory")
#define CP_WAIT1()  asm volatile("cp.async.wait_group 1;" ::: "memory")
#define CP_WAIT0()  asm volatile("cp.async.wait_group 0;" ::: "memory")

// ---------------- CSR build + state init (one CTA per graph) ------------------
__global__ __launch_bounds__(256) void csr_build(const int* __restrict__ esrc,
                                                 const int* __restrict__ edst)
{
    __shared__ int sdeg[NPERg];
    __shared__ int sa[512], sb2[512];
    __shared__ int cursor[NPERg];
    const int g = blockIdx.x, t = threadIdx.x;
    const int ebase = g * EPGg, vbase = g * NPERg;

    for (int v = t; v < NPERg; v += 256) sdeg[v] = 0;
    __syncthreads();
    for (int e = t; e < EPGg; e += 256)
        atomicAdd(&sdeg[edst[ebase + e] - vbase], 1);
    __syncthreads();

    for (int i = t; i < 512; i += 256) sa[i] = (i < NPERg) ? sdeg[i] : 0;
    __syncthreads();
    int* src = sa; int* dst = sb2;
    for (int off = 1; off < 512; off <<= 1) {
        for (int i = t; i < 512; i += 256)
            dst[i] = src[i] + ((i >= off) ? src[i - off] : 0);
        __syncthreads();
        int* tmp = src; src = dst; dst = tmp;
    }

    for (int v = t; v < NPERg; v += 256) {
        int ex = v ? src[v - 1] : 0;
        g_rowptr[g*(NPERg+1) + v] = ex;
        cursor[v] = ebase + ex;
        g_active[vbase + v] = 1;
    }
    if (t == 0) g_rowptr[g*(NPERg+1) + NPERg] = src[NPERg - 1];
    g_z[g*256 + t] = 0.f;
    __syncthreads();

    for (int e = t; e < EPGg; e += 256) {
        int d = edst[ebase + e] - vbase;
        int s = esrc[ebase + e] - vbase;
        int pos = atomicAdd(&cursor[d], 1);
        g_col[pos] = s;
    }
}

// ---------------- fused conversion: weights + layer-1 input ------------------
#define WBLK ((256*KPAD1 + 255)/256)                        // 448
#define ABLK ((int)(((long long)NNODES*KPAD1/4 + 255)/256)) // 22400
__global__ void conv_all(const float* __restrict__ xin,
                         const float* __restrict__ Wrel, const float* __restrict__ Wroot,
                         int K, int Kpad)
{
    if (blockIdx.x < WBLK) {
        int idx = blockIdx.x * 256 + threadIdx.x;
        if (idx >= 256 * Kpad) return;
        int k = idx % Kpad;
        int r = idx / Kpad;
        float v = 0.f;
        if (k < K) v = (r < 128) ? Wrel[(size_t)r*K + k] : Wroot[(size_t)(r-128)*K + k];
        __nv_bfloat16 hi = __float2bfloat16(v);
        g_bh[idx] = hi;
        g_bl[idx] = __float2bfloat16(v - __bfloat162float(hi));
    } else {
        long long gid = (long long)(blockIdx.x - WBLK) * 256 + threadIdx.x;
        long long tot4 = (long long)NNODES * Kpad / 4;
        if (gid >= tot4) return;
        long long base = gid * 4;
        int k = (int)(base % Kpad);
        long long row = base / Kpad;
        float4 v;
        if (k < K) v = *(const float4*)&xin[row * K + k];
        else       v = make_float4(0.f, 0.f, 0.f, 0.f);
        __nv_bfloat16 h0 = __float2bfloat16(v.x), h1 = __float2bfloat16(v.y);
        __nv_bfloat16 h2 = __float2bfloat16(v.z), h3 = __float2bfloat16(v.w);
        __nv_bfloat162* ph = (__nv_bfloat162*)&g_ah[base];
        ph[0] = __nv_bfloat162(h0, h1);
        ph[1] = __nv_bfloat162(h2, h3);
        __nv_bfloat162* pl = (__nv_bfloat162*)&g_al[base];
        pl[0] = __nv_bfloat162(__float2bfloat16(v.x - __bfloat162float(h0)),
                               __float2bfloat16(v.y - __bfloat162float(h1)));
        pl[1] = __nv_bfloat162(__float2bfloat16(v.z - __bfloat162float(h2)),
                               __float2bfloat16(v.w - __bfloat162float(h3)));
    }
}

__global__ void conv_w(const float* __restrict__ Wrel, const float* __restrict__ Wroot,
                       int K, int Kpad) {
    int idx = blockIdx.x * blockDim.x + threadIdx.x;
    if (idx >= 256 * Kpad) return;
    int k = idx % Kpad;
    int r = idx / Kpad;
    float v = 0.f;
    if (k < K) v = (r < 128) ? Wrel[(size_t)r*K + k] : Wroot[(size_t)(r-128)*K + k];
    __nv_bfloat16 hi = __float2bfloat16(v);
    g_bh[idx] = hi;
    g_bl[idx] = __float2bfloat16(v - __bfloat162float(hi));
}

// ---------------- HMMA GEMM (merged-N, cp.async 2-stage, pad-skip) ------------
#define STAGE_BYTES 98304
#define GEMM_SMEM   (2*STAGE_BYTES)   // 196608

__global__ __launch_bounds__(512, 1) void hmma_gemm(int K, int Kpad)
{
    extern __shared__ char smem[];
    const int t = threadIdx.x, wid = t >> 5, lane = t & 31;
    const int m0 = blockIdx.x * 128;
    const int warp_m = (wid & 3) * 32;
    const int warp_n = (wid >> 2) * 64;
    const uint32_t sb = smem_u32(smem);
    const int nchunks = Kpad >> 6;

    float acc[2][8][4];
    #pragma unroll
    for (int mi = 0; mi < 2; mi++)
        #pragma unroll
        for (int ni = 0; ni < 8; ni++)
            #pragma unroll
            for (int q = 0; q < 4; q++) acc[mi][ni][q] = 0.f;

    const int j = lane >> 3, rr = lane & 7;

    auto issue = [&](int c, int stage) {
        const int k0 = c * 64;
        const uint32_t sdst = sb + (uint32_t)stage * STAGE_BYTES;
        #pragma unroll
        for (int it = 0; it < 12; it++) {
            int idx = t + it * 512;
            const __nv_bfloat16* src;
            size_t grow;
            uint32_t dstoff;
            int rem;
            if (idx < 2048) {
                int buf = idx >> 10;
                rem = idx & 1023;
                src = buf ? g_al : g_ah;
                grow = (size_t)(m0 + (rem >> 3));
                dstoff = (uint32_t)buf * 16384u;
            } else {
                int j2 = idx - 2048;
                int buf = j2 >> 11;
                rem = j2 & 2047;
                src = buf ? g_bl : g_bh;
                grow = (size_t)(rem >> 3);
                dstoff = 32768u + (uint32_t)buf * 32768u;
            }
            int r = rem >> 3, u = rem & 7;
            const void* gp = src + grow * Kpad + k0 + u*8;
            uint32_t off = (uint32_t)(r*128 + ((u*16) ^ ((r & 7) << 4)));
            cp16(sdst + dstoff + off, gp);
        }
        CP_COMMIT();
    };

    issue(0, 0);
    for (int c = 0; c < nchunks; c++) {
        const int st = c & 1;
        if (c + 1 < nchunks) { issue(c + 1, (c + 1) & 1); CP_WAIT1(); }
        else                 { CP_WAIT0(); }
        __syncthreads();

        const uint32_t sbase = sb + (uint32_t)st*STAGE_BYTES;
        // skip pure-padding k16 steps (k >= K is zero-filled)
        const int ksmax = min(4, (K - c*64 + 15) >> 4);
        for (int ks = 0; ks < ksmax; ks++) {
            uint32_t ah[2][4], al[2][4];
            #pragma unroll
            for (int mi = 0; mi < 2; mi++) {
                int arow = warp_m + mi*16 + (j & 1)*8 + rr;
                uint32_t akb = (uint32_t)((ks*32 + (j >> 1)*16) ^ (rr << 4));
                uint32_t addr = sbase + (uint32_t)(arow*128) + akb;
                ldmat_x4(ah[mi], addr);
                ldmat_x4(al[mi], addr + 16384u);
            }
            #pragma unroll
            for (int np = 0; np < 4; np++) {
                uint32_t bh[4], bl[4];
                int brow = warp_n + np*16 + (j >> 1)*8 + rr;
                uint32_t bkb = (uint32_t)((ks*32 + (j & 1)*16) ^ (rr << 4));
                uint32_t baddr = sbase + 32768u + (uint32_t)(brow*128) + bkb;
                ldmat_x4(bh, baddr);
                ldmat_x4(bl, baddr + 32768u);
                #pragma unroll
                for (int p = 0; p < 3; p++) {
                    #pragma unroll
                    for (int tt = 0; tt < 2; tt++) {
                        #pragma unroll
                        for (int mi = 0; mi < 2; mi++) {
                            const uint32_t* af = (p == 2) ? al[mi] : ah[mi];
                            const uint32_t* bf = (p == 1) ? (bl + 2*tt) : (bh + 2*tt);
                            mma_bf16(acc[mi][2*np + tt], af, bf);
                        }
                    }
                }
            }
        }
        __syncthreads();
    }

    const int gid = lane >> 2, tig = lane & 3;
    #pragma unroll
    for (int mi = 0; mi < 2; mi++) {
        #pragma unroll
        for (int ni = 0; ni < 8; ni++) {
            int row = m0 + warp_m + mi*16 + gid;
            int col = warp_n + ni*8 + 2*tig;
            float* p0 = &g_tmp[(size_t)row*256 + col];
            float* p1 = &g_tmp[(size_t)(row + 8)*256 + col];
            *(float2*)p0 = make_float2(acc[mi][ni][0], acc[mi][ni][1]);
            *(float2*)p1 = make_float2(acc[mi][ni][2], acc[mi][ni][3]);
        }
    }
}

// ---------------- fused layer: SpMM + epi + score + topk + gate + readout -----
// one CTA per graph, 1024 threads; dynamic smem = xrel [400][128] (200KB).
// Tile is dead after phase A; phase-C reduction buffers alias into it.
// doMLP: run the MLP head + log_softmax in-CTA (layer 3 only).
__global__ __launch_bounds__(1024) void layer_fused(
    const float* __restrict__ bias, const float* __restrict__ pw,
    int k, int doConv, int doMLP,
    const float* __restrict__ W1, const float* __restrict__ bl1,
    const float* __restrict__ W2, const float* __restrict__ bl2,
    const float* __restrict__ W3, const float* __restrict__ bl3,
    float* __restrict__ out)
{
    extern __shared__ float sx[];   // [400][128]
    __shared__ unsigned long long skey[512];   // sortable(score)<<9 | (511-v)
    __shared__ float gate[NPERg];              // reused as zs[256] for MLP
    __shared__ unsigned char selF[NPERg];
    __shared__ __align__(16) float spw[128];
    __shared__ float snorm;
    __shared__ float a1s[128], a2s[64], lgs[2];

    const int g = blockIdx.x, t = threadIdx.x;
    const int w = t >> 5, lane = t & 31;

    for (int idx = t; idx < NPERg*32; idx += 1024) {
        int v = idx >> 5, c4i = (idx & 31) << 2;
        *(float4*)&sx[v*Hdim + c4i] =
            *(const float4*)&g_tmp[(size_t)(g*NPERg + v)*256 + c4i];
    }
    if (t < 128) spw[t] = pw[t];
    __syncthreads();
    if (t == 0) {
        float s = 0.f;
        for (int i = 0; i < 128; i++) s += spw[i]*spw[i];
        snorm = sqrtf(s) + 1e-16f;
    }
    __syncthreads();

    // ---- phase A: aggregate + epilogue + score ----
    float4 bv = *(const float4*)&bias[lane*4];
    float4 pwv = *(const float4*)&spw[lane*4];
    for (int v = w; v < NPERg; v += 32) {
        int row = g*NPERg + v;
        int act = g_active[row];
        float4 outv = make_float4(0.f, 0.f, 0.f, 0.f);
        if (act) {                        // skip dead nodes entirely
            float4 acc = make_float4(0.f, 0.f, 0.f, 0.f);
            int e0 = g_rowptr[g*(NPERg+1) + v];
            int e1 = g_rowptr[g*(NPERg+1) + v + 1];
            const int* cp = &g_col[g*EPGg];
            int e = e0;
            for (; e + 3 < e1; e += 4) {
                int s0 = cp[e], s1 = cp[e+1], s2 = cp[e+2], s3 = cp[e+3];
                float4 m0 = *(const float4*)&sx[s0*Hdim + lane*4];
                float4 m1 = *(const float4*)&sx[s1*Hdim + lane*4];
                float4 m2 = *(const float4*)&sx[s2*Hdim + lane*4];
                float4 m3 = *(const float4*)&sx[s3*Hdim + lane*4];
                acc.x += (m0.x + m1.x) + (m2.x + m3.x);
                acc.y += (m0.y + m1.y) + (m2.y + m3.y);
                acc.z += (m0.z + m1.z) + (m2.z + m3.z);
                acc.w += (m0.w + m1.w) + (m2.w + m3.w);
            }
            for (; e < e1; e++) {
                int s = cp[e];
                float4 m = *(const float4*)&sx[s*Hdim + lane*4];
                acc.x += m.x; acc.y += m.y; acc.z += m.z; acc.w += m.w;
            }
            float4 rt = *(const float4*)&g_tmp[(size_t)row*256 + 128 + lane*4];
            outv.x = fmaxf(acc.x + rt.x + bv.x, 0.f);
            outv.y = fmaxf(acc.y + rt.y + bv.y, 0.f);
            outv.z = fmaxf(acc.z + rt.z + bv.z, 0.f);
            outv.w = fmaxf(acc.w + rt.w + bv.w, 0.f);
        }
        *(float4*)&g_h[(size_t)row*Hdim + lane*4] = outv;
        float d = outv.x*pwv.x + outv.y*pwv.y + outv.z*pwv.z + outv.w*pwv.w;
        #pragma unroll
        for (int o = 16; o > 0; o >>= 1) d += __shfl_xor_sync(0xffffffffu, d, o);
        if (lane == 0) {
            float scv = act ? d / snorm : -1e30f;
            uint32_t ub = __float_as_uint(scv);
            ub = (ub & 0x80000000u) ? ~ub : (ub | 0x80000000u);
            skey[v] = ((unsigned long long)ub << 9) | (unsigned long long)(511 - v);
        }
    }
    for (int i = NPERg + t; i < 512; i += 1024) skey[i] = 0ull;
    __syncthreads();

    // ---- phase B: bitonic sort on packed keys (descending) ----
    for (int ksz = 2; ksz <= 512; ksz <<= 1) {
        for (int j = ksz >> 1; j > 0; j >>= 1) {
            if (t < 512) {
                int i = t;
                int ixj = i ^ j;
                if (ixj > i) {
                    unsigned long long a = skey[i], b = skey[ixj];
                    bool up = ((i & ksz) == 0);
                    if ((a < b) == up) { skey[i] = b; skey[ixj] = a; }
                }
            }
            __syncthreads();
        }
    }

    for (int v = t; v < NPERg; v += 1024) { gate[v] = 0.f; selF[v] = 0; }
    __syncthreads();
    if (t < k) {
        unsigned long long kk = skey[t];
        int v = 511 - (int)(kk & 511u);
        uint32_t ub = (uint32_t)(kk >> 9);
        uint32_t fb = (ub & 0x80000000u) ? (ub & 0x7FFFFFFFu) : ~ub;
        gate[v] = tanhf(__uint_as_float(fb));
        selF[v] = 1;
    }
    __syncthreads();

    for (int v = t; v < NPERg; v += 1024) g_active[g*NPERg + v] = selF[v];

    // ---- phase C: gate + readout (+ optional bf16 conversion) ----
    float* red_mx = sx;                 // alias dead sx tile
    float* red_sm = sx + 32*128;
    const int c4 = lane << 2;
    const int v0 = w;
    float4 mx = make_float4(-3.0e38f, -3.0e38f, -3.0e38f, -3.0e38f);
    float4 sm = make_float4(0.f, 0.f, 0.f, 0.f);
    for (int v = v0; v < NPERg; v += 32) {
        size_t row = (size_t)(g*NPERg + v);
        if (selF[v]) {
            float4 val = *(const float4*)&g_h[row*Hdim + c4];
            float gt = gate[v];
            val.x *= gt; val.y *= gt; val.z *= gt; val.w *= gt;
            if (doConv) {
                __nv_bfloat16 h0 = __float2bfloat16(val.x);
                __nv_bfloat16 h1 = __float2bfloat16(val.y);
                __nv_bfloat16 h2 = __float2bfloat16(val.z);
                __nv_bfloat16 h3 = __float2bfloat16(val.w);
                __nv_bfloat162* ph = (__nv_bfloat162*)&g_ah[row*Hdim + c4];
                ph[0] = __nv_bfloat162(h0, h1);
                ph[1] = __nv_bfloat162(h2, h3);
                __nv_bfloat162* pl = (__nv_bfloat162*)&g_al[row*Hdim + c4];
                pl[0] = __nv_bfloat162(__float2bfloat16(val.x - __bfloat162float(h0)),
                                       __float2bfloat16(val.y - __bfloat162float(h1)));
                pl[1] = __nv_bfloat162(__float2bfloat16(val.z - __bfloat162float(h2)),
                                       __float2bfloat16(val.w - __bfloat162float(h3)));
            }
            mx.x = fmaxf(mx.x, val.x); mx.y = fmaxf(mx.y, val.y);
            mx.z = fmaxf(mx.z, val.z); mx.w = fmaxf(mx.w, val.w);
            sm.x += val.x; sm.y += val.y; sm.z += val.z; sm.w += val.w;
        } else if (doConv) {
            *(uint2*)&g_ah[row*Hdim + c4] = make_uint2(0u, 0u);
            *(uint2*)&g_al[row*Hdim + c4] = make_uint2(0u, 0u);
        }
    }
    *(float4*)&red_mx[v0*128 + c4] = mx;
    *(float4*)&red_sm[v0*128 + c4] = sm;
    __syncthreads();

    if (t < 128) {
        float m = red_mx[t], s = red_sm[t];
        #pragma unroll
        for (int r = 1; r < 32; r++) {
            m = fmaxf(m, red_mx[r*128 + t]);
            s += red_sm[r*128 + t];
        }
        float z0 = g_z[g*256 + t] + m;
        float z1 = g_z[g*256 + 128 + t] + s / (float)k;
        if (doMLP) {
            gate[t] = z0; gate[128 + t] = z1;   // zs in smem (gate is dead)
        } else {
            g_z[g*256 + t]       = z0;
            g_z[g*256 + 128 + t] = z1;
        }
    }

    // ---- fused MLP head (layer 3 only) ----
    if (doMLP) {
        __syncthreads();
        if (t < 128) {
            float acc = bl1[t];
            const float* wr = &W1[(size_t)t*256];
            for (int kk = 0; kk < 256; kk++) acc += wr[kk]*gate[kk];
            a1s[t] = fmaxf(acc, 0.f);
        }
        __syncthreads();
        if (t < 64) {
            float acc = bl2[t];
            const float* wr = &W2[(size_t)t*128];
            for (int kk = 0; kk < 128; kk++) acc += wr[kk]*a1s[kk];
            a2s[t] = fmaxf(acc, 0.f);
        }
        __syncthreads();
        if (t < 2) {
            float acc = bl3[t];
            const float* wr = &W3[(size_t)t*64];
            for (int kk = 0; kk < 64; kk++) acc += wr[kk]*a2s[kk];
            lgs[t] = acc;
        }
        __syncthreads();
        if (t < 2) {
            float m2 = fmaxf(lgs[0], lgs[1]);
            float lse = m2 + logf(expf(lgs[0] - m2) + expf(lgs[1] - m2));
            out[g*2 + t] = lgs[t] - lse;
        }
    }
}

// ---------------- launcher ----------------
extern "C" void kernel_launch(void* const* d_in, const int* in_sizes, int n_in,
                              void* d_out, int out_size)
{
    const float* x      = (const float*)d_in[0];
    const int*   esrc   = (const int*)  d_in[1];
    const int*   edst   = (const int*)  d_in[2];
    const float* Wrel1  = (const float*)d_in[4];
    const float* Wroot1 = (const float*)d_in[5];
    const float* b1     = (const float*)d_in[6];
    const float* pw1    = (const float*)d_in[7];
    const float* Wrel2  = (const float*)d_in[8];
    const float* Wroot2 = (const float*)d_in[9];
    const float* b2     = (const float*)d_in[10];
    const float* pw2    = (const float*)d_in[11];
    const float* Wrel3  = (const float*)d_in[12];
    const float* Wroot3 = (const float*)d_in[13];
    const float* b3     = (const float*)d_in[14];
    const float* pw3    = (const float*)d_in[15];
    const float* W1     = (const float*)d_in[16];
    const float* bl1    = (const float*)d_in[17];
    const float* W2     = (const float*)d_in[18];
    const float* bl2    = (const float*)d_in[19];
    const float* W3     = (const float*)d_in[20];
    const float* bl3    = (const float*)d_in[21];
    float* out = (float*)d_out;

    const int LAYER_SMEM = NPERg * Hdim * (int)sizeof(float);  // 204800
    cudaFuncSetAttribute(layer_fused, cudaFuncAttributeMaxDynamicSharedMemorySize, LAYER_SMEM);
    cudaFuncSetAttribute(hmma_gemm, cudaFuncAttributeMaxDynamicSharedMemorySize, GEMM_SMEM);

    // layer 1 (K=400, Kpad=448); layer_fused in profiled slot #4
    csr_build<<<Bg, 256>>>(esrc, edst);
    conv_all<<<WBLK + ABLK, 256>>>(x, Wrel1, Wroot1, 400, KPAD1);
    hmma_gemm<<<NNODES/128, 512, GEMM_SMEM>>>(400, KPAD1);
    layer_fused<<<Bg, 1024, LAYER_SMEM>>>(b1, pw1, KP1, 1, 0,
        nullptr, nullptr, nullptr, nullptr, nullptr, nullptr, nullptr);

    // layer 2 (K=128)
    conv_w<<<(256*Hdim + 255)/256, 256>>>(Wrel2, Wroot2, Hdim, Hdim);
    hmma_gemm<<<NNODES/128, 512, GEMM_SMEM>>>(Hdim, Hdim);
    layer_fused<<<Bg, 1024, LAYER_SMEM>>>(b2, pw2, KP2, 1, 0,
        nullptr, nullptr, nullptr, nullptr, nullptr, nullptr, nullptr);

    // layer 3 (K=128) + fused MLP head
    conv_w<<<(256*Hdim + 255)/256, 256>>>(Wrel3, Wroot3, Hdim, Hdim);
    hmma_gemm<<<NNODES/128, 512, GEMM_SMEM>>>(Hdim, Hdim);
    layer_fused<<<Bg, 1024, LAYER_SMEM>>>(b3, pw3, KP3, 0, 1,
        W1, bl1, W2, bl2, W3, bl3, out);
}

// round 17
// speedup vs baseline: 2.6269x; 1.0152x over previous
#include <cuda_runtime.h>
#include <cuda_bf16.h>
#include <math.h>
#include <stdint.h>

#define Bg 128
#define NPERg 400
#define NNODES (Bg*NPERg)      // 51200
#define EPGg 6400
#define NE (Bg*EPGg)           // 819200
#define Hdim 128
#define KP1 320
#define KP2 256
#define KP3 205
#define KPAD1 448              // ceil(400/64)*64
#define WELEMS (256*(KPAD1 + 128 + 128))   // 180224
#define WOFF2 (256*KPAD1)                  // 114688
#define WOFF3 (256*(KPAD1+128))            // 147456

// ---------------- scratch (device globals; no allocation allowed) -------------
__device__ float g_tmp[NNODES*256];     // GEMM out: [xrel | xroot] per node
__device__ float g_h[NNODES*Hdim];      // node features (internal to fused layer)
__device__ int   g_rowptr[Bg*(NPERg+1)];
__device__ int   g_col[NE];             // local src index per CSR entry
__device__ int   g_active[NNODES];
__device__ float g_z[Bg*256];           // accumulated readouts x1+x2
__device__ __align__(16) __nv_bfloat16 g_ah[(size_t)NNODES*Hdim];  // A hi (L2/L3)
__device__ __align__(16) __nv_bfloat16 g_al[(size_t)NNODES*Hdim];  // A lo (L2/L3)
__device__ __align__(16) __nv_bfloat16 g_bhALL[WELEMS];            // B hi x3 layers
__device__ __align__(16) __nv_bfloat16 g_blALL[WELEMS];            // B lo x3 layers

// ---------------- helpers ----------------
__device__ __forceinline__ uint32_t smem_u32(const void* p) {
    uint32_t a;
    asm("{ .reg .u64 t; cvta.to.shared.u64 t, %1; cvt.u32.u64 %0, t; }" : "=r"(a) : "l"(p));
    return a;
}
__device__ __forceinline__ void ldmat_x4(uint32_t* r, uint32_t addr) {
    asm volatile("ldmatrix.sync.aligned.m8n8.x4.shared.b16 {%0,%1,%2,%3}, [%4];"
                 : "=r"(r[0]), "=r"(r[1]), "=r"(r[2]), "=r"(r[3]) : "r"(addr));
}
__device__ __forceinline__ void mma_bf16(float* c, const uint32_t* a, const uint32_t* b) {
    asm volatile("mma.sync.aligned.m16n8k16.row.col.f32.bf16.bf16.f32 "
                 "{%0,%1,%2,%3}, {%4,%5,%6,%7}, {%8,%9}, {%0,%1,%2,%3};"
                 : "+f"(c[0]), "+f"(c[1]), "+f"(c[2]), "+f"(c[3])
                 : "r"(a[0]), "r"(a[1]), "r"(a[2]), "r"(a[3]), "r"(b[0]), "r"(b[1]));
}
__device__ __forceinline__ void cp16(uint32_t saddr, const void* gaddr) {
    asm volatile("cp.async.cg.shared.global [%0], [%1], 16;" :: "r"(saddr), "l"(gaddr));
}
#define CP_COMMIT() asm volatile("cp.async.commit_group;" ::: "memory")
#define CP_WAIT1()  asm volatile("cp.async.wait_group 1;" ::: "memory")
#define CP_WAIT0()  asm volatile("cp.async.wait_group 0;" ::: "memory")

// ---------------- CSR build + state init (one CTA per graph) ------------------
__global__ __launch_bounds__(256) void csr_build(const int* __restrict__ esrc,
                                                 const int* __restrict__ edst)
{
    __shared__ int sdeg[NPERg];
    __shared__ int sa[512], sb2[512];
    __shared__ int cursor[NPERg];
    const int g = blockIdx.x, t = threadIdx.x;
    const int ebase = g * EPGg, vbase = g * NPERg;

    for (int v = t; v < NPERg; v += 256) sdeg[v] = 0;
    __syncthreads();
    for (int e = t; e < EPGg; e += 256)
        atomicAdd(&sdeg[edst[ebase + e] - vbase], 1);
    __syncthreads();

    for (int i = t; i < 512; i += 256) sa[i] = (i < NPERg) ? sdeg[i] : 0;
    __syncthreads();
    int* src = sa; int* dst = sb2;
    for (int off = 1; off < 512; off <<= 1) {
        for (int i = t; i < 512; i += 256)
            dst[i] = src[i] + ((i >= off) ? src[i - off] : 0);
        __syncthreads();
        int* tmp = src; src = dst; dst = tmp;
    }

    for (int v = t; v < NPERg; v += 256) {
        int ex = v ? src[v - 1] : 0;
        g_rowptr[g*(NPERg+1) + v] = ex;
        cursor[v] = ebase + ex;
        g_active[vbase + v] = 1;
    }
    if (t == 0) g_rowptr[g*(NPERg+1) + NPERg] = src[NPERg - 1];
    g_z[g*256 + t] = 0.f;
    __syncthreads();

    for (int e = t; e < EPGg; e += 256) {
        int d = edst[ebase + e] - vbase;
        int s = esrc[ebase + e] - vbase;
        int pos = atomicAdd(&cursor[d], 1);
        g_col[pos] = s;
    }
}

// ---------------- all-weights split-bf16 conversion (one launch) --------------
// blocks [0,448): L1 (Kpad=448), [448,576): L2, [576,704): L3 (Kpad=128)
__global__ void conv_wall(const float* __restrict__ Wrel1, const float* __restrict__ Wroot1,
                          const float* __restrict__ Wrel2, const float* __restrict__ Wroot2,
                          const float* __restrict__ Wrel3, const float* __restrict__ Wroot3)
{
    int b = blockIdx.x, t = threadIdx.x;
    int idx, K, Kpad, base;
    const float *Wr, *Wo;
    if (b < 448)      { idx = b*256 + t;        K = 400; Kpad = KPAD1; base = 0;     Wr = Wrel1; Wo = Wroot1; }
    else if (b < 576) { idx = (b-448)*256 + t;  K = 128; Kpad = 128;   base = WOFF2; Wr = Wrel2; Wo = Wroot2; }
    else              { idx = (b-576)*256 + t;  K = 128; Kpad = 128;   base = WOFF3; Wr = Wrel3; Wo = Wroot3; }
    int k = idx % Kpad;
    int r = idx / Kpad;
    float v = 0.f;
    if (k < K) v = (r < 128) ? Wr[(size_t)r*K + k] : Wo[(size_t)(r-128)*K + k];
    __nv_bfloat16 hi = __float2bfloat16(v);
    g_bhALL[base + idx] = hi;
    g_blALL[base + idx] = __float2bfloat16(v - __bfloat162float(hi));
}

// ---------------- HMMA GEMM (merged-N, cp.async 2-stage, fused A-convert) -----
// mode 0: A staged from fp32 x with in-register split-bf16 conversion (layer 1)
// mode 1: A staged via cp.async from g_ah/g_al (layers 2/3)
#define STAGE_BYTES 98304
#define GEMM_SMEM   (2*STAGE_BYTES)   // 196608

__global__ __launch_bounds__(512, 1) void hmma_gemm(const float* __restrict__ xin,
                                                    int mode, int woff, int K, int Kpad)
{
    extern __shared__ char smem[];
    const int t = threadIdx.x, wid = t >> 5, lane = t & 31;
    const int m0 = blockIdx.x * 128;
    const int warp_m = (wid & 3) * 32;
    const int warp_n = (wid >> 2) * 64;
    const uint32_t sb = smem_u32(smem);
    const int nchunks = Kpad >> 6;
    const __nv_bfloat16* __restrict__ bhp = g_bhALL + woff;
    const __nv_bfloat16* __restrict__ blp = g_blALL + woff;

    float acc[2][8][4];
    #pragma unroll
    for (int mi = 0; mi < 2; mi++)
        #pragma unroll
        for (int ni = 0; ni < 8; ni++)
            #pragma unroll
            for (int q = 0; q < 4; q++) acc[mi][ni][q] = 0.f;

    const int j = lane >> 3, rr = lane & 7;

    // B staging (both modes): 4096 uint4, 8 cp.async per thread, one commit group
    auto issueB = [&](int c, int stage) {
        const int k0 = c * 64;
        const uint32_t sdst = sb + (uint32_t)stage * STAGE_BYTES;
        #pragma unroll
        for (int it = 0; it < 8; it++) {
            int idx = t + it * 512;            // 0..4095
            int buf = idx >> 11;
            int rem = idx & 2047;
            const __nv_bfloat16* src = buf ? blp : bhp;
            int r = rem >> 3, u = rem & 7;
            const void* gp = src + (size_t)r * Kpad + k0 + u*8;
            uint32_t off = (uint32_t)(r*128 + ((u*16) ^ ((r & 7) << 4)));
            cp16(sdst + 32768u + (uint32_t)buf*32768u + off, gp);
        }
    };
    // A staging mode 1: 2048 uint4, 4 cp.async per thread (same commit group as B)
    auto issueA1 = [&](int c, int stage) {
        const int k0 = c * 64;
        const uint32_t sdst = sb + (uint32_t)stage * STAGE_BYTES;
        #pragma unroll
        for (int it = 0; it < 4; it++) {
            int idx = t + it * 512;            // 0..2047
            int buf = idx >> 10;
            int rem = idx & 1023;
            const __nv_bfloat16* src = buf ? g_al : g_ah;
            int r = rem >> 3, u = rem & 7;
            const void* gp = src + (size_t)(m0 + r) * Kpad + k0 + u*8;
            uint32_t off = (uint32_t)(r*128 + ((u*16) ^ ((r & 7) << 4)));
            cp16(sdst + (uint32_t)buf*16384u + off, gp);
        }
    };
    // A staging mode 0: sync LDG fp32 + convert + STS. 1024 granules of 8 floats;
    // each thread handles 2 granules (4 LDG.128 issued back-to-back, MLP=4).
    auto stageA0 = [&](int c, int stage) {
        const int k0 = c * 64;
        const uint32_t sdst = sb + (uint32_t)stage * STAGE_BYTES;
        float4 va[2][2];
        int rs[2], us[2];
        #pragma unroll
        for (int gIdx = 0; gIdx < 2; gIdx++) {
            int id = t + gIdx * 512;           // 0..1023
            int r = id >> 3, u = id & 7;
            rs[gIdx] = r; us[gIdx] = u;
            int kk = k0 + u*8;
            if (kk + 8 <= K) {                 // K%8==0: granule full or empty
                const float* gp = xin + (size_t)(m0 + r) * K + kk;
                va[gIdx][0] = *(const float4*)gp;
                va[gIdx][1] = *(const float4*)(gp + 4);
            } else {
                va[gIdx][0] = make_float4(0.f, 0.f, 0.f, 0.f);
                va[gIdx][1] = make_float4(0.f, 0.f, 0.f, 0.f);
            }
        }
        #pragma unroll
        for (int gIdx = 0; gIdx < 2; gIdx++) {
            uint32_t hw[4], lw[4];
            #pragma unroll
            for (int q = 0; q < 2; q++) {
                float4 v = va[gIdx][q];
                __nv_bfloat16 h0 = __float2bfloat16(v.x), h1 = __float2bfloat16(v.y);
                __nv_bfloat16 h2 = __float2bfloat16(v.z), h3 = __float2bfloat16(v.w);
                __nv_bfloat162 p0(h0, h1), p1(h2, h3);
                hw[2*q+0] = *(uint32_t*)&p0;
                hw[2*q+1] = *(uint32_t*)&p1;
                __nv_bfloat162 q0(__float2bfloat16(v.x - __bfloat162float(h0)),
                                  __float2bfloat16(v.y - __bfloat162float(h1)));
                __nv_bfloat162 q1(__float2bfloat16(v.z - __bfloat162float(h2)),
                                  __float2bfloat16(v.w - __bfloat162float(h3)));
                lw[2*q+0] = *(uint32_t*)&q0;
                lw[2*q+1] = *(uint32_t*)&q1;
            }
            uint32_t off = (uint32_t)(rs[gIdx]*128 + ((us[gIdx]*16) ^ ((rs[gIdx] & 7) << 4)));
            *(uint4*)(smem + (sdst - sb) + off)           = make_uint4(hw[0], hw[1], hw[2], hw[3]);
            *(uint4*)(smem + (sdst - sb) + 16384u + off)  = make_uint4(lw[0], lw[1], lw[2], lw[3]);
        }
    };

    auto stage_chunk = [&](int c, int stage) {
        if (mode == 0) stageA0(c, stage);
        else           issueA1(c, stage);
        issueB(c, stage);
        CP_COMMIT();
    };

    stage_chunk(0, 0);
    for (int c = 0; c < nchunks; c++) {
        const int st = c & 1;
        if (c + 1 < nchunks) { stage_chunk(c + 1, st ^ 1); CP_WAIT1(); }
        else                 { CP_WAIT0(); }
        __syncthreads();

        const uint32_t sbase = sb + (uint32_t)st*STAGE_BYTES;
        const int ksmax = min(4, (K - c*64 + 15) >> 4);   // skip pure padding
        for (int ks = 0; ks < ksmax; ks++) {
            uint32_t ah[2][4], al[2][4];
            #pragma unroll
            for (int mi = 0; mi < 2; mi++) {
                int arow = warp_m + mi*16 + (j & 1)*8 + rr;
                uint32_t akb = (uint32_t)((ks*32 + (j >> 1)*16) ^ (rr << 4));
                uint32_t addr = sbase + (uint32_t)(arow*128) + akb;
                ldmat_x4(ah[mi], addr);
                ldmat_x4(al[mi], addr + 16384u);
            }
            #pragma unroll
            for (int np = 0; np < 4; np++) {
                uint32_t bh[4], bl[4];
                int brow = warp_n + np*16 + (j >> 1)*8 + rr;
                uint32_t bkb = (uint32_t)((ks*32 + (j & 1)*16) ^ (rr << 4));
                uint32_t baddr = sbase + 32768u + (uint32_t)(brow*128) + bkb;
                ldmat_x4(bh, baddr);
                ldmat_x4(bl, baddr + 32768u);
                #pragma unroll
                for (int p = 0; p < 3; p++) {
                    #pragma unroll
                    for (int tt = 0; tt < 2; tt++) {
                        #pragma unroll
                        for (int mi = 0; mi < 2; mi++) {
                            const uint32_t* af = (p == 2) ? al[mi] : ah[mi];
                            const uint32_t* bf = (p == 1) ? (bl + 2*tt) : (bh + 2*tt);
                            mma_bf16(acc[mi][2*np + tt], af, bf);
                        }
                    }
                }
            }
        }
        __syncthreads();
    }

    const int gid = lane >> 2, tig = lane & 3;
    #pragma unroll
    for (int mi = 0; mi < 2; mi++) {
        #pragma unroll
        for (int ni = 0; ni < 8; ni++) {
            int row = m0 + warp_m + mi*16 + gid;
            int col = warp_n + ni*8 + 2*tig;
            float* p0 = &g_tmp[(size_t)row*256 + col];
            float* p1 = &g_tmp[(size_t)(row + 8)*256 + col];
            *(float2*)p0 = make_float2(acc[mi][ni][0], acc[mi][ni][1]);
            *(float2*)p1 = make_float2(acc[mi][ni][2], acc[mi][ni][3]);
        }
    }
}

// ---------------- fused layer: SpMM + epi + score + topk + gate + readout -----
__global__ __launch_bounds__(1024) void layer_fused(
    const float* __restrict__ bias, const float* __restrict__ pw,
    int k, int doConv, int doMLP,
    const float* __restrict__ W1, const float* __restrict__ bl1,
    const float* __restrict__ W2, const float* __restrict__ bl2,
    const float* __restrict__ W3, const float* __restrict__ bl3,
    float* __restrict__ out)
{
    extern __shared__ float sx[];   // [400][128]
    __shared__ unsigned long long skey[512];
    __shared__ float gate[NPERg];              // reused as zs[256] for MLP
    __shared__ unsigned char selF[NPERg];
    __shared__ __align__(16) float spw[128];
    __shared__ float snorm;
    __shared__ float a1s[128], a2s[64], lgs[2];

    const int g = blockIdx.x, t = threadIdx.x;
    const int w = t >> 5, lane = t & 31;

    for (int idx = t; idx < NPERg*32; idx += 1024) {
        int v = idx >> 5, c4i = (idx & 31) << 2;
        *(float4*)&sx[v*Hdim + c4i] =
            *(const float4*)&g_tmp[(size_t)(g*NPERg + v)*256 + c4i];
    }
    if (t < 128) spw[t] = pw[t];
    __syncthreads();
    if (t == 0) {
        float s = 0.f;
        for (int i = 0; i < 128; i++) s += spw[i]*spw[i];
        snorm = sqrtf(s) + 1e-16f;
    }
    __syncthreads();

    // ---- phase A: aggregate + epilogue + score ----
    float4 bv = *(const float4*)&bias[lane*4];
    float4 pwv = *(const float4*)&spw[lane*4];
    for (int v = w; v < NPERg; v += 32) {
        int row = g*NPERg + v;
        int act = g_active[row];
        float4 outv = make_float4(0.f, 0.f, 0.f, 0.f);
        if (act) {
            float4 acc = make_float4(0.f, 0.f, 0.f, 0.f);
            int e0 = g_rowptr[g*(NPERg+1) + v];
            int e1 = g_rowptr[g*(NPERg+1) + v + 1];
            const int* cp = &g_col[g*EPGg];
            int e = e0;
            for (; e + 3 < e1; e += 4) {
                int s0 = cp[e], s1 = cp[e+1], s2 = cp[e+2], s3 = cp[e+3];
                float4 m0 = *(const float4*)&sx[s0*Hdim + lane*4];
                float4 m1 = *(const float4*)&sx[s1*Hdim + lane*4];
                float4 m2 = *(const float4*)&sx[s2*Hdim + lane*4];
                float4 m3 = *(const float4*)&sx[s3*Hdim + lane*4];
                acc.x += (m0.x + m1.x) + (m2.x + m3.x);
                acc.y += (m0.y + m1.y) + (m2.y + m3.y);
                acc.z += (m0.z + m1.z) + (m2.z + m3.z);
                acc.w += (m0.w + m1.w) + (m2.w + m3.w);
            }
            for (; e < e1; e++) {
                int s = cp[e];
                float4 m = *(const float4*)&sx[s*Hdim + lane*4];
                acc.x += m.x; acc.y += m.y; acc.z += m.z; acc.w += m.w;
            }
            float4 rt = *(const float4*)&g_tmp[(size_t)row*256 + 128 + lane*4];
            outv.x = fmaxf(acc.x + rt.x + bv.x, 0.f);
            outv.y = fmaxf(acc.y + rt.y + bv.y, 0.f);
            outv.z = fmaxf(acc.z + rt.z + bv.z, 0.f);
            outv.w = fmaxf(acc.w + rt.w + bv.w, 0.f);
        }
        *(float4*)&g_h[(size_t)row*Hdim + lane*4] = outv;
        float d = outv.x*pwv.x + outv.y*pwv.y + outv.z*pwv.z + outv.w*pwv.w;
        #pragma unroll
        for (int o = 16; o > 0; o >>= 1) d += __shfl_xor_sync(0xffffffffu, d, o);
        if (lane == 0) {
            float scv = act ? d / snorm : -1e30f;
            uint32_t ub = __float_as_uint(scv);
            ub = (ub & 0x80000000u) ? ~ub : (ub | 0x80000000u);
            skey[v] = ((unsigned long long)ub << 9) | (unsigned long long)(511 - v);
        }
    }
    for (int i = NPERg + t; i < 512; i += 1024) skey[i] = 0ull;
    __syncthreads();

    // ---- phase B: bitonic sort (descending) ----
    for (int ksz = 2; ksz <= 512; ksz <<= 1) {
        for (int j = ksz >> 1; j > 0; j >>= 1) {
            if (t < 512) {
                int i = t;
                int ixj = i ^ j;
                if (ixj > i) {
                    unsigned long long a = skey[i], b = skey[ixj];
                    bool up = ((i & ksz) == 0);
                    if ((a < b) == up) { skey[i] = b; skey[ixj] = a; }
                }
            }
            __syncthreads();
        }
    }

    for (int v = t; v < NPERg; v += 1024) { gate[v] = 0.f; selF[v] = 0; }
    __syncthreads();
    if (t < k) {
        unsigned long long kk = skey[t];
        int v = 511 - (int)(kk & 511u);
        uint32_t ub = (uint32_t)(kk >> 9);
        uint32_t fb = (ub & 0x80000000u) ? (ub & 0x7FFFFFFFu) : ~ub;
        gate[v] = tanhf(__uint_as_float(fb));
        selF[v] = 1;
    }
    __syncthreads();

    for (int v = t; v < NPERg; v += 1024) g_active[g*NPERg + v] = selF[v];

    // ---- phase C: gate + readout (+ optional bf16 conversion) ----
    float* red_mx = sx;                 // alias dead sx tile
    float* red_sm = sx + 32*128;
    const int c4 = lane << 2;
    const int v0 = w;
    float4 mx = make_float4(-3.0e38f, -3.0e38f, -3.0e38f, -3.0e38f);
    float4 sm = make_float4(0.f, 0.f, 0.f, 0.f);
    for (int v = v0; v < NPERg; v += 32) {
        size_t row = (size_t)(g*NPERg + v);
        if (selF[v]) {
            float4 val = *(const float4*)&g_h[row*Hdim + c4];
            float gt = gate[v];
            val.x *= gt; val.y *= gt; val.z *= gt; val.w *= gt;
            if (doConv) {
                __nv_bfloat16 h0 = __float2bfloat16(val.x);
                __nv_bfloat16 h1 = __float2bfloat16(val.y);
                __nv_bfloat16 h2 = __float2bfloat16(val.z);
                __nv_bfloat16 h3 = __float2bfloat16(val.w);
                __nv_bfloat162* ph = (__nv_bfloat162*)&g_ah[row*Hdim + c4];
                ph[0] = __nv_bfloat162(h0, h1);
                ph[1] = __nv_bfloat162(h2, h3);
                __nv_bfloat162* pl = (__nv_bfloat162*)&g_al[row*Hdim + c4];
                pl[0] = __nv_bfloat162(__float2bfloat16(val.x - __bfloat162float(h0)),
                                       __float2bfloat16(val.y - __bfloat162float(h1)));
                pl[1] = __nv_bfloat162(__float2bfloat16(val.z - __bfloat162float(h2)),
                                       __float2bfloat16(val.w - __bfloat162float(h3)));
            }
            mx.x = fmaxf(mx.x, val.x); mx.y = fmaxf(mx.y, val.y);
            mx.z = fmaxf(mx.z, val.z); mx.w = fmaxf(mx.w, val.w);
            sm.x += val.x; sm.y += val.y; sm.z += val.z; sm.w += val.w;
        } else if (doConv) {
            *(uint2*)&g_ah[row*Hdim + c4] = make_uint2(0u, 0u);
            *(uint2*)&g_al[row*Hdim + c4] = make_uint2(0u, 0u);
        }
    }
    *(float4*)&red_mx[v0*128 + c4] = mx;
    *(float4*)&red_sm[v0*128 + c4] = sm;
    __syncthreads();

    if (t < 128) {
        float m = red_mx[t], s = red_sm[t];
        #pragma unroll
        for (int r = 1; r < 32; r++) {
            m = fmaxf(m, red_mx[r*128 + t]);
            s += red_sm[r*128 + t];
        }
        float z0 = g_z[g*256 + t] + m;
        float z1 = g_z[g*256 + 128 + t] + s / (float)k;
        if (doMLP) {
            gate[t] = z0; gate[128 + t] = z1;
        } else {
            g_z[g*256 + t]       = z0;
            g_z[g*256 + 128 + t] = z1;
        }
    }

    if (doMLP) {
        __syncthreads();
        if (t < 128) {
            float acc = bl1[t];
            const float* wr = &W1[(size_t)t*256];
            for (int kk = 0; kk < 256; kk++) acc += wr[kk]*gate[kk];
            a1s[t] = fmaxf(acc, 0.f);
        }
        __syncthreads();
        if (t < 64) {
            float acc = bl2[t];
            const float* wr = &W2[(size_t)t*128];
            for (int kk = 0; kk < 128; kk++) acc += wr[kk]*a1s[kk];
            a2s[t] = fmaxf(acc, 0.f);
        }
        __syncthreads();
        if (t < 2) {
            float acc = bl3[t];
            const float* wr = &W3[(size_t)t*64];
            for (int kk = 0; kk < 64; kk++) acc += wr[kk]*a2s[kk];
            lgs[t] = acc;
        }
        __syncthreads();
        if (t < 2) {
            float m2 = fmaxf(lgs[0], lgs[1]);
            float lse = m2 + logf(expf(lgs[0] - m2) + expf(lgs[1] - m2));
            out[g*2 + t] = lgs[t] - lse;
        }
    }
}

// ---------------- launcher ----------------
extern "C" void kernel_launch(void* const* d_in, const int* in_sizes, int n_in,
                              void* d_out, int out_size)
{
    const float* x      = (const float*)d_in[0];
    const int*   esrc   = (const int*)  d_in[1];
    const int*   edst   = (const int*)  d_in[2];
    const float* Wrel1  = (const float*)d_in[4];
    const float* Wroot1 = (const float*)d_in[5];
    const float* b1     = (const float*)d_in[6];
    const float* pw1    = (const float*)d_in[7];
    const float* Wrel2  = (const float*)d_in[8];
    const float* Wroot2 = (const float*)d_in[9];
    const float* b2     = (const float*)d_in[10];
    const float* pw2    = (const float*)d_in[11];
    const float* Wrel3  = (const float*)d_in[12];
    const float* Wroot3 = (const float*)d_in[13];
    const float* b3     = (const float*)d_in[14];
    const float* pw3    = (const float*)d_in[15];
    const float* W1     = (const float*)d_in[16];
    const float* bl1    = (const float*)d_in[17];
    const float* W2     = (const float*)d_in[18];
    const float* bl2    = (const float*)d_in[19];
    const float* W3     = (const float*)d_in[20];
    const float* bl3    = (const float*)d_in[21];
    float* out = (float*)d_out;

    const int LAYER_SMEM = NPERg * Hdim * (int)sizeof(float);  // 204800
    cudaFuncSetAttribute(layer_fused, cudaFuncAttributeMaxDynamicSharedMemorySize, LAYER_SMEM);
    cudaFuncSetAttribute(hmma_gemm, cudaFuncAttributeMaxDynamicSharedMemorySize, GEMM_SMEM);

    // layer 1 (K=400, Kpad=448): A converted in-GEMM from fp32 x
    csr_build<<<Bg, 256>>>(esrc, edst);
    conv_wall<<<704, 256>>>(Wrel1, Wroot1, Wrel2, Wroot2, Wrel3, Wroot3);
    hmma_gemm<<<NNODES/128, 512, GEMM_SMEM>>>(x, 0, 0, 400, KPAD1);
    layer_fused<<<Bg, 1024, LAYER_SMEM>>>(b1, pw1, KP1, 1, 0,    // <- profiled
        nullptr, nullptr, nullptr, nullptr, nullptr, nullptr, nullptr);

    // layer 2 (K=128)
    hmma_gemm<<<NNODES/128, 512, GEMM_SMEM>>>(nullptr, 1, WOFF2, Hdim, Hdim);
    layer_fused<<<Bg, 1024, LAYER_SMEM>>>(b2, pw2, KP2, 1, 0,
        nullptr, nullptr, nullptr, nullptr, nullptr, nullptr, nullptr);

    // layer 3 (K=128) + fused MLP head
    hmma_gemm<<<NNODES/128, 512, GEMM_SMEM>>>(nullptr, 1, WOFF3, Hdim, Hdim);
    layer_fused<<<Bg, 1024, LAYER_SMEM>>>(b3, pw3, KP3, 0, 1,
        W1, bl1, W2, bl2, W3, bl3, out);
}